// round 11
// baseline (speedup 1.0000x reference)
#include <cuda_runtime.h>
#include <cuda_bf16.h>
#include <math.h>
#include <stdint.h>

typedef __nv_bfloat16 bf16;

// ---------------- problem dims ----------------
#define BB    32
#define NN    512
#define BD    768            // L*H
#define ROWS  (BB*NN)        // 16384
#define OUTC  64
#define KSUP  4
#define ZC    256            // KSUP*OUTC
#define AS    ((size_t)NN*NN)

// ---------------- device scratch (no allocation) ----------------
__device__ __align__(256) bf16  g_Mh [2*AS], g_Ml [2*AS];    // M = A+(1+eps)I, split
__device__ __align__(256) bf16  g_Xh[(size_t)ROWS*BD], g_Xl[(size_t)ROWS*BD];
__device__ __align__(256) bf16  g_Wth[ZC*BD], g_Wtl[ZC*BD];  // W^T repack [ko][d]
__device__ __align__(256) bf16  g_Zh[(size_t)ROWS*ZC], g_Zl[(size_t)ROWS*ZC];
__device__ __align__(256) bf16  g_Vh[(size_t)2*ROWS*OUTC], g_Vl[(size_t)2*ROWS*OUTC];
__device__ __align__(256) float g_midp[2][(size_t)ROWS*OUTC]; // stage2b slabs (per s)
__device__ float g_sum[OUTC], g_sumsq[OUTC];

__device__ __forceinline__ uint32_t smem_u32(const void* p) {
    uint32_t a;
    asm("{ .reg .u64 t; cvta.to.shared.u64 t, %1; cvt.u32.u64 %0, t; }" : "=r"(a) : "l"(p));
    return a;
}
__device__ __forceinline__ void split_bf16(float v, bf16& h, bf16& l) {
    h = __float2bfloat16(v);
    l = __float2bfloat16(v - __bfloat162float(h));
}
__device__ __forceinline__ uint32_t pack2(bf16 lo, bf16 hi) {
    return ((uint32_t)__bfloat16_as_ushort(hi) << 16) | __bfloat16_as_ushort(lo);
}
__device__ __forceinline__ float bf_lo(uint32_t u) {
    return __bfloat162float(__ushort_as_bfloat16((unsigned short)(u & 0xFFFF)));
}
__device__ __forceinline__ float bf_hi(uint32_t u) {
    return __bfloat162float(__ushort_as_bfloat16((unsigned short)(u >> 16)));
}
__device__ __forceinline__ void cp16(uint32_t s, const void* g) {
    asm volatile("cp.async.cg.shared.global [%0], [%1], 16;"
                 :: "r"(s), "l"(__cvta_generic_to_global(g)) : "memory");
}
#define CP_COMMIT() asm volatile("cp.async.commit_group;" ::: "memory")
#define CP_WAIT1()  asm volatile("cp.async.wait_group 1;"  ::: "memory")
#define CP_WAIT2()  asm volatile("cp.async.wait_group 2;"  ::: "memory")

#define LDSM_X4(r0,r1,r2,r3,addr) \
    asm volatile("ldmatrix.sync.aligned.m8n8.x4.shared.b16 {%0,%1,%2,%3}, [%4];" \
                 : "=r"(r0), "=r"(r1), "=r"(r2), "=r"(r3) : "r"(addr))
#define LDSM_X4T(r0,r1,r2,r3,addr) \
    asm volatile("ldmatrix.sync.aligned.m8n8.x4.trans.shared.b16 {%0,%1,%2,%3}, [%4];" \
                 : "=r"(r0), "=r"(r1), "=r"(r2), "=r"(r3) : "r"(addr))
#define MMA_BF16(c0,c1,c2,c3,a0,a1,a2,a3,b0,b1) \
    asm volatile("mma.sync.aligned.m16n8k16.row.col.f32.bf16.bf16.f32 " \
                 "{%0,%1,%2,%3}, {%4,%5,%6,%7}, {%8,%9}, {%0,%1,%2,%3};" \
                 : "+f"(c0), "+f"(c1), "+f"(c2), "+f"(c3) \
                 : "r"(a0), "r"(a1), "r"(a2), "r"(a3), "r"(b0), "r"(b1))

// ---------------- prep kernels ----------------
__global__ void prep_M(const float* __restrict__ sup, const float* __restrict__ eps) {
    int idx = blockIdx.x * blockDim.x + threadIdx.x;
    if (idx >= 2 * (int)AS) return;
    int rest = idx & (int)(AS - 1);
    int n = rest >> 9, m = rest & 511;
    float v = sup[idx] + ((n == m) ? (1.0f + eps[0]) : 0.0f);
    bf16 h, l; split_bf16(v, h, l);
    g_Mh[idx] = h; g_Ml[idx] = l;
}

__global__ void prep_W(const float* __restrict__ w) {
    int idx = blockIdx.x * blockDim.x + threadIdx.x;   // ko*768 + d
    if (idx >= ZC * BD) return;
    int d  = idx % BD;
    int ko = idx / BD;
    int k = ko >> 6, o = ko & 63;
    int l = d >> 6, h = d & 63;
    float v = w[((size_t)l * 256 + h * 4 + k) * OUTC + o];
    bf16 hh, ll; split_bf16(v, hh, ll);
    g_Wth[idx] = hh; g_Wtl[idx] = ll;
}

__global__ void split_X(const float* __restrict__ x) {
    int idx = blockIdx.x * blockDim.x + threadIdx.x;
    if (idx >= (int)(ROWS * (size_t)BD / 4)) return;
    float4 v = ((const float4*)x)[idx];
    bf16 h0,l0,h1,l1,h2,l2,h3,l3;
    split_bf16(v.x,h0,l0); split_bf16(v.y,h1,l1);
    split_bf16(v.z,h2,l2); split_bf16(v.w,h3,l3);
    uint2 ph, pl;
    ph.x = pack2(h0,h1); ph.y = pack2(h2,h3);
    pl.x = pack2(l0,l1); pl.y = pack2(l2,l3);
    ((uint2*)g_Xh)[idx] = ph;
    ((uint2*)g_Xl)[idx] = pl;
}

// ---------------- stage1 (HMMA, BK=64, 3-stage cp.async, 512 thr, occ 2) ---------
// CTA 128x128, 16 warps in 4x4 grid of 32x32 warp tiles.
#define S1_PAD 72
#define S1_NCHUNK 36          // 3 parts * 768/64
#define S1_TILE (128 * S1_PAD)
#define S1_SMEM (6 * S1_TILE * 2)   // 3 A + 3 B stages

__global__ __launch_bounds__(512, 2) void stage1_mma() {
    extern __shared__ __align__(16) bf16 sm1[];
    bf16* Asm = sm1;
    bf16* Bsm = sm1 + 3 * S1_TILE;

    const int tid = threadIdx.x;
    const int warp = tid >> 5, lane = tid & 31;
    const int wm = warp >> 2, wn = warp & 3;     // 4x4 warps, 32x32 tiles
    const int g = lane >> 2, q = lane & 3;
    const int r0 = blockIdx.y * 128;
    const int c0 = blockIdx.x * 128;

    // round-5 validated lane-invariant ldmatrix offsets
    const int aRowOff = ((lane >> 3) & 1) * 8 + (lane & 7);
    const int aKOff   = (lane >> 4) * 8;
    const int bRowOff = (lane >> 4) * 8 + (lane & 7);
    const int bKOff   = ((lane >> 3) & 1) * 8;

    uint32_t aB[3], bB[3];
#pragma unroll
    for (int st = 0; st < 3; ++st) {
        aB[st] = smem_u32(Asm + st * S1_TILE);
        bB[st] = smem_u32(Bsm + st * S1_TILE);
    }

    float c[2][4][4];
#pragma unroll
    for (int i = 0; i < 2; ++i)
#pragma unroll
        for (int j = 0; j < 4; ++j)
#pragma unroll
            for (int t = 0; t < 4; ++t) c[i][j][t] = 0.f;

    auto load_stage = [&](int ch) {
        int st = ch % 3;
        int part = ch / 12;
        int kpos = (ch % 12) * 64;
        const bf16* Ap = (part == 1) ? g_Xl : g_Xh;
        const bf16* Bp = (part == 2) ? g_Wtl : g_Wth;
#pragma unroll
        for (int t = 0; t < 2; ++t) {
            int u = tid + t * 512;
            int row = u >> 3, seg = u & 7;
            uint32_t so = (uint32_t)(row * S1_PAD + seg * 8) * 2;
            cp16(aB[st] + so, Ap + (size_t)(r0 + row) * BD + kpos + seg * 8);
            cp16(bB[st] + so, Bp + (size_t)(c0 + row) * BD + kpos + seg * 8);
        }
        CP_COMMIT();
    };

    load_stage(0); load_stage(1);

#pragma unroll 3
    for (int ch = 0; ch < S1_NCHUNK; ++ch) {
        CP_WAIT1();
        __syncthreads();
        int st = ch % 3;
#pragma unroll
        for (int ks = 0; ks < 64; ks += 16) {
            uint32_t a[2][4];
#pragma unroll
            for (int i = 0; i < 2; ++i) {
                uint32_t addr = aB[st]
                    + (uint32_t)(wm * 32 + i * 16 + aRowOff) * (S1_PAD * 2)
                    + (uint32_t)(ks + aKOff) * 2;
                LDSM_X4(a[i][0], a[i][1], a[i][2], a[i][3], addr);
            }
            uint32_t b[4][2];
#pragma unroll
            for (int j2 = 0; j2 < 2; ++j2) {
                uint32_t addr = bB[st]
                    + (uint32_t)(wn * 32 + j2 * 16 + bRowOff) * (S1_PAD * 2)
                    + (uint32_t)(ks + bKOff) * 2;
                uint32_t r0_, r1_, r2_, r3_;
                LDSM_X4(r0_, r1_, r2_, r3_, addr);
                b[2*j2][0]   = r0_; b[2*j2][1]   = r1_;
                b[2*j2+1][0] = r2_; b[2*j2+1][1] = r3_;
            }
#pragma unroll
            for (int i = 0; i < 2; ++i)
#pragma unroll
                for (int j = 0; j < 4; ++j)
                    MMA_BF16(c[i][j][0], c[i][j][1], c[i][j][2], c[i][j][3],
                             a[i][0], a[i][1], a[i][2], a[i][3], b[j][0], b[j][1]);
        }
        if (ch + 2 < S1_NCHUNK) load_stage(ch + 2);
        else CP_COMMIT();   // empty group keeps wait(1) arithmetic exact at tail
    }

    // epilogue: split fp32 -> Zh/Zl bf16
#pragma unroll
    for (int i = 0; i < 2; ++i) {
        int row = r0 + wm * 32 + i * 16 + g;
#pragma unroll
        for (int j = 0; j < 4; ++j) {
            int col = c0 + wn * 32 + j * 8 + 2 * q;
#pragma unroll
            for (int hrow = 0; hrow < 2; ++hrow) {
                float v0 = c[i][j][hrow * 2], v1 = c[i][j][hrow * 2 + 1];
                bf16 h0, l0, h1, l1;
                split_bf16(v0, h0, l0); split_bf16(v1, h1, l1);
                size_t off = (size_t)(row + hrow * 8) * ZC + col;
                *(uint32_t*)&g_Zh[off] = pack2(h0, h1);
                *(uint32_t*)&g_Zl[off] = pack2(l0, l1);
            }
        }
    }
}

// ---------------- stage2a (HMMA): V_s = Z_{2s} + M_s * Z_{2s+1} (fused vadd) -----
// grid (4, BB, 2); z = s. 48 chunks of BK=32 (3 parts * 512/32).
#define S2_APAD 40
#define S2_BPAD 72
#define S2_NCH 48
#define S2_ATILE (128 * S2_APAD)
#define S2_BTILE (32 * S2_BPAD)
#define S2_SMEM ((4 * S2_ATILE + 4 * S2_BTILE) * 2)

__global__ __launch_bounds__(256, 2) void stage2a_mma() {
    extern __shared__ __align__(16) bf16 sm2[];
    bf16* Asm = sm2;
    bf16* Bsm = sm2 + 4 * S2_ATILE;

    const int tid = threadIdx.x;
    const int warp = tid >> 5, lane = tid & 31;
    const int wm = warp >> 1, wn = warp & 1;
    const int g = lane >> 2, q = lane & 3;
    const int n0 = blockIdx.x * 128;
    const int b  = blockIdx.y;
    const int s  = blockIdx.z;

    const int aLdRow = tid >> 2, aLdSeg = tid & 3;
    const int bLdRow = tid >> 3, bLdSeg = tid & 7;
    const int fragRow  = lane & 15;
    const int fragCol8 = (lane >> 4) * 8;

    uint32_t aB[4], bB[4];
#pragma unroll
    for (int st = 0; st < 4; ++st) {
        aB[st] = smem_u32(Asm + st * S2_ATILE);
        bB[st] = smem_u32(Bsm + st * S2_BTILE);
    }

    float c[2][4][4];
#pragma unroll
    for (int i = 0; i < 2; ++i)
#pragma unroll
        for (int j = 0; j < 4; ++j)
#pragma unroll
            for (int t = 0; t < 4; ++t) c[i][j][t] = 0.f;

    const int zcol = (2 * s + 1) * 64;

    auto load_stage = [&](int ch) {
        int st = ch & 3;
        int part = ch >> 4;          // 0,1,2
        int mpos = (ch & 15) * 32;
        const bf16* Am = ((part == 1) ? g_Ml : g_Mh) + (size_t)s * AS;
        cp16(aB[st] + (uint32_t)(aLdRow * S2_APAD + aLdSeg * 8) * 2,
             Am + (size_t)(n0 + aLdRow) * NN + mpos + aLdSeg * 8);
        cp16(aB[st] + (uint32_t)((aLdRow + 64) * S2_APAD + aLdSeg * 8) * 2,
             Am + (size_t)(n0 + aLdRow + 64) * NN + mpos + aLdSeg * 8);
        const bf16* Zp = (part == 2) ? g_Zl : g_Zh;
        cp16(bB[st] + (uint32_t)(bLdRow * S2_BPAD + bLdSeg * 8) * 2,
             Zp + (size_t)(b * NN + mpos + bLdRow) * ZC + zcol + bLdSeg * 8);
        CP_COMMIT();
    };

    load_stage(0); load_stage(1); load_stage(2);

    for (int ch = 0; ch < S2_NCH; ++ch) {
        CP_WAIT2();
        __syncthreads();
        int st = ch & 3;
#pragma unroll
        for (int ks = 0; ks < 32; ks += 16) {
            uint32_t a[2][4];
#pragma unroll
            for (int i = 0; i < 2; ++i) {
                uint32_t addr = aB[st]
                    + (uint32_t)(wm * 32 + i * 16 + fragRow) * (S2_APAD * 2)
                    + (uint32_t)(ks + fragCol8) * 2;
                LDSM_X4(a[i][0], a[i][1], a[i][2], a[i][3], addr);
            }
            uint32_t b_[4][2];
#pragma unroll
            for (int jj = 0; jj < 2; ++jj) {
                uint32_t addr = bB[st]
                    + (uint32_t)(ks + fragRow) * (S2_BPAD * 2)
                    + (uint32_t)(wn * 32 + jj * 16 + fragCol8) * 2;
                uint32_t r0_, r1_, r2_, r3_;
                LDSM_X4T(r0_, r1_, r2_, r3_, addr);
                b_[2*jj][0] = r0_;   b_[2*jj][1] = r1_;
                b_[2*jj+1][0] = r2_; b_[2*jj+1][1] = r3_;
            }
#pragma unroll
            for (int i = 0; i < 2; ++i)
#pragma unroll
                for (int j = 0; j < 4; ++j)
                    MMA_BF16(c[i][j][0], c[i][j][1], c[i][j][2], c[i][j][3],
                             a[i][0], a[i][1], a[i][2], a[i][3], b_[j][0], b_[j][1]);
        }
        if (ch + 3 < S2_NCH) load_stage(ch + 3);
        else CP_COMMIT();
    }

    // fused epilogue: V = Z_even + U, split to bf16 -> Vh/Vl
    const size_t vbase = ((size_t)(s * BB + b) * NN) * OUTC;
#pragma unroll
    for (int i = 0; i < 2; ++i) {
#pragma unroll
        for (int j = 0; j < 4; ++j) {
            int col = wn * 32 + j * 8 + 2 * q;
#pragma unroll
            for (int hrow = 0; hrow < 2; ++hrow) {
                int row = n0 + wm * 32 + i * 16 + g + hrow * 8;
                size_t zo = (size_t)(b * NN + row) * ZC + s * 128 + col;
                uint32_t zh = *(const uint32_t*)&g_Zh[zo];
                uint32_t zl = *(const uint32_t*)&g_Zl[zo];
                float v0 = c[i][j][hrow * 2]     + bf_lo(zh) + bf_lo(zl);
                float v1 = c[i][j][hrow * 2 + 1] + bf_hi(zh) + bf_hi(zl);
                bf16 h0, l0, h1, l1;
                split_bf16(v0, h0, l0); split_bf16(v1, h1, l1);
                size_t vo = vbase + (size_t)row * OUTC + col;
                *(uint32_t*)&g_Vh[vo] = pack2(h0, h1);
                *(uint32_t*)&g_Vl[vo] = pack2(l0, l1);
            }
        }
    }
}

// ---------------- stage2b (HMMA): midp[s] = M_s * V_s ----------------------------
__global__ __launch_bounds__(256, 2) void stage2b_mma() {
    extern __shared__ __align__(16) bf16 sm3[];
    bf16* Asm = sm3;
    bf16* Bsm = sm3 + 4 * S2_ATILE;

    const int tid = threadIdx.x;
    const int warp = tid >> 5, lane = tid & 31;
    const int wm = warp >> 1, wn = warp & 1;
    const int g = lane >> 2, q = lane & 3;
    const int n0 = blockIdx.x * 128;
    const int b  = blockIdx.y;
    const int s  = blockIdx.z;

    const int aLdRow = tid >> 2, aLdSeg = tid & 3;
    const int bLdRow = tid >> 3, bLdSeg = tid & 7;
    const int fragRow  = lane & 15;
    const int fragCol8 = (lane >> 4) * 8;

    uint32_t aB[4], bB[4];
#pragma unroll
    for (int st = 0; st < 4; ++st) {
        aB[st] = smem_u32(Asm + st * S2_ATILE);
        bB[st] = smem_u32(Bsm + st * S2_BTILE);
    }

    float c[2][4][4];
#pragma unroll
    for (int i = 0; i < 2; ++i)
#pragma unroll
        for (int j = 0; j < 4; ++j)
#pragma unroll
            for (int t = 0; t < 4; ++t) c[i][j][t] = 0.f;

    const size_t vbase = ((size_t)(s * BB + b) * NN) * OUTC;

    auto load_stage = [&](int ch) {
        int st = ch & 3;
        int part = ch >> 4;          // 0,1,2
        int mpos = (ch & 15) * 32;
        const bf16* Am = ((part == 1) ? g_Ml : g_Mh) + (size_t)s * AS;
        cp16(aB[st] + (uint32_t)(aLdRow * S2_APAD + aLdSeg * 8) * 2,
             Am + (size_t)(n0 + aLdRow) * NN + mpos + aLdSeg * 8);
        cp16(aB[st] + (uint32_t)((aLdRow + 64) * S2_APAD + aLdSeg * 8) * 2,
             Am + (size_t)(n0 + aLdRow + 64) * NN + mpos + aLdSeg * 8);
        const bf16* Vp = (part == 2) ? g_Vl : g_Vh;
        cp16(bB[st] + (uint32_t)(bLdRow * S2_BPAD + bLdSeg * 8) * 2,
             Vp + vbase + (size_t)(mpos + bLdRow) * OUTC + bLdSeg * 8);
        CP_COMMIT();
    };

    load_stage(0); load_stage(1); load_stage(2);

    for (int ch = 0; ch < S2_NCH; ++ch) {
        CP_WAIT2();
        __syncthreads();
        int st = ch & 3;
#pragma unroll
        for (int ks = 0; ks < 32; ks += 16) {
            uint32_t a[2][4];
#pragma unroll
            for (int i = 0; i < 2; ++i) {
                uint32_t addr = aB[st]
                    + (uint32_t)(wm * 32 + i * 16 + fragRow) * (S2_APAD * 2)
                    + (uint32_t)(ks + fragCol8) * 2;
                LDSM_X4(a[i][0], a[i][1], a[i][2], a[i][3], addr);
            }
            uint32_t b_[4][2];
#pragma unroll
            for (int jj = 0; jj < 2; ++jj) {
                uint32_t addr = bB[st]
                    + (uint32_t)(ks + fragRow) * (S2_BPAD * 2)
                    + (uint32_t)(wn * 32 + jj * 16 + fragCol8) * 2;
                uint32_t r0_, r1_, r2_, r3_;
                LDSM_X4T(r0_, r1_, r2_, r3_, addr);
                b_[2*jj][0] = r0_;   b_[2*jj][1] = r1_;
                b_[2*jj+1][0] = r2_; b_[2*jj+1][1] = r3_;
            }
#pragma unroll
            for (int i = 0; i < 2; ++i)
#pragma unroll
                for (int j = 0; j < 4; ++j)
                    MMA_BF16(c[i][j][0], c[i][j][1], c[i][j][2], c[i][j][3],
                             a[i][0], a[i][1], a[i][2], a[i][3], b_[j][0], b_[j][1]);
        }
        if (ch + 3 < S2_NCH) load_stage(ch + 3);
        else CP_COMMIT();
    }

    float* O = g_midp[s];
#pragma unroll
    for (int i = 0; i < 2; ++i) {
        int row = n0 + wm * 32 + i * 16 + g;
#pragma unroll
        for (int j = 0; j < 4; ++j) {
            int col = wn * 32 + j * 8 + 2 * q;
            float2 v0 = { c[i][j][0], c[i][j][1] };
            float2 v1 = { c[i][j][2], c[i][j][3] };
            *(float2*)&O[(size_t)(b * NN + row) * OUTC + col] = v0;
            *(float2*)&O[(size_t)(b * NN + row + 8) * OUTC + col] = v1;
        }
    }
}

// ---------------- BN tail (reads both slabs directly) ----------------
__global__ void zero_stats() {
    if (threadIdx.x < OUTC) { g_sum[threadIdx.x] = 0.f; g_sumsq[threadIdx.x] = 0.f; }
}
__global__ __launch_bounds__(256) void bn_stats() {
    const int c = threadIdx.x & 63;
    const int rl = threadIdx.x >> 6;
    float s = 0.f, s2 = 0.f;
    for (int r = blockIdx.x * 4 + rl; r < ROWS; r += gridDim.x * 4) {
        size_t off = (size_t)r * OUTC + c;
        float v = g_midp[0][off] + g_midp[1][off];
        s += v; s2 += v * v;
    }
    __shared__ float sh[256], sh2[256];
    sh[threadIdx.x] = s; sh2[threadIdx.x] = s2;
    __syncthreads();
    if (rl == 0) {
        s  = sh[c] + sh[c + 64] + sh[c + 128] + sh[c + 192];
        s2 = sh2[c] + sh2[c + 64] + sh2[c + 128] + sh2[c + 192];
        atomicAdd(&g_sum[c], s); atomicAdd(&g_sumsq[c], s2);
    }
}
__global__ __launch_bounds__(256) void bn_relu_fc2(
    const float* __restrict__ gamma, const float* __restrict__ beta,
    const float* __restrict__ w2,    const float* __restrict__ b2,
    float* __restrict__ out)
{
    __shared__ float w2t[64][65];
    __shared__ float ysm[64][65];
    __shared__ float scale_s[64], shift_s[64];
    const int tid = threadIdx.x;
    const int r0 = blockIdx.x * 64;

#pragma unroll
    for (int t = 0; t < 16; ++t) {
        int idx = tid + t * 256;
        int o = idx >> 6, cc = idx & 63;
        w2t[cc][o] = w2[idx];
    }
    if (tid < OUTC) {
        const float invN = 1.0f / (float)ROWS;
        float mean = g_sum[tid] * invN;
        float var  = g_sumsq[tid] * invN - mean * mean;
        float sc   = gamma[tid] * rsqrtf(var + 1e-5f);
        scale_s[tid] = sc;
        shift_s[tid] = beta[tid] - mean * sc;
    }
    __syncthreads();

#pragma unroll
    for (int t = 0; t < 16; ++t) {
        int idx = tid + t * 256;
        int r = idx >> 6, cc = idx & 63;
        size_t off = (size_t)(r0 + r) * OUTC + cc;
        float v = g_midp[0][off] + g_midp[1][off];
        ysm[r][cc] = fmaxf(fmaf(v, scale_s[cc], shift_s[cc]), 0.f);
    }
    __syncthreads();

    const int tr = tid >> 4, tc = tid & 15;
    float acc[4][4];
#pragma unroll
    for (int i = 0; i < 4; ++i)
#pragma unroll
        for (int j = 0; j < 4; ++j) acc[i][j] = b2[tc * 4 + j];
    for (int k = 0; k < 64; ++k) {
        float w0 = w2t[k][tc * 4 + 0], w1 = w2t[k][tc * 4 + 1];
        float w2v = w2t[k][tc * 4 + 2], w3 = w2t[k][tc * 4 + 3];
#pragma unroll
        for (int i = 0; i < 4; ++i) {
            float y = ysm[tr * 4 + i][k];
            acc[i][0] = fmaf(y, w0, acc[i][0]);
            acc[i][1] = fmaf(y, w1, acc[i][1]);
            acc[i][2] = fmaf(y, w2v, acc[i][2]);
            acc[i][3] = fmaf(y, w3, acc[i][3]);
        }
    }
#pragma unroll
    for (int i = 0; i < 4; ++i)
        *(float4*)&out[(size_t)(r0 + tr * 4 + i) * OUTC + tc * 4] = *(float4*)&acc[i][0];
}

// ---------------- launch ----------------
extern "C" void kernel_launch(void* const* d_in, const int* in_sizes, int n_in,
                              void* d_out, int out_size) {
    const float* x       = (const float*)d_in[0];
    const float* support = (const float*)d_in[1];
    const float* weight  = (const float*)d_in[2];
    const float* eps     = (const float*)d_in[3];
    const float* gamma   = (const float*)d_in[4];
    const float* beta    = (const float*)d_in[5];
    const float* w2      = (const float*)d_in[6];
    const float* b2      = (const float*)d_in[7];
    float* out           = (float*)d_out;

    cudaFuncSetAttribute(stage1_mma,  cudaFuncAttributeMaxDynamicSharedMemorySize, S1_SMEM);
    cudaFuncSetAttribute(stage2a_mma, cudaFuncAttributeMaxDynamicSharedMemorySize, S2_SMEM);
    cudaFuncSetAttribute(stage2b_mma, cudaFuncAttributeMaxDynamicSharedMemorySize, S2_SMEM);

    prep_M<<<(2 * (int)AS + 255) / 256, 256>>>(support, eps);
    prep_W<<<(ZC * BD + 255) / 256, 256>>>(weight);
    split_X<<<(int)(ROWS * (size_t)BD / 4 + 255) / 256, 256>>>(x);

    stage1_mma<<<dim3(ZC / 128, ROWS / 128), 512, S1_SMEM>>>();

    stage2a_mma<<<dim3(NN / 128, BB, 2), 256, S2_SMEM>>>();
    stage2b_mma<<<dim3(NN / 128, BB, 2), 256, S2_SMEM>>>();

    zero_stats<<<1, 64>>>();
    bn_stats<<<128, 256>>>();
    bn_relu_fc2<<<ROWS / 64, 256>>>(gamma, beta, w2, b2, out);
}

// round 12
// speedup vs baseline: 1.0640x; 1.0640x over previous
#include <cuda_runtime.h>
#include <cuda_bf16.h>
#include <math.h>
#include <stdint.h>

typedef __nv_bfloat16 bf16;

// ---------------- problem dims ----------------
#define BB    32
#define NN    512
#define BD    768            // L*H
#define ROWS  (BB*NN)        // 16384
#define OUTC  64
#define KSUP  4
#define ZC    256            // KSUP*OUTC
#define AS    ((size_t)NN*NN)

// ---------------- device scratch (no allocation) ----------------
__device__ __align__(256) bf16  g_Mh [2*AS], g_Ml [2*AS];    // M = A+(1+eps)I, split
__device__ __align__(256) bf16  g_Xh[(size_t)ROWS*BD], g_Xl[(size_t)ROWS*BD];
__device__ __align__(256) bf16  g_Wth[ZC*BD], g_Wtl[ZC*BD];  // W^T repack [ko][d]
__device__ __align__(256) bf16  g_Zh[(size_t)ROWS*ZC], g_Zl[(size_t)ROWS*ZC];
__device__ __align__(256) bf16  g_Vh[(size_t)2*ROWS*OUTC], g_Vl[(size_t)2*ROWS*OUTC];
__device__ __align__(256) float g_midp[2][(size_t)ROWS*OUTC]; // stage2b slabs (per s)
__device__ float g_sum[OUTC], g_sumsq[OUTC];

__device__ __forceinline__ uint32_t smem_u32(const void* p) {
    uint32_t a;
    asm("{ .reg .u64 t; cvta.to.shared.u64 t, %1; cvt.u32.u64 %0, t; }" : "=r"(a) : "l"(p));
    return a;
}
__device__ __forceinline__ void split_bf16(float v, bf16& h, bf16& l) {
    h = __float2bfloat16(v);
    l = __float2bfloat16(v - __bfloat162float(h));
}
__device__ __forceinline__ uint32_t pack2(bf16 lo, bf16 hi) {
    return ((uint32_t)__bfloat16_as_ushort(hi) << 16) | __bfloat16_as_ushort(lo);
}
__device__ __forceinline__ float bf_lo(uint32_t u) {
    return __bfloat162float(__ushort_as_bfloat16((unsigned short)(u & 0xFFFF)));
}
__device__ __forceinline__ float bf_hi(uint32_t u) {
    return __bfloat162float(__ushort_as_bfloat16((unsigned short)(u >> 16)));
}
__device__ __forceinline__ void cp16(uint32_t s, const void* g) {
    asm volatile("cp.async.cg.shared.global [%0], [%1], 16;"
                 :: "r"(s), "l"(__cvta_generic_to_global(g)) : "memory");
}
#define CP_COMMIT() asm volatile("cp.async.commit_group;" ::: "memory")
#define CP_WAIT1()  asm volatile("cp.async.wait_group 1;"  ::: "memory")

#define LDSM_X4(r0,r1,r2,r3,addr) \
    asm volatile("ldmatrix.sync.aligned.m8n8.x4.shared.b16 {%0,%1,%2,%3}, [%4];" \
                 : "=r"(r0), "=r"(r1), "=r"(r2), "=r"(r3) : "r"(addr))
#define LDSM_X4T(r0,r1,r2,r3,addr) \
    asm volatile("ldmatrix.sync.aligned.m8n8.x4.trans.shared.b16 {%0,%1,%2,%3}, [%4];" \
                 : "=r"(r0), "=r"(r1), "=r"(r2), "=r"(r3) : "r"(addr))
#define MMA_BF16(c0,c1,c2,c3,a0,a1,a2,a3,b0,b1) \
    asm volatile("mma.sync.aligned.m16n8k16.row.col.f32.bf16.bf16.f32 " \
                 "{%0,%1,%2,%3}, {%4,%5,%6,%7}, {%8,%9}, {%0,%1,%2,%3};" \
                 : "+f"(c0), "+f"(c1), "+f"(c2), "+f"(c3) \
                 : "r"(a0), "r"(a1), "r"(a2), "r"(a3), "r"(b0), "r"(b1))

// ---------------- prep kernels ----------------
__global__ void prep_M(const float* __restrict__ sup, const float* __restrict__ eps) {
    int idx = blockIdx.x * blockDim.x + threadIdx.x;
    if (idx >= 2 * (int)AS) return;
    int rest = idx & (int)(AS - 1);
    int n = rest >> 9, m = rest & 511;
    float v = sup[idx] + ((n == m) ? (1.0f + eps[0]) : 0.0f);
    bf16 h, l; split_bf16(v, h, l);
    g_Mh[idx] = h; g_Ml[idx] = l;
}

__global__ void prep_W(const float* __restrict__ w) {
    int idx = blockIdx.x * blockDim.x + threadIdx.x;   // ko*768 + d
    if (idx >= ZC * BD) return;
    int d  = idx % BD;
    int ko = idx / BD;
    int k = ko >> 6, o = ko & 63;
    int l = d >> 6, h = d & 63;
    float v = w[((size_t)l * 256 + h * 4 + k) * OUTC + o];
    bf16 hh, ll; split_bf16(v, hh, ll);
    g_Wth[idx] = hh; g_Wtl[idx] = ll;
}

__global__ void split_X(const float* __restrict__ x) {
    int idx = blockIdx.x * blockDim.x + threadIdx.x;
    if (idx >= (int)(ROWS * (size_t)BD / 4)) return;
    float4 v = ((const float4*)x)[idx];
    bf16 h0,l0,h1,l1,h2,l2,h3,l3;
    split_bf16(v.x,h0,l0); split_bf16(v.y,h1,l1);
    split_bf16(v.z,h2,l2); split_bf16(v.w,h3,l3);
    uint2 ph, pl;
    ph.x = pack2(h0,h1); ph.y = pack2(h2,h3);
    pl.x = pack2(l0,l1); pl.y = pack2(l2,l3);
    ((uint2*)g_Xh)[idx] = ph;
    ((uint2*)g_Xl)[idx] = pl;
}

// ---------------- stage1 (round-10 proven: 256 thr, 32x64 tiles, BK=64) ----------
#define S1_PAD 72
#define S1_NCHUNK 36          // 3 parts * 768/64
#define S1_TILE (128 * S1_PAD)
#define S1_SMEM (6 * S1_TILE * 2)   // 3 A + 3 B stages

__global__ __launch_bounds__(256, 2) void stage1_mma() {
    extern __shared__ __align__(16) bf16 sm1[];
    bf16* Asm = sm1;
    bf16* Bsm = sm1 + 3 * S1_TILE;

    const int tid = threadIdx.x;
    const int warp = tid >> 5, lane = tid & 31;
    const int wm = warp >> 1, wn = warp & 1;
    const int g = lane >> 2, q = lane & 3;
    const int r0 = blockIdx.y * 128;
    const int c0 = blockIdx.x * 128;

    // round-5 validated lane-invariant ldmatrix offsets
    const int aRowOff = ((lane >> 3) & 1) * 8 + (lane & 7);
    const int aKOff   = (lane >> 4) * 8;
    const int bRowOff = (lane >> 4) * 8 + (lane & 7);
    const int bKOff   = ((lane >> 3) & 1) * 8;

    uint32_t aB[3], bB[3];
#pragma unroll
    for (int st = 0; st < 3; ++st) {
        aB[st] = smem_u32(Asm + st * S1_TILE);
        bB[st] = smem_u32(Bsm + st * S1_TILE);
    }

    float c[2][8][4];
#pragma unroll
    for (int i = 0; i < 2; ++i)
#pragma unroll
        for (int j = 0; j < 8; ++j)
#pragma unroll
            for (int t = 0; t < 4; ++t) c[i][j][t] = 0.f;

    auto load_stage = [&](int ch) {
        int st = ch % 3;
        int part = ch / 12;
        int kpos = (ch % 12) * 64;
        const bf16* Ap = (part == 1) ? g_Xl : g_Xh;
        const bf16* Bp = (part == 2) ? g_Wtl : g_Wth;
#pragma unroll
        for (int t = 0; t < 4; ++t) {
            int u = tid + t * 256;
            int row = u >> 3, seg = u & 7;
            uint32_t so = (uint32_t)(row * S1_PAD + seg * 8) * 2;
            cp16(aB[st] + so, Ap + (size_t)(r0 + row) * BD + kpos + seg * 8);
            cp16(bB[st] + so, Bp + (size_t)(c0 + row) * BD + kpos + seg * 8);
        }
        CP_COMMIT();
    };

    load_stage(0); load_stage(1);

#pragma unroll 3
    for (int ch = 0; ch < S1_NCHUNK; ++ch) {
        CP_WAIT1();
        __syncthreads();
        int st = ch % 3;
#pragma unroll
        for (int ks = 0; ks < 64; ks += 16) {
            uint32_t a[2][4];
#pragma unroll
            for (int i = 0; i < 2; ++i) {
                uint32_t addr = aB[st]
                    + (uint32_t)(wm * 32 + i * 16 + aRowOff) * (S1_PAD * 2)
                    + (uint32_t)(ks + aKOff) * 2;
                LDSM_X4(a[i][0], a[i][1], a[i][2], a[i][3], addr);
            }
            uint32_t b[8][2];
#pragma unroll
            for (int j2 = 0; j2 < 4; ++j2) {
                uint32_t addr = bB[st]
                    + (uint32_t)(wn * 64 + j2 * 16 + bRowOff) * (S1_PAD * 2)
                    + (uint32_t)(ks + bKOff) * 2;
                uint32_t r0_, r1_, r2_, r3_;
                LDSM_X4(r0_, r1_, r2_, r3_, addr);
                b[2*j2][0]   = r0_; b[2*j2][1]   = r1_;
                b[2*j2+1][0] = r2_; b[2*j2+1][1] = r3_;
            }
#pragma unroll
            for (int i = 0; i < 2; ++i)
#pragma unroll
                for (int j = 0; j < 8; ++j)
                    MMA_BF16(c[i][j][0], c[i][j][1], c[i][j][2], c[i][j][3],
                             a[i][0], a[i][1], a[i][2], a[i][3], b[j][0], b[j][1]);
        }
        if (ch + 2 < S1_NCHUNK) load_stage(ch + 2);
        else CP_COMMIT();   // empty group keeps wait(1) arithmetic exact at tail
    }

    // epilogue: split fp32 -> Zh/Zl bf16
#pragma unroll
    for (int i = 0; i < 2; ++i) {
        int row = r0 + wm * 32 + i * 16 + g;
#pragma unroll
        for (int j = 0; j < 8; ++j) {
            int col = c0 + wn * 64 + j * 8 + 2 * q;
#pragma unroll
            for (int hrow = 0; hrow < 2; ++hrow) {
                float v0 = c[i][j][hrow * 2], v1 = c[i][j][hrow * 2 + 1];
                bf16 h0, l0, h1, l1;
                split_bf16(v0, h0, l0); split_bf16(v1, h1, l1);
                size_t off = (size_t)(row + hrow * 8) * ZC + col;
                *(uint32_t*)&g_Zh[off] = pack2(h0, h1);
                *(uint32_t*)&g_Zl[off] = pack2(l0, l1);
            }
        }
    }
}

// ---------------- stage2 common: BK=64, 3-stage, CTA 128n x 64 cols --------------
#define S2_APAD 72
#define S2_BPAD 72
#define S2_NCH 24             // 3 parts * 512/64
#define S2_ATILE (128 * S2_APAD)
#define S2_BTILE (64 * S2_BPAD)
#define S2_SMEM ((3 * S2_ATILE + 3 * S2_BTILE) * 2)

// stage2a: V_s = Z_{2s} + M_s * Z_{2s+1}  (fused vadd epilogue)
__global__ __launch_bounds__(256, 2) void stage2a_mma() {
    extern __shared__ __align__(16) bf16 sm2[];
    bf16* Asm = sm2;
    bf16* Bsm = sm2 + 3 * S2_ATILE;

    const int tid = threadIdx.x;
    const int warp = tid >> 5, lane = tid & 31;
    const int wm = warp >> 1, wn = warp & 1;
    const int g = lane >> 2, q = lane & 3;
    const int n0 = blockIdx.x * 128;
    const int b  = blockIdx.y;
    const int s  = blockIdx.z;

    const int fragRow  = lane & 15;
    const int fragCol8 = (lane >> 4) * 8;

    uint32_t aB[3], bB[3];
#pragma unroll
    for (int st = 0; st < 3; ++st) {
        aB[st] = smem_u32(Asm + st * S2_ATILE);
        bB[st] = smem_u32(Bsm + st * S2_BTILE);
    }

    float c[2][4][4];
#pragma unroll
    for (int i = 0; i < 2; ++i)
#pragma unroll
        for (int j = 0; j < 4; ++j)
#pragma unroll
            for (int t = 0; t < 4; ++t) c[i][j][t] = 0.f;

    const int zcol = (2 * s + 1) * 64;

    auto load_stage = [&](int ch) {
        int st = ch % 3;
        int part = ch / 8;           // 0,1,2
        int mpos = (ch % 8) * 64;
        const bf16* Am = ((part == 1) ? g_Ml : g_Mh) + (size_t)s * AS;
#pragma unroll
        for (int t = 0; t < 4; ++t) {
            int u = tid + t * 256;
            int row = u >> 3, seg = u & 7;
            cp16(aB[st] + (uint32_t)(row * S2_APAD + seg * 8) * 2,
                 Am + (size_t)(n0 + row) * NN + mpos + seg * 8);
        }
        const bf16* Zp = (part == 2) ? g_Zl : g_Zh;
#pragma unroll
        for (int t = 0; t < 2; ++t) {
            int u = tid + t * 256;
            int row = u >> 3, seg = u & 7;
            cp16(bB[st] + (uint32_t)(row * S2_BPAD + seg * 8) * 2,
                 Zp + (size_t)(b * NN + mpos + row) * ZC + zcol + seg * 8);
        }
        CP_COMMIT();
    };

    load_stage(0); load_stage(1);

#pragma unroll 3
    for (int ch = 0; ch < S2_NCH; ++ch) {
        CP_WAIT1();
        __syncthreads();
        int st = ch % 3;
#pragma unroll
        for (int ks = 0; ks < 64; ks += 16) {
            uint32_t a[2][4];
#pragma unroll
            for (int i = 0; i < 2; ++i) {
                uint32_t addr = aB[st]
                    + (uint32_t)(wm * 32 + i * 16 + fragRow) * (S2_APAD * 2)
                    + (uint32_t)(ks + fragCol8) * 2;
                LDSM_X4(a[i][0], a[i][1], a[i][2], a[i][3], addr);
            }
            uint32_t b_[4][2];
#pragma unroll
            for (int jj = 0; jj < 2; ++jj) {
                uint32_t addr = bB[st]
                    + (uint32_t)(ks + fragRow) * (S2_BPAD * 2)
                    + (uint32_t)(wn * 32 + jj * 16 + fragCol8) * 2;
                uint32_t r0_, r1_, r2_, r3_;
                LDSM_X4T(r0_, r1_, r2_, r3_, addr);
                b_[2*jj][0] = r0_;   b_[2*jj][1] = r1_;
                b_[2*jj+1][0] = r2_; b_[2*jj+1][1] = r3_;
            }
#pragma unroll
            for (int i = 0; i < 2; ++i)
#pragma unroll
                for (int j = 0; j < 4; ++j)
                    MMA_BF16(c[i][j][0], c[i][j][1], c[i][j][2], c[i][j][3],
                             a[i][0], a[i][1], a[i][2], a[i][3], b_[j][0], b_[j][1]);
        }
        if (ch + 2 < S2_NCH) load_stage(ch + 2);
        else CP_COMMIT();
    }

    // fused epilogue: V = Z_even + U, split to bf16 -> Vh/Vl
    const size_t vbase = ((size_t)(s * BB + b) * NN) * OUTC;
#pragma unroll
    for (int i = 0; i < 2; ++i) {
#pragma unroll
        for (int j = 0; j < 4; ++j) {
            int col = wn * 32 + j * 8 + 2 * q;
#pragma unroll
            for (int hrow = 0; hrow < 2; ++hrow) {
                int row = n0 + wm * 32 + i * 16 + g + hrow * 8;
                size_t zo = (size_t)(b * NN + row) * ZC + s * 128 + col;
                uint32_t zh = *(const uint32_t*)&g_Zh[zo];
                uint32_t zl = *(const uint32_t*)&g_Zl[zo];
                float v0 = c[i][j][hrow * 2]     + bf_lo(zh) + bf_lo(zl);
                float v1 = c[i][j][hrow * 2 + 1] + bf_hi(zh) + bf_hi(zl);
                bf16 h0, l0, h1, l1;
                split_bf16(v0, h0, l0); split_bf16(v1, h1, l1);
                size_t vo = vbase + (size_t)row * OUTC + col;
                *(uint32_t*)&g_Vh[vo] = pack2(h0, h1);
                *(uint32_t*)&g_Vl[vo] = pack2(l0, l1);
            }
        }
    }
}

// stage2b: midp[s] = M_s * V_s
__global__ __launch_bounds__(256, 2) void stage2b_mma() {
    extern __shared__ __align__(16) bf16 sm3[];
    bf16* Asm = sm3;
    bf16* Bsm = sm3 + 3 * S2_ATILE;

    const int tid = threadIdx.x;
    const int warp = tid >> 5, lane = tid & 31;
    const int wm = warp >> 1, wn = warp & 1;
    const int g = lane >> 2, q = lane & 3;
    const int n0 = blockIdx.x * 128;
    const int b  = blockIdx.y;
    const int s  = blockIdx.z;

    const int fragRow  = lane & 15;
    const int fragCol8 = (lane >> 4) * 8;

    uint32_t aB[3], bB[3];
#pragma unroll
    for (int st = 0; st < 3; ++st) {
        aB[st] = smem_u32(Asm + st * S2_ATILE);
        bB[st] = smem_u32(Bsm + st * S2_BTILE);
    }

    float c[2][4][4];
#pragma unroll
    for (int i = 0; i < 2; ++i)
#pragma unroll
        for (int j = 0; j < 4; ++j)
#pragma unroll
            for (int t = 0; t < 4; ++t) c[i][j][t] = 0.f;

    const size_t vbase = ((size_t)(s * BB + b) * NN) * OUTC;

    auto load_stage = [&](int ch) {
        int st = ch % 3;
        int part = ch / 8;
        int mpos = (ch % 8) * 64;
        const bf16* Am = ((part == 1) ? g_Ml : g_Mh) + (size_t)s * AS;
#pragma unroll
        for (int t = 0; t < 4; ++t) {
            int u = tid + t * 256;
            int row = u >> 3, seg = u & 7;
            cp16(aB[st] + (uint32_t)(row * S2_APAD + seg * 8) * 2,
                 Am + (size_t)(n0 + row) * NN + mpos + seg * 8);
        }
        const bf16* Vp = (part == 2) ? g_Vl : g_Vh;
#pragma unroll
        for (int t = 0; t < 2; ++t) {
            int u = tid + t * 256;
            int row = u >> 3, seg = u & 7;
            cp16(bB[st] + (uint32_t)(row * S2_BPAD + seg * 8) * 2,
                 Vp + vbase + (size_t)(mpos + row) * OUTC + seg * 8);
        }
        CP_COMMIT();
    };

    load_stage(0); load_stage(1);

#pragma unroll 3
    for (int ch = 0; ch < S2_NCH; ++ch) {
        CP_WAIT1();
        __syncthreads();
        int st = ch % 3;
#pragma unroll
        for (int ks = 0; ks < 64; ks += 16) {
            uint32_t a[2][4];
#pragma unroll
            for (int i = 0; i < 2; ++i) {
                uint32_t addr = aB[st]
                    + (uint32_t)(wm * 32 + i * 16 + fragRow) * (S2_APAD * 2)
                    + (uint32_t)(ks + fragCol8) * 2;
                LDSM_X4(a[i][0], a[i][1], a[i][2], a[i][3], addr);
            }
            uint32_t b_[4][2];
#pragma unroll
            for (int jj = 0; jj < 2; ++jj) {
                uint32_t addr = bB[st]
                    + (uint32_t)(ks + fragRow) * (S2_BPAD * 2)
                    + (uint32_t)(wn * 32 + jj * 16 + fragCol8) * 2;
                uint32_t r0_, r1_, r2_, r3_;
                LDSM_X4T(r0_, r1_, r2_, r3_, addr);
                b_[2*jj][0] = r0_;   b_[2*jj][1] = r1_;
                b_[2*jj+1][0] = r2_; b_[2*jj+1][1] = r3_;
            }
#pragma unroll
            for (int i = 0; i < 2; ++i)
#pragma unroll
                for (int j = 0; j < 4; ++j)
                    MMA_BF16(c[i][j][0], c[i][j][1], c[i][j][2], c[i][j][3],
                             a[i][0], a[i][1], a[i][2], a[i][3], b_[j][0], b_[j][1]);
        }
        if (ch + 2 < S2_NCH) load_stage(ch + 2);
        else CP_COMMIT();
    }

    float* O = g_midp[s];
#pragma unroll
    for (int i = 0; i < 2; ++i) {
        int row = n0 + wm * 32 + i * 16 + g;
#pragma unroll
        for (int j = 0; j < 4; ++j) {
            int col = wn * 32 + j * 8 + 2 * q;
            float2 v0 = { c[i][j][0], c[i][j][1] };
            float2 v1 = { c[i][j][2], c[i][j][3] };
            *(float2*)&O[(size_t)(b * NN + row) * OUTC + col] = v0;
            *(float2*)&O[(size_t)(b * NN + row + 8) * OUTC + col] = v1;
        }
    }
}

// ---------------- BN tail (reads both slabs directly) ----------------
__global__ void zero_stats() {
    if (threadIdx.x < OUTC) { g_sum[threadIdx.x] = 0.f; g_sumsq[threadIdx.x] = 0.f; }
}
__global__ __launch_bounds__(256) void bn_stats() {
    const int c = threadIdx.x & 63;
    const int rl = threadIdx.x >> 6;
    float s = 0.f, s2 = 0.f;
    for (int r = blockIdx.x * 4 + rl; r < ROWS; r += gridDim.x * 4) {
        size_t off = (size_t)r * OUTC + c;
        float v = g_midp[0][off] + g_midp[1][off];
        s += v; s2 += v * v;
    }
    __shared__ float sh[256], sh2[256];
    sh[threadIdx.x] = s; sh2[threadIdx.x] = s2;
    __syncthreads();
    if (rl == 0) {
        s  = sh[c] + sh[c + 64] + sh[c + 128] + sh[c + 192];
        s2 = sh2[c] + sh2[c + 64] + sh2[c + 128] + sh2[c + 192];
        atomicAdd(&g_sum[c], s); atomicAdd(&g_sumsq[c], s2);
    }
}
__global__ __launch_bounds__(256) void bn_relu_fc2(
    const float* __restrict__ gamma, const float* __restrict__ beta,
    const float* __restrict__ w2,    const float* __restrict__ b2,
    float* __restrict__ out)
{
    __shared__ float w2t[64][65];
    __shared__ float ysm[64][65];
    __shared__ float scale_s[64], shift_s[64];
    const int tid = threadIdx.x;
    const int r0 = blockIdx.x * 64;

#pragma unroll
    for (int t = 0; t < 16; ++t) {
        int idx = tid + t * 256;
        int o = idx >> 6, cc = idx & 63;
        w2t[cc][o] = w2[idx];
    }
    if (tid < OUTC) {
        const float invN = 1.0f / (float)ROWS;
        float mean = g_sum[tid] * invN;
        float var  = g_sumsq[tid] * invN - mean * mean;
        float sc   = gamma[tid] * rsqrtf(var + 1e-5f);
        scale_s[tid] = sc;
        shift_s[tid] = beta[tid] - mean * sc;
    }
    __syncthreads();

#pragma unroll
    for (int t = 0; t < 16; ++t) {
        int idx = tid + t * 256;
        int r = idx >> 6, cc = idx & 63;
        size_t off = (size_t)(r0 + r) * OUTC + cc;
        float v = g_midp[0][off] + g_midp[1][off];
        ysm[r][cc] = fmaxf(fmaf(v, scale_s[cc], shift_s[cc]), 0.f);
    }
    __syncthreads();

    const int tr = tid >> 4, tc = tid & 15;
    float acc[4][4];
#pragma unroll
    for (int i = 0; i < 4; ++i)
#pragma unroll
        for (int j = 0; j < 4; ++j) acc[i][j] = b2[tc * 4 + j];
    for (int k = 0; k < 64; ++k) {
        float w0 = w2t[k][tc * 4 + 0], w1 = w2t[k][tc * 4 + 1];
        float w2v = w2t[k][tc * 4 + 2], w3 = w2t[k][tc * 4 + 3];
#pragma unroll
        for (int i = 0; i < 4; ++i) {
            float y = ysm[tr * 4 + i][k];
            acc[i][0] = fmaf(y, w0, acc[i][0]);
            acc[i][1] = fmaf(y, w1, acc[i][1]);
            acc[i][2] = fmaf(y, w2v, acc[i][2]);
            acc[i][3] = fmaf(y, w3, acc[i][3]);
        }
    }
#pragma unroll
    for (int i = 0; i < 4; ++i)
        *(float4*)&out[(size_t)(r0 + tr * 4 + i) * OUTC + tc * 4] = *(float4*)&acc[i][0];
}

// ---------------- launch ----------------
extern "C" void kernel_launch(void* const* d_in, const int* in_sizes, int n_in,
                              void* d_out, int out_size) {
    const float* x       = (const float*)d_in[0];
    const float* support = (const float*)d_in[1];
    const float* weight  = (const float*)d_in[2];
    const float* eps     = (const float*)d_in[3];
    const float* gamma   = (const float*)d_in[4];
    const float* beta    = (const float*)d_in[5];
    const float* w2      = (const float*)d_in[6];
    const float* b2      = (const float*)d_in[7];
    float* out           = (float*)d_out;

    cudaFuncSetAttribute(stage1_mma,  cudaFuncAttributeMaxDynamicSharedMemorySize, S1_SMEM);
    cudaFuncSetAttribute(stage2a_mma, cudaFuncAttributeMaxDynamicSharedMemorySize, S2_SMEM);
    cudaFuncSetAttribute(stage2b_mma, cudaFuncAttributeMaxDynamicSharedMemorySize, S2_SMEM);

    prep_M<<<(2 * (int)AS + 255) / 256, 256>>>(support, eps);
    prep_W<<<(ZC * BD + 255) / 256, 256>>>(weight);
    split_X<<<(int)(ROWS * (size_t)BD / 4 + 255) / 256, 256>>>(x);

    stage1_mma<<<dim3(ZC / 128, ROWS / 128), 256, S1_SMEM>>>();

    stage2a_mma<<<dim3(NN / 128, BB, 2), 256, S2_SMEM>>>();
    stage2b_mma<<<dim3(NN / 128, BB, 2), 256, S2_SMEM>>>();

    zero_stats<<<1, 64>>>();
    bn_stats<<<128, 256>>>();
    bn_relu_fc2<<<ROWS / 64, 256>>>(gamma, beta, w2, b2, out);
}

// round 13
// speedup vs baseline: 1.1290x; 1.0611x over previous
#include <cuda_runtime.h>
#include <cuda_bf16.h>
#include <math.h>
#include <stdint.h>

typedef __nv_bfloat16 bf16;

// ---------------- problem dims ----------------
#define BB    32
#define NN    512
#define BD    768            // L*H
#define ROWS  (BB*NN)        // 16384
#define OUTC  64
#define KSUP  4
#define ZC    256            // KSUP*OUTC
#define AS    ((size_t)NN*NN)

// ---------------- device scratch (no allocation) ----------------
__device__ __align__(256) bf16  g_Mh [2*AS], g_Ml [2*AS];    // M = A+(1+eps)I, split
__device__ __align__(256) bf16  g_Wth[ZC*BD], g_Wtl[ZC*BD];  // W^T repack [ko][d]
__device__ __align__(256) bf16  g_Zh[(size_t)ROWS*ZC], g_Zl[(size_t)ROWS*ZC];
__device__ __align__(256) bf16  g_Vh[(size_t)2*ROWS*OUTC], g_Vl[(size_t)2*ROWS*OUTC];
__device__ __align__(256) float g_mid[(size_t)ROWS*OUTC];
__device__ float g_sum[OUTC], g_sumsq[OUTC];

__device__ __forceinline__ uint32_t smem_u32(const void* p) {
    uint32_t a;
    asm("{ .reg .u64 t; cvta.to.shared.u64 t, %1; cvt.u32.u64 %0, t; }" : "=r"(a) : "l"(p));
    return a;
}
__device__ __forceinline__ void split_bf16(float v, bf16& h, bf16& l) {
    h = __float2bfloat16(v);
    l = __float2bfloat16(v - __bfloat162float(h));
}
__device__ __forceinline__ uint32_t pack2(bf16 lo, bf16 hi) {
    return ((uint32_t)__bfloat16_as_ushort(hi) << 16) | __bfloat16_as_ushort(lo);
}
__device__ __forceinline__ float bf_lo(uint32_t u) {
    return __bfloat162float(__ushort_as_bfloat16((unsigned short)(u & 0xFFFF)));
}
__device__ __forceinline__ float bf_hi(uint32_t u) {
    return __bfloat162float(__ushort_as_bfloat16((unsigned short)(u >> 16)));
}
__device__ __forceinline__ void cp16(uint32_t s, const void* g) {
    asm volatile("cp.async.cg.shared.global [%0], [%1], 16;"
                 :: "r"(s), "l"(__cvta_generic_to_global(g)) : "memory");
}
#define CP_COMMIT() asm volatile("cp.async.commit_group;" ::: "memory")
#define CP_WAIT1()  asm volatile("cp.async.wait_group 1;"  ::: "memory")

#define LDSM_X4(r0,r1,r2,r3,addr) \
    asm volatile("ldmatrix.sync.aligned.m8n8.x4.shared.b16 {%0,%1,%2,%3}, [%4];" \
                 : "=r"(r0), "=r"(r1), "=r"(r2), "=r"(r3) : "r"(addr))
#define LDSM_X4T(r0,r1,r2,r3,addr) \
    asm volatile("ldmatrix.sync.aligned.m8n8.x4.trans.shared.b16 {%0,%1,%2,%3}, [%4];" \
                 : "=r"(r0), "=r"(r1), "=r"(r2), "=r"(r3) : "r"(addr))
#define MMA_BF16(c0,c1,c2,c3,a0,a1,a2,a3,b0,b1) \
    asm volatile("mma.sync.aligned.m16n8k16.row.col.f32.bf16.bf16.f32 " \
                 "{%0,%1,%2,%3}, {%4,%5,%6,%7}, {%8,%9}, {%0,%1,%2,%3};" \
                 : "+f"(c0), "+f"(c1), "+f"(c2), "+f"(c3) \
                 : "r"(a0), "r"(a1), "r"(a2), "r"(a3), "r"(b0), "r"(b1))

// ---------------- prep kernels ----------------
__global__ void prep_M(const float* __restrict__ sup, const float* __restrict__ eps) {
    int idx = blockIdx.x * blockDim.x + threadIdx.x;
    if (idx >= 2 * (int)AS) return;
    int rest = idx & (int)(AS - 1);
    int n = rest >> 9, m = rest & 511;
    float v = sup[idx] + ((n == m) ? (1.0f + eps[0]) : 0.0f);
    bf16 h, l; split_bf16(v, h, l);
    g_Mh[idx] = h; g_Ml[idx] = l;
}

__global__ void prep_W(const float* __restrict__ w) {
    int idx = blockIdx.x * blockDim.x + threadIdx.x;   // ko*768 + d
    if (idx >= ZC * BD) return;
    int d  = idx % BD;
    int ko = idx / BD;
    int k = ko >> 6, o = ko & 63;
    int l = d >> 6, h = d & 63;
    float v = w[((size_t)l * 256 + h * 4 + k) * OUTC + o];
    bf16 hh, ll; split_bf16(v, hh, ll);
    g_Wth[idx] = hh; g_Wtl[idx] = ll;
}

// ---------------- stage1 (fused X-split; BK=64; 12 chunks x 3 parts) -------------
// smem: Ah[2], Al[2], Wh[3], Wl[3] tiles of 128x72 bf16 (18.4 KB each) = 184 KB.
#define S1_PAD 72
#define S1_NCH 12
#define S1_TILE (128 * S1_PAD)
#define S1_SMEM (10 * S1_TILE * 2)

__global__ __launch_bounds__(256, 1) void stage1_mma(const float* __restrict__ X) {
    extern __shared__ __align__(16) bf16 sm1[];
    // layout: Ah0 Ah1 Al0 Al1 Wh0 Wh1 Wh2 Wl0 Wl1 Wl2
    const int tid = threadIdx.x;
    const int warp = tid >> 5, lane = tid & 31;
    const int wm = warp >> 1, wn = warp & 1;
    const int g = lane >> 2, q = lane & 3;
    const int r0 = blockIdx.y * 128;
    const int c0 = blockIdx.x * 128;

    // validated lane-invariant ldmatrix offsets
    const int aRowOff = ((lane >> 3) & 1) * 8 + (lane & 7);
    const int aKOff   = (lane >> 4) * 8;
    const int bRowOff = (lane >> 4) * 8 + (lane & 7);
    const int bKOff   = ((lane >> 3) & 1) * 8;

    uint32_t AhB[2], AlB[2], WhB[3], WlB[3];
#pragma unroll
    for (int i = 0; i < 2; ++i) {
        AhB[i] = smem_u32(sm1 + (0 + i) * S1_TILE);
        AlB[i] = smem_u32(sm1 + (2 + i) * S1_TILE);
    }
#pragma unroll
    for (int i = 0; i < 3; ++i) {
        WhB[i] = smem_u32(sm1 + (4 + i) * S1_TILE);
        WlB[i] = smem_u32(sm1 + (7 + i) * S1_TILE);
    }

    float c[2][8][4];
#pragma unroll
    for (int i = 0; i < 2; ++i)
#pragma unroll
        for (int j = 0; j < 8; ++j)
#pragma unroll
            for (int t = 0; t < 4; ++t) c[i][j][t] = 0.f;

    // X staging registers: 8 float4 per thread (rows tid>>4 .. step, 16 f4/row)
    const int xRow = tid >> 4;          // base row, +16 per t... see indexing below
    const int xSeg = tid & 15;
    float4 xv[8];

    auto ldgX = [&](int ch) {
        int kpos = ch * 64;
#pragma unroll
        for (int t = 0; t < 8; ++t) {
            int row = xRow + t * 16;
            xv[t] = *(const float4*)(X + (size_t)(r0 + row) * BD + kpos + xSeg * 4);
        }
    };
    auto cvtSts = [&](int abuf) {
#pragma unroll
        for (int t = 0; t < 8; ++t) {
            int row = xRow + t * 16;
            bf16 h0,l0,h1,l1,h2,l2,h3,l3;
            split_bf16(xv[t].x, h0, l0); split_bf16(xv[t].y, h1, l1);
            split_bf16(xv[t].z, h2, l2); split_bf16(xv[t].w, h3, l3);
            uint2 ph = { pack2(h0, h1), pack2(h2, h3) };
            uint2 pl = { pack2(l0, l1), pack2(l2, l3) };
            uint32_t so = (uint32_t)(row * S1_PAD + xSeg * 4) * 2;
            *(uint2*)((char*)sm1 + (AhB[abuf] - smem_u32(sm1)) + so) = ph;   // via generic
            *(uint2*)((char*)sm1 + (AlB[abuf] - smem_u32(sm1)) + so) = pl;
        }
    };
    auto loadW = [&](int ch) {
        int wb = ch % 3;
        int kpos = ch * 64;
#pragma unroll
        for (int t = 0; t < 4; ++t) {
            int u = tid + t * 256;
            int row = u >> 3, seg = u & 7;
            uint32_t so = (uint32_t)(row * S1_PAD + seg * 8) * 2;
            cp16(WhB[wb] + so, g_Wth + (size_t)(c0 + row) * BD + kpos + seg * 8);
            cp16(WlB[wb] + so, g_Wtl + (size_t)(c0 + row) * BD + kpos + seg * 8);
        }
        CP_COMMIT();
    };

    // prologue
    ldgX(0); cvtSts(0);
    loadW(0); loadW(1);
    ldgX(1);
    CP_WAIT1();
    __syncthreads();

    for (int ch = 0; ch < S1_NCH; ++ch) {
        int abuf = ch & 1, wbuf = ch % 3;
#pragma unroll
        for (int ks = 0; ks < 64; ks += 16) {
            uint32_t ah[2][4], al[2][4];
#pragma unroll
            for (int i = 0; i < 2; ++i) {
                uint32_t ro = (uint32_t)(wm * 32 + i * 16 + aRowOff) * (S1_PAD * 2)
                            + (uint32_t)(ks + aKOff) * 2;
                LDSM_X4(ah[i][0], ah[i][1], ah[i][2], ah[i][3], AhB[abuf] + ro);
                LDSM_X4(al[i][0], al[i][1], al[i][2], al[i][3], AlB[abuf] + ro);
            }
            uint32_t bh[8][2], bl[8][2];
#pragma unroll
            for (int j2 = 0; j2 < 4; ++j2) {
                uint32_t ro = (uint32_t)(wn * 64 + j2 * 16 + bRowOff) * (S1_PAD * 2)
                            + (uint32_t)(ks + bKOff) * 2;
                uint32_t r0_, r1_, r2_, r3_;
                LDSM_X4(r0_, r1_, r2_, r3_, WhB[wbuf] + ro);
                bh[2*j2][0] = r0_;   bh[2*j2][1] = r1_;
                bh[2*j2+1][0] = r2_; bh[2*j2+1][1] = r3_;
                LDSM_X4(r0_, r1_, r2_, r3_, WlB[wbuf] + ro);
                bl[2*j2][0] = r0_;   bl[2*j2][1] = r1_;
                bl[2*j2+1][0] = r2_; bl[2*j2+1][1] = r3_;
            }
#pragma unroll
            for (int i = 0; i < 2; ++i)
#pragma unroll
                for (int j = 0; j < 8; ++j) {
                    MMA_BF16(c[i][j][0], c[i][j][1], c[i][j][2], c[i][j][3],
                             ah[i][0], ah[i][1], ah[i][2], ah[i][3], bh[j][0], bh[j][1]);
                    MMA_BF16(c[i][j][0], c[i][j][1], c[i][j][2], c[i][j][3],
                             al[i][0], al[i][1], al[i][2], al[i][3], bh[j][0], bh[j][1]);
                    MMA_BF16(c[i][j][0], c[i][j][1], c[i][j][2], c[i][j][3],
                             ah[i][0], ah[i][1], ah[i][2], ah[i][3], bl[j][0], bl[j][1]);
                }
        }
        if (ch + 1 < S1_NCH) cvtSts(abuf ^ 1);       // X(ch+1) from xv
        if (ch + 2 < S1_NCH) { ldgX(ch + 2); loadW(ch + 2); }
        else CP_COMMIT();
        CP_WAIT1();
        __syncthreads();
    }

    // epilogue: split fp32 -> Zh/Zl bf16
#pragma unroll
    for (int i = 0; i < 2; ++i) {
        int row = r0 + wm * 32 + i * 16 + g;
#pragma unroll
        for (int j = 0; j < 8; ++j) {
            int col = c0 + wn * 64 + j * 8 + 2 * q;
#pragma unroll
            for (int hrow = 0; hrow < 2; ++hrow) {
                float v0 = c[i][j][hrow * 2], v1 = c[i][j][hrow * 2 + 1];
                bf16 h0, l0, h1, l1;
                split_bf16(v0, h0, l0); split_bf16(v1, h1, l1);
                size_t off = (size_t)(row + hrow * 8) * ZC + col;
                *(uint32_t*)&g_Zh[off] = pack2(h0, h1);
                *(uint32_t*)&g_Zl[off] = pack2(l0, l1);
            }
        }
    }
}

// ---------------- stage2 common: BK=64, 3-stage, CTA 128n x 64 cols --------------
#define S2_APAD 72
#define S2_BPAD 72
#define S2_ATILE (128 * S2_APAD)
#define S2_BTILE (64 * S2_BPAD)
#define S2_SMEM ((3 * S2_ATILE + 3 * S2_BTILE) * 2)

// stage2a: V_s = Z_{2s} + M_s * Z_{2s+1}  (fused vadd epilogue)
#define S2A_NCH 24
__global__ __launch_bounds__(256, 2) void stage2a_mma() {
    extern __shared__ __align__(16) bf16 sm2[];
    bf16* Asm = sm2;
    bf16* Bsm = sm2 + 3 * S2_ATILE;

    const int tid = threadIdx.x;
    const int warp = tid >> 5, lane = tid & 31;
    const int wm = warp >> 1, wn = warp & 1;
    const int g = lane >> 2, q = lane & 3;
    const int n0 = blockIdx.x * 128;
    const int b  = blockIdx.y;
    const int s  = blockIdx.z;

    const int fragRow  = lane & 15;
    const int fragCol8 = (lane >> 4) * 8;

    uint32_t aB[3], bB[3];
#pragma unroll
    for (int st = 0; st < 3; ++st) {
        aB[st] = smem_u32(Asm + st * S2_ATILE);
        bB[st] = smem_u32(Bsm + st * S2_BTILE);
    }

    float c[2][4][4];
#pragma unroll
    for (int i = 0; i < 2; ++i)
#pragma unroll
        for (int j = 0; j < 4; ++j)
#pragma unroll
            for (int t = 0; t < 4; ++t) c[i][j][t] = 0.f;

    const int zcol = (2 * s + 1) * 64;

    auto load_stage = [&](int ch) {
        int st = ch % 3;
        int part = ch / 8;           // 0,1,2
        int mpos = (ch % 8) * 64;
        const bf16* Am = ((part == 1) ? g_Ml : g_Mh) + (size_t)s * AS;
#pragma unroll
        for (int t = 0; t < 4; ++t) {
            int u = tid + t * 256;
            int row = u >> 3, seg = u & 7;
            cp16(aB[st] + (uint32_t)(row * S2_APAD + seg * 8) * 2,
                 Am + (size_t)(n0 + row) * NN + mpos + seg * 8);
        }
        const bf16* Zp = (part == 2) ? g_Zl : g_Zh;
#pragma unroll
        for (int t = 0; t < 2; ++t) {
            int u = tid + t * 256;
            int row = u >> 3, seg = u & 7;
            cp16(bB[st] + (uint32_t)(row * S2_BPAD + seg * 8) * 2,
                 Zp + (size_t)(b * NN + mpos + row) * ZC + zcol + seg * 8);
        }
        CP_COMMIT();
    };

    load_stage(0); load_stage(1);

#pragma unroll 3
    for (int ch = 0; ch < S2A_NCH; ++ch) {
        CP_WAIT1();
        __syncthreads();
        int st = ch % 3;
#pragma unroll
        for (int ks = 0; ks < 64; ks += 16) {
            uint32_t a[2][4];
#pragma unroll
            for (int i = 0; i < 2; ++i) {
                uint32_t addr = aB[st]
                    + (uint32_t)(wm * 32 + i * 16 + fragRow) * (S2_APAD * 2)
                    + (uint32_t)(ks + fragCol8) * 2;
                LDSM_X4(a[i][0], a[i][1], a[i][2], a[i][3], addr);
            }
            uint32_t b_[4][2];
#pragma unroll
            for (int jj = 0; jj < 2; ++jj) {
                uint32_t addr = bB[st]
                    + (uint32_t)(ks + fragRow) * (S2_BPAD * 2)
                    + (uint32_t)(wn * 32 + jj * 16 + fragCol8) * 2;
                uint32_t r0_, r1_, r2_, r3_;
                LDSM_X4T(r0_, r1_, r2_, r3_, addr);
                b_[2*jj][0] = r0_;   b_[2*jj][1] = r1_;
                b_[2*jj+1][0] = r2_; b_[2*jj+1][1] = r3_;
            }
#pragma unroll
            for (int i = 0; i < 2; ++i)
#pragma unroll
                for (int j = 0; j < 4; ++j)
                    MMA_BF16(c[i][j][0], c[i][j][1], c[i][j][2], c[i][j][3],
                             a[i][0], a[i][1], a[i][2], a[i][3], b_[j][0], b_[j][1]);
        }
        if (ch + 2 < S2A_NCH) load_stage(ch + 2);
        else CP_COMMIT();
    }

    // fused epilogue: V = Z_even + M*Z_odd, split to bf16 -> Vh/Vl
    const size_t vbase = ((size_t)(s * BB + b) * NN) * OUTC;
#pragma unroll
    for (int i = 0; i < 2; ++i) {
#pragma unroll
        for (int j = 0; j < 4; ++j) {
            int col = wn * 32 + j * 8 + 2 * q;
#pragma unroll
            for (int hrow = 0; hrow < 2; ++hrow) {
                int row = n0 + wm * 32 + i * 16 + g + hrow * 8;
                size_t zo = (size_t)(b * NN + row) * ZC + s * 128 + col;
                uint32_t zh = *(const uint32_t*)&g_Zh[zo];
                uint32_t zl = *(const uint32_t*)&g_Zl[zo];
                float v0 = c[i][j][hrow * 2]     + bf_lo(zh) + bf_lo(zl);
                float v1 = c[i][j][hrow * 2 + 1] + bf_hi(zh) + bf_hi(zl);
                bf16 h0, l0, h1, l1;
                split_bf16(v0, h0, l0); split_bf16(v1, h1, l1);
                size_t vo = vbase + (size_t)row * OUTC + col;
                *(uint32_t*)&g_Vh[vo] = pack2(h0, h1);
                *(uint32_t*)&g_Vl[vo] = pack2(l0, l1);
            }
        }
    }
}

// stage2b (merged s): mid = M_0*V_0 + M_1*V_1 ; grid (4, BB), 48 chunks
#define S2B_NCH 48
__global__ __launch_bounds__(256, 2) void stage2b_mma() {
    extern __shared__ __align__(16) bf16 sm3[];
    bf16* Asm = sm3;
    bf16* Bsm = sm3 + 3 * S2_ATILE;

    const int tid = threadIdx.x;
    const int warp = tid >> 5, lane = tid & 31;
    const int wm = warp >> 1, wn = warp & 1;
    const int g = lane >> 2, q = lane & 3;
    const int n0 = blockIdx.x * 128;
    const int b  = blockIdx.y;

    const int fragRow  = lane & 15;
    const int fragCol8 = (lane >> 4) * 8;

    uint32_t aB[3], bB[3];
#pragma unroll
    for (int st = 0; st < 3; ++st) {
        aB[st] = smem_u32(Asm + st * S2_ATILE);
        bB[st] = smem_u32(Bsm + st * S2_BTILE);
    }

    float c[2][4][4];
#pragma unroll
    for (int i = 0; i < 2; ++i)
#pragma unroll
        for (int j = 0; j < 4; ++j)
#pragma unroll
            for (int t = 0; t < 4; ++t) c[i][j][t] = 0.f;

    auto load_stage = [&](int ch) {
        int st = ch % 3;
        int s = ch / 24;
        int r = ch % 24;
        int part = r / 8;
        int mpos = (r % 8) * 64;
        const bf16* Am = ((part == 1) ? g_Ml : g_Mh) + (size_t)s * AS;
#pragma unroll
        for (int t = 0; t < 4; ++t) {
            int u = tid + t * 256;
            int row = u >> 3, seg = u & 7;
            cp16(aB[st] + (uint32_t)(row * S2_APAD + seg * 8) * 2,
                 Am + (size_t)(n0 + row) * NN + mpos + seg * 8);
        }
        const bf16* Vp = (part == 2) ? g_Vl : g_Vh;
        size_t vbase = ((size_t)(s * BB + b) * NN) * OUTC;
#pragma unroll
        for (int t = 0; t < 2; ++t) {
            int u = tid + t * 256;
            int row = u >> 3, seg = u & 7;
            cp16(bB[st] + (uint32_t)(row * S2_BPAD + seg * 8) * 2,
                 Vp + vbase + (size_t)(mpos + row) * OUTC + seg * 8);
        }
        CP_COMMIT();
    };

    load_stage(0); load_stage(1);

#pragma unroll 3
    for (int ch = 0; ch < S2B_NCH; ++ch) {
        CP_WAIT1();
        __syncthreads();
        int st = ch % 3;
#pragma unroll
        for (int ks = 0; ks < 64; ks += 16) {
            uint32_t a[2][4];
#pragma unroll
            for (int i = 0; i < 2; ++i) {
                uint32_t addr = aB[st]
                    + (uint32_t)(wm * 32 + i * 16 + fragRow) * (S2_APAD * 2)
                    + (uint32_t)(ks + fragCol8) * 2;
                LDSM_X4(a[i][0], a[i][1], a[i][2], a[i][3], addr);
            }
            uint32_t b_[4][2];
#pragma unroll
            for (int jj = 0; jj < 2; ++jj) {
                uint32_t addr = bB[st]
                    + (uint32_t)(ks + fragRow) * (S2_BPAD * 2)
                    + (uint32_t)(wn * 32 + jj * 16 + fragCol8) * 2;
                uint32_t r0_, r1_, r2_, r3_;
                LDSM_X4T(r0_, r1_, r2_, r3_, addr);
                b_[2*jj][0] = r0_;   b_[2*jj][1] = r1_;
                b_[2*jj+1][0] = r2_; b_[2*jj+1][1] = r3_;
            }
#pragma unroll
            for (int i = 0; i < 2; ++i)
#pragma unroll
                for (int j = 0; j < 4; ++j)
                    MMA_BF16(c[i][j][0], c[i][j][1], c[i][j][2], c[i][j][3],
                             a[i][0], a[i][1], a[i][2], a[i][3], b_[j][0], b_[j][1]);
        }
        if (ch + 2 < S2B_NCH) load_stage(ch + 2);
        else CP_COMMIT();
    }

    // epilogue: write mid directly
#pragma unroll
    for (int i = 0; i < 2; ++i) {
        int row = n0 + wm * 32 + i * 16 + g;
#pragma unroll
        for (int j = 0; j < 4; ++j) {
            int col = wn * 32 + j * 8 + 2 * q;
            float2 v0 = { c[i][j][0], c[i][j][1] };
            float2 v1 = { c[i][j][2], c[i][j][3] };
            *(float2*)&g_mid[(size_t)(b * NN + row) * OUTC + col] = v0;
            *(float2*)&g_mid[(size_t)(b * NN + row + 8) * OUTC + col] = v1;
        }
    }
}

// ---------------- BN tail ----------------
__global__ void zero_stats() {
    if (threadIdx.x < OUTC) { g_sum[threadIdx.x] = 0.f; g_sumsq[threadIdx.x] = 0.f; }
}
__global__ __launch_bounds__(256) void bn_stats() {
    const int c = threadIdx.x & 63;
    const int rl = threadIdx.x >> 6;
    float s = 0.f, s2 = 0.f;
    for (int r = blockIdx.x * 4 + rl; r < ROWS; r += gridDim.x * 4) {
        float v = g_mid[(size_t)r * OUTC + c];
        s += v; s2 += v * v;
    }
    __shared__ float sh[256], sh2[256];
    sh[threadIdx.x] = s; sh2[threadIdx.x] = s2;
    __syncthreads();
    if (rl == 0) {
        s  = sh[c] + sh[c + 64] + sh[c + 128] + sh[c + 192];
        s2 = sh2[c] + sh2[c + 64] + sh2[c + 128] + sh2[c + 192];
        atomicAdd(&g_sum[c], s); atomicAdd(&g_sumsq[c], s2);
    }
}
__global__ __launch_bounds__(256) void bn_relu_fc2(
    const float* __restrict__ gamma, const float* __restrict__ beta,
    const float* __restrict__ w2,    const float* __restrict__ b2,
    float* __restrict__ out)
{
    __shared__ float w2t[64][65];
    __shared__ float ysm[64][65];
    __shared__ float scale_s[64], shift_s[64];
    const int tid = threadIdx.x;
    const int r0 = blockIdx.x * 64;

#pragma unroll
    for (int t = 0; t < 16; ++t) {
        int idx = tid + t * 256;
        int o = idx >> 6, cc = idx & 63;
        w2t[cc][o] = w2[idx];
    }
    if (tid < OUTC) {
        const float invN = 1.0f / (float)ROWS;
        float mean = g_sum[tid] * invN;
        float var  = g_sumsq[tid] * invN - mean * mean;
        float sc   = gamma[tid] * rsqrtf(var + 1e-5f);
        scale_s[tid] = sc;
        shift_s[tid] = beta[tid] - mean * sc;
    }
    __syncthreads();

#pragma unroll
    for (int t = 0; t < 16; ++t) {
        int idx = tid + t * 256;
        int r = idx >> 6, cc = idx & 63;
        float v = g_mid[(size_t)(r0 + r) * OUTC + cc];
        ysm[r][cc] = fmaxf(fmaf(v, scale_s[cc], shift_s[cc]), 0.f);
    }
    __syncthreads();

    const int tr = tid >> 4, tc = tid & 15;
    float acc[4][4];
#pragma unroll
    for (int i = 0; i < 4; ++i)
#pragma unroll
        for (int j = 0; j < 4; ++j) acc[i][j] = b2[tc * 4 + j];
    for (int k = 0; k < 64; ++k) {
        float w0 = w2t[k][tc * 4 + 0], w1 = w2t[k][tc * 4 + 1];
        float w2v = w2t[k][tc * 4 + 2], w3 = w2t[k][tc * 4 + 3];
#pragma unroll
        for (int i = 0; i < 4; ++i) {
            float y = ysm[tr * 4 + i][k];
            acc[i][0] = fmaf(y, w0, acc[i][0]);
            acc[i][1] = fmaf(y, w1, acc[i][1]);
            acc[i][2] = fmaf(y, w2v, acc[i][2]);
            acc[i][3] = fmaf(y, w3, acc[i][3]);
        }
    }
#pragma unroll
    for (int i = 0; i < 4; ++i)
        *(float4*)&out[(size_t)(r0 + tr * 4 + i) * OUTC + tc * 4] = *(float4*)&acc[i][0];
}

// ---------------- launch ----------------
extern "C" void kernel_launch(void* const* d_in, const int* in_sizes, int n_in,
                              void* d_out, int out_size) {
    const float* x       = (const float*)d_in[0];
    const float* support = (const float*)d_in[1];
    const float* weight  = (const float*)d_in[2];
    const float* eps     = (const float*)d_in[3];
    const float* gamma   = (const float*)d_in[4];
    const float* beta    = (const float*)d_in[5];
    const float* w2      = (const float*)d_in[6];
    const float* b2      = (const float*)d_in[7];
    float* out           = (float*)d_out;

    cudaFuncSetAttribute(stage1_mma,  cudaFuncAttributeMaxDynamicSharedMemorySize, S1_SMEM);
    cudaFuncSetAttribute(stage2a_mma, cudaFuncAttributeMaxDynamicSharedMemorySize, S2_SMEM);
    cudaFuncSetAttribute(stage2b_mma, cudaFuncAttributeMaxDynamicSharedMemorySize, S2_SMEM);

    prep_M<<<(2 * (int)AS + 255) / 256, 256>>>(support, eps);
    prep_W<<<(ZC * BD + 255) / 256, 256>>>(weight);

    stage1_mma<<<dim3(ZC / 128, ROWS / 128), 256, S1_SMEM>>>(x);

    stage2a_mma<<<dim3(NN / 128, BB, 2), 256, S2_SMEM>>>();
    stage2b_mma<<<dim3(NN / 128, BB), 256, S2_SMEM>>>();

    zero_stats<<<1, 64>>>();
    bn_stats<<<128, 256>>>();
    bn_relu_fc2<<<ROWS / 64, 256>>>(gamma, beta, w2, b2, out);
}

// round 14
// speedup vs baseline: 1.1466x; 1.0156x over previous
#include <cuda_runtime.h>
#include <cuda_bf16.h>
#include <math.h>
#include <stdint.h>

typedef __nv_bfloat16 bf16;

// ---------------- problem dims ----------------
#define BB    32
#define NN    512
#define BD    768            // L*H
#define ROWS  (BB*NN)        // 16384
#define OUTC  64
#define KSUP  4
#define ZC    256            // KSUP*OUTC
#define AS    ((size_t)NN*NN)

// ---------------- device scratch (no allocation) ----------------
__device__ __align__(256) bf16  g_Mh [2*AS], g_Ml [2*AS];    // M = A+(1+eps)I, split
__device__ __align__(256) bf16  g_Wth[ZC*BD], g_Wtl[ZC*BD];  // W^T repack [ko][d]
__device__ __align__(256) bf16  g_Zh[(size_t)ROWS*ZC], g_Zl[(size_t)ROWS*ZC];
__device__ __align__(256) bf16  g_Vh[(size_t)2*ROWS*OUTC], g_Vl[(size_t)2*ROWS*OUTC];
__device__ __align__(256) float g_midp[2][(size_t)ROWS*OUTC]; // stage2b slabs (per s)
__device__ float g_sum[OUTC], g_sumsq[OUTC];

__device__ __forceinline__ uint32_t smem_u32(const void* p) {
    uint32_t a;
    asm("{ .reg .u64 t; cvta.to.shared.u64 t, %1; cvt.u32.u64 %0, t; }" : "=r"(a) : "l"(p));
    return a;
}
__device__ __forceinline__ void split_bf16(float v, bf16& h, bf16& l) {
    h = __float2bfloat16(v);
    l = __float2bfloat16(v - __bfloat162float(h));
}
__device__ __forceinline__ uint32_t pack2(bf16 lo, bf16 hi) {
    return ((uint32_t)__bfloat16_as_ushort(hi) << 16) | __bfloat16_as_ushort(lo);
}
__device__ __forceinline__ float bf_lo(uint32_t u) {
    return __bfloat162float(__ushort_as_bfloat16((unsigned short)(u & 0xFFFF)));
}
__device__ __forceinline__ float bf_hi(uint32_t u) {
    return __bfloat162float(__ushort_as_bfloat16((unsigned short)(u >> 16)));
}
__device__ __forceinline__ void cp16(uint32_t s, const void* g) {
    asm volatile("cp.async.cg.shared.global [%0], [%1], 16;"
                 :: "r"(s), "l"(__cvta_generic_to_global(g)) : "memory");
}
#define CP_COMMIT() asm volatile("cp.async.commit_group;" ::: "memory")
#define CP_WAIT1()  asm volatile("cp.async.wait_group 1;"  ::: "memory")

#define LDSM_X4(r0,r1,r2,r3,addr) \
    asm volatile("ldmatrix.sync.aligned.m8n8.x4.shared.b16 {%0,%1,%2,%3}, [%4];" \
                 : "=r"(r0), "=r"(r1), "=r"(r2), "=r"(r3) : "r"(addr))
#define LDSM_X4T(r0,r1,r2,r3,addr) \
    asm volatile("ldmatrix.sync.aligned.m8n8.x4.trans.shared.b16 {%0,%1,%2,%3}, [%4];" \
                 : "=r"(r0), "=r"(r1), "=r"(r2), "=r"(r3) : "r"(addr))
#define MMA_BF16(c0,c1,c2,c3,a0,a1,a2,a3,b0,b1) \
    asm volatile("mma.sync.aligned.m16n8k16.row.col.f32.bf16.bf16.f32 " \
                 "{%0,%1,%2,%3}, {%4,%5,%6,%7}, {%8,%9}, {%0,%1,%2,%3};" \
                 : "+f"(c0), "+f"(c1), "+f"(c2), "+f"(c3) \
                 : "r"(a0), "r"(a1), "r"(a2), "r"(a3), "r"(b0), "r"(b1))

// ---------------- fused prep: M split + W repack/split + zero stats --------------
__global__ void prep_all(const float* __restrict__ sup, const float* __restrict__ eps,
                         const float* __restrict__ w) {
    int idx = blockIdx.x * blockDim.x + threadIdx.x;
    if (idx < 64) { g_sum[idx] = 0.f; g_sumsq[idx] = 0.f; }
    if (idx < 2 * (int)AS) {
        int rest = idx & (int)(AS - 1);
        int n = rest >> 9, m = rest & 511;
        float v = sup[idx] + ((n == m) ? (1.0f + eps[0]) : 0.0f);
        bf16 h, l; split_bf16(v, h, l);
        g_Mh[idx] = h; g_Ml[idx] = l;
    } else {
        int widx = idx - 2 * (int)AS;          // ko*768 + d
        if (widx >= ZC * BD) return;
        int d  = widx % BD;
        int ko = widx / BD;
        int k = ko >> 6, o = ko & 63;
        int l = d >> 6, h = d & 63;
        float v = w[((size_t)l * 256 + h * 4 + k) * OUTC + o];
        bf16 hh, ll; split_bf16(v, hh, ll);
        g_Wth[widx] = hh; g_Wtl[widx] = ll;
    }
}

// ---------------- stage1 (fused X-split; BK=64; 12 chunks x 3 parts) -------------
#define S1_PAD 72
#define S1_NCH 12
#define S1_TILE (128 * S1_PAD)
#define S1_SMEM (10 * S1_TILE * 2)

__global__ __launch_bounds__(256, 1) void stage1_mma(const float* __restrict__ X) {
    extern __shared__ __align__(16) bf16 sm1[];
    const int tid = threadIdx.x;
    const int warp = tid >> 5, lane = tid & 31;
    const int wm = warp >> 1, wn = warp & 1;
    const int g = lane >> 2, q = lane & 3;
    const int r0 = blockIdx.y * 128;
    const int c0 = blockIdx.x * 128;

    const int aRowOff = ((lane >> 3) & 1) * 8 + (lane & 7);
    const int aKOff   = (lane >> 4) * 8;
    const int bRowOff = (lane >> 4) * 8 + (lane & 7);
    const int bKOff   = ((lane >> 3) & 1) * 8;

    uint32_t AhB[2], AlB[2], WhB[3], WlB[3];
#pragma unroll
    for (int i = 0; i < 2; ++i) {
        AhB[i] = smem_u32(sm1 + (0 + i) * S1_TILE);
        AlB[i] = smem_u32(sm1 + (2 + i) * S1_TILE);
    }
#pragma unroll
    for (int i = 0; i < 3; ++i) {
        WhB[i] = smem_u32(sm1 + (4 + i) * S1_TILE);
        WlB[i] = smem_u32(sm1 + (7 + i) * S1_TILE);
    }

    float c[2][8][4];
#pragma unroll
    for (int i = 0; i < 2; ++i)
#pragma unroll
        for (int j = 0; j < 8; ++j)
#pragma unroll
            for (int t = 0; t < 4; ++t) c[i][j][t] = 0.f;

    const int xRow = tid >> 4;
    const int xSeg = tid & 15;
    float4 xv[8];

    auto ldgX = [&](int ch) {
        int kpos = ch * 64;
#pragma unroll
        for (int t = 0; t < 8; ++t) {
            int row = xRow + t * 16;
            xv[t] = *(const float4*)(X + (size_t)(r0 + row) * BD + kpos + xSeg * 4);
        }
    };
    auto cvtSts = [&](int abuf) {
#pragma unroll
        for (int t = 0; t < 8; ++t) {
            int row = xRow + t * 16;
            bf16 h0,l0,h1,l1,h2,l2,h3,l3;
            split_bf16(xv[t].x, h0, l0); split_bf16(xv[t].y, h1, l1);
            split_bf16(xv[t].z, h2, l2); split_bf16(xv[t].w, h3, l3);
            uint2 ph = { pack2(h0, h1), pack2(h2, h3) };
            uint2 pl = { pack2(l0, l1), pack2(l2, l3) };
            uint32_t so = (uint32_t)(row * S1_PAD + xSeg * 4) * 2;
            *(uint2*)((char*)sm1 + (AhB[abuf] - smem_u32(sm1)) + so) = ph;
            *(uint2*)((char*)sm1 + (AlB[abuf] - smem_u32(sm1)) + so) = pl;
        }
    };
    auto loadW = [&](int ch) {
        int wb = ch % 3;
        int kpos = ch * 64;
#pragma unroll
        for (int t = 0; t < 4; ++t) {
            int u = tid + t * 256;
            int row = u >> 3, seg = u & 7;
            uint32_t so = (uint32_t)(row * S1_PAD + seg * 8) * 2;
            cp16(WhB[wb] + so, g_Wth + (size_t)(c0 + row) * BD + kpos + seg * 8);
            cp16(WlB[wb] + so, g_Wtl + (size_t)(c0 + row) * BD + kpos + seg * 8);
        }
        CP_COMMIT();
    };

    ldgX(0); cvtSts(0);
    loadW(0); loadW(1);
    ldgX(1);
    CP_WAIT1();
    __syncthreads();

    for (int ch = 0; ch < S1_NCH; ++ch) {
        int abuf = ch & 1, wbuf = ch % 3;
#pragma unroll
        for (int ks = 0; ks < 64; ks += 16) {
            uint32_t ah[2][4], al[2][4];
#pragma unroll
            for (int i = 0; i < 2; ++i) {
                uint32_t ro = (uint32_t)(wm * 32 + i * 16 + aRowOff) * (S1_PAD * 2)
                            + (uint32_t)(ks + aKOff) * 2;
                LDSM_X4(ah[i][0], ah[i][1], ah[i][2], ah[i][3], AhB[abuf] + ro);
                LDSM_X4(al[i][0], al[i][1], al[i][2], al[i][3], AlB[abuf] + ro);
            }
            uint32_t bh[8][2], bl[8][2];
#pragma unroll
            for (int j2 = 0; j2 < 4; ++j2) {
                uint32_t ro = (uint32_t)(wn * 64 + j2 * 16 + bRowOff) * (S1_PAD * 2)
                            + (uint32_t)(ks + bKOff) * 2;
                uint32_t r0_, r1_, r2_, r3_;
                LDSM_X4(r0_, r1_, r2_, r3_, WhB[wbuf] + ro);
                bh[2*j2][0] = r0_;   bh[2*j2][1] = r1_;
                bh[2*j2+1][0] = r2_; bh[2*j2+1][1] = r3_;
                LDSM_X4(r0_, r1_, r2_, r3_, WlB[wbuf] + ro);
                bl[2*j2][0] = r0_;   bl[2*j2][1] = r1_;
                bl[2*j2+1][0] = r2_; bl[2*j2+1][1] = r3_;
            }
#pragma unroll
            for (int i = 0; i < 2; ++i)
#pragma unroll
                for (int j = 0; j < 8; ++j) {
                    MMA_BF16(c[i][j][0], c[i][j][1], c[i][j][2], c[i][j][3],
                             ah[i][0], ah[i][1], ah[i][2], ah[i][3], bh[j][0], bh[j][1]);
                    MMA_BF16(c[i][j][0], c[i][j][1], c[i][j][2], c[i][j][3],
                             al[i][0], al[i][1], al[i][2], al[i][3], bh[j][0], bh[j][1]);
                    MMA_BF16(c[i][j][0], c[i][j][1], c[i][j][2], c[i][j][3],
                             ah[i][0], ah[i][1], ah[i][2], ah[i][3], bl[j][0], bl[j][1]);
                }
        }
        if (ch + 1 < S1_NCH) cvtSts(abuf ^ 1);
        if (ch + 2 < S1_NCH) { ldgX(ch + 2); loadW(ch + 2); }
        else CP_COMMIT();
        CP_WAIT1();
        __syncthreads();
    }

#pragma unroll
    for (int i = 0; i < 2; ++i) {
        int row = r0 + wm * 32 + i * 16 + g;
#pragma unroll
        for (int j = 0; j < 8; ++j) {
            int col = c0 + wn * 64 + j * 8 + 2 * q;
#pragma unroll
            for (int hrow = 0; hrow < 2; ++hrow) {
                float v0 = c[i][j][hrow * 2], v1 = c[i][j][hrow * 2 + 1];
                bf16 h0, l0, h1, l1;
                split_bf16(v0, h0, l0); split_bf16(v1, h1, l1);
                size_t off = (size_t)(row + hrow * 8) * ZC + col;
                *(uint32_t*)&g_Zh[off] = pack2(h0, h1);
                *(uint32_t*)&g_Zl[off] = pack2(l0, l1);
            }
        }
    }
}

// ---------------- stage2 common: BK=64, 3-stage, CTA 128n x 64 cols --------------
#define S2_APAD 72
#define S2_BPAD 72
#define S2_NCH 24
#define S2_ATILE (128 * S2_APAD)
#define S2_BTILE (64 * S2_BPAD)
#define S2_SMEM ((3 * S2_ATILE + 3 * S2_BTILE) * 2)

// stage2a: V_s = Z_{2s} + M_s * Z_{2s+1}  (fused vadd epilogue)
__global__ __launch_bounds__(256, 2) void stage2a_mma() {
    extern __shared__ __align__(16) bf16 sm2[];
    bf16* Asm = sm2;
    bf16* Bsm = sm2 + 3 * S2_ATILE;

    const int tid = threadIdx.x;
    const int warp = tid >> 5, lane = tid & 31;
    const int wm = warp >> 1, wn = warp & 1;
    const int g = lane >> 2, q = lane & 3;
    const int n0 = blockIdx.x * 128;
    const int b  = blockIdx.y;
    const int s  = blockIdx.z;

    const int fragRow  = lane & 15;
    const int fragCol8 = (lane >> 4) * 8;

    uint32_t aB[3], bB[3];
#pragma unroll
    for (int st = 0; st < 3; ++st) {
        aB[st] = smem_u32(Asm + st * S2_ATILE);
        bB[st] = smem_u32(Bsm + st * S2_BTILE);
    }

    float c[2][4][4];
#pragma unroll
    for (int i = 0; i < 2; ++i)
#pragma unroll
        for (int j = 0; j < 4; ++j)
#pragma unroll
            for (int t = 0; t < 4; ++t) c[i][j][t] = 0.f;

    const int zcol = (2 * s + 1) * 64;

    auto load_stage = [&](int ch) {
        int st = ch % 3;
        int part = ch / 8;
        int mpos = (ch % 8) * 64;
        const bf16* Am = ((part == 1) ? g_Ml : g_Mh) + (size_t)s * AS;
#pragma unroll
        for (int t = 0; t < 4; ++t) {
            int u = tid + t * 256;
            int row = u >> 3, seg = u & 7;
            cp16(aB[st] + (uint32_t)(row * S2_APAD + seg * 8) * 2,
                 Am + (size_t)(n0 + row) * NN + mpos + seg * 8);
        }
        const bf16* Zp = (part == 2) ? g_Zl : g_Zh;
#pragma unroll
        for (int t = 0; t < 2; ++t) {
            int u = tid + t * 256;
            int row = u >> 3, seg = u & 7;
            cp16(bB[st] + (uint32_t)(row * S2_BPAD + seg * 8) * 2,
                 Zp + (size_t)(b * NN + mpos + row) * ZC + zcol + seg * 8);
        }
        CP_COMMIT();
    };

    load_stage(0); load_stage(1);

#pragma unroll 3
    for (int ch = 0; ch < S2_NCH; ++ch) {
        CP_WAIT1();
        __syncthreads();
        int st = ch % 3;
#pragma unroll
        for (int ks = 0; ks < 64; ks += 16) {
            uint32_t a[2][4];
#pragma unroll
            for (int i = 0; i < 2; ++i) {
                uint32_t addr = aB[st]
                    + (uint32_t)(wm * 32 + i * 16 + fragRow) * (S2_APAD * 2)
                    + (uint32_t)(ks + fragCol8) * 2;
                LDSM_X4(a[i][0], a[i][1], a[i][2], a[i][3], addr);
            }
            uint32_t b_[4][2];
#pragma unroll
            for (int jj = 0; jj < 2; ++jj) {
                uint32_t addr = bB[st]
                    + (uint32_t)(ks + fragRow) * (S2_BPAD * 2)
                    + (uint32_t)(wn * 32 + jj * 16 + fragCol8) * 2;
                uint32_t r0_, r1_, r2_, r3_;
                LDSM_X4T(r0_, r1_, r2_, r3_, addr);
                b_[2*jj][0] = r0_;   b_[2*jj][1] = r1_;
                b_[2*jj+1][0] = r2_; b_[2*jj+1][1] = r3_;
            }
#pragma unroll
            for (int i = 0; i < 2; ++i)
#pragma unroll
                for (int j = 0; j < 4; ++j)
                    MMA_BF16(c[i][j][0], c[i][j][1], c[i][j][2], c[i][j][3],
                             a[i][0], a[i][1], a[i][2], a[i][3], b_[j][0], b_[j][1]);
        }
        if (ch + 2 < S2_NCH) load_stage(ch + 2);
        else CP_COMMIT();
    }

    const size_t vbase = ((size_t)(s * BB + b) * NN) * OUTC;
#pragma unroll
    for (int i = 0; i < 2; ++i) {
#pragma unroll
        for (int j = 0; j < 4; ++j) {
            int col = wn * 32 + j * 8 + 2 * q;
#pragma unroll
            for (int hrow = 0; hrow < 2; ++hrow) {
                int row = n0 + wm * 32 + i * 16 + g + hrow * 8;
                size_t zo = (size_t)(b * NN + row) * ZC + s * 128 + col;
                uint32_t zh = *(const uint32_t*)&g_Zh[zo];
                uint32_t zl = *(const uint32_t*)&g_Zl[zo];
                float v0 = c[i][j][hrow * 2]     + bf_lo(zh) + bf_lo(zl);
                float v1 = c[i][j][hrow * 2 + 1] + bf_hi(zh) + bf_hi(zl);
                bf16 h0, l0, h1, l1;
                split_bf16(v0, h0, l0); split_bf16(v1, h1, l1);
                size_t vo = vbase + (size_t)row * OUTC + col;
                *(uint32_t*)&g_Vh[vo] = pack2(h0, h1);
                *(uint32_t*)&g_Vl[vo] = pack2(l0, l1);
            }
        }
    }
}

// stage2b: midp[s] = M_s * V_s ; grid (4, BB, 2), 24 chunks, full chip
__global__ __launch_bounds__(256, 2) void stage2b_mma() {
    extern __shared__ __align__(16) bf16 sm3[];
    bf16* Asm = sm3;
    bf16* Bsm = sm3 + 3 * S2_ATILE;

    const int tid = threadIdx.x;
    const int warp = tid >> 5, lane = tid & 31;
    const int wm = warp >> 1, wn = warp & 1;
    const int g = lane >> 2, q = lane & 3;
    const int n0 = blockIdx.x * 128;
    const int b  = blockIdx.y;
    const int s  = blockIdx.z;

    const int fragRow  = lane & 15;
    const int fragCol8 = (lane >> 4) * 8;

    uint32_t aB[3], bB[3];
#pragma unroll
    for (int st = 0; st < 3; ++st) {
        aB[st] = smem_u32(Asm + st * S2_ATILE);
        bB[st] = smem_u32(Bsm + st * S2_BTILE);
    }

    float c[2][4][4];
#pragma unroll
    for (int i = 0; i < 2; ++i)
#pragma unroll
        for (int j = 0; j < 4; ++j)
#pragma unroll
            for (int t = 0; t < 4; ++t) c[i][j][t] = 0.f;

    const size_t vbase = ((size_t)(s * BB + b) * NN) * OUTC;

    auto load_stage = [&](int ch) {
        int st = ch % 3;
        int part = ch / 8;
        int mpos = (ch % 8) * 64;
        const bf16* Am = ((part == 1) ? g_Ml : g_Mh) + (size_t)s * AS;
#pragma unroll
        for (int t = 0; t < 4; ++t) {
            int u = tid + t * 256;
            int row = u >> 3, seg = u & 7;
            cp16(aB[st] + (uint32_t)(row * S2_APAD + seg * 8) * 2,
                 Am + (size_t)(n0 + row) * NN + mpos + seg * 8);
        }
        const bf16* Vp = (part == 2) ? g_Vl : g_Vh;
#pragma unroll
        for (int t = 0; t < 2; ++t) {
            int u = tid + t * 256;
            int row = u >> 3, seg = u & 7;
            cp16(bB[st] + (uint32_t)(row * S2_BPAD + seg * 8) * 2,
                 Vp + vbase + (size_t)(mpos + row) * OUTC + seg * 8);
        }
        CP_COMMIT();
    };

    load_stage(0); load_stage(1);

#pragma unroll 3
    for (int ch = 0; ch < S2_NCH; ++ch) {
        CP_WAIT1();
        __syncthreads();
        int st = ch % 3;
#pragma unroll
        for (int ks = 0; ks < 64; ks += 16) {
            uint32_t a[2][4];
#pragma unroll
            for (int i = 0; i < 2; ++i) {
                uint32_t addr = aB[st]
                    + (uint32_t)(wm * 32 + i * 16 + fragRow) * (S2_APAD * 2)
                    + (uint32_t)(ks + fragCol8) * 2;
                LDSM_X4(a[i][0], a[i][1], a[i][2], a[i][3], addr);
            }
            uint32_t b_[4][2];
#pragma unroll
            for (int jj = 0; jj < 2; ++jj) {
                uint32_t addr = bB[st]
                    + (uint32_t)(ks + fragRow) * (S2_BPAD * 2)
                    + (uint32_t)(wn * 32 + jj * 16 + fragCol8) * 2;
                uint32_t r0_, r1_, r2_, r3_;
                LDSM_X4T(r0_, r1_, r2_, r3_, addr);
                b_[2*jj][0] = r0_;   b_[2*jj][1] = r1_;
                b_[2*jj+1][0] = r2_; b_[2*jj+1][1] = r3_;
            }
#pragma unroll
            for (int i = 0; i < 2; ++i)
#pragma unroll
                for (int j = 0; j < 4; ++j)
                    MMA_BF16(c[i][j][0], c[i][j][1], c[i][j][2], c[i][j][3],
                             a[i][0], a[i][1], a[i][2], a[i][3], b_[j][0], b_[j][1]);
        }
        if (ch + 2 < S2_NCH) load_stage(ch + 2);
        else CP_COMMIT();
    }

    float* O = g_midp[s];
#pragma unroll
    for (int i = 0; i < 2; ++i) {
        int row = n0 + wm * 32 + i * 16 + g;
#pragma unroll
        for (int j = 0; j < 4; ++j) {
            int col = wn * 32 + j * 8 + 2 * q;
            float2 v0 = { c[i][j][0], c[i][j][1] };
            float2 v1 = { c[i][j][2], c[i][j][3] };
            *(float2*)&O[(size_t)(b * NN + row) * OUTC + col] = v0;
            *(float2*)&O[(size_t)(b * NN + row + 8) * OUTC + col] = v1;
        }
    }
}

// ---------------- BN tail (reads both slabs) ----------------
__global__ __launch_bounds__(256) void bn_stats() {
    const int c = threadIdx.x & 63;
    const int rl = threadIdx.x >> 6;
    float s = 0.f, s2 = 0.f;
    for (int r = blockIdx.x * 4 + rl; r < ROWS; r += gridDim.x * 4) {
        size_t off = (size_t)r * OUTC + c;
        float v = g_midp[0][off] + g_midp[1][off];
        s += v; s2 += v * v;
    }
    __shared__ float sh[256], sh2[256];
    sh[threadIdx.x] = s; sh2[threadIdx.x] = s2;
    __syncthreads();
    if (rl == 0) {
        s  = sh[c] + sh[c + 64] + sh[c + 128] + sh[c + 192];
        s2 = sh2[c] + sh2[c + 64] + sh2[c + 128] + sh2[c + 192];
        atomicAdd(&g_sum[c], s); atomicAdd(&g_sumsq[c], s2);
    }
}
__global__ __launch_bounds__(256) void bn_relu_fc2(
    const float* __restrict__ gamma, const float* __restrict__ beta,
    const float* __restrict__ w2,    const float* __restrict__ b2,
    float* __restrict__ out)
{
    __shared__ float w2t[64][65];
    __shared__ float ysm[64][65];
    __shared__ float scale_s[64], shift_s[64];
    const int tid = threadIdx.x;
    const int r0 = blockIdx.x * 64;

#pragma unroll
    for (int t = 0; t < 16; ++t) {
        int idx = tid + t * 256;
        int o = idx >> 6, cc = idx & 63;
        w2t[cc][o] = w2[idx];
    }
    if (tid < OUTC) {
        const float invN = 1.0f / (float)ROWS;
        float mean = g_sum[tid] * invN;
        float var  = g_sumsq[tid] * invN - mean * mean;
        float sc   = gamma[tid] * rsqrtf(var + 1e-5f);
        scale_s[tid] = sc;
        shift_s[tid] = beta[tid] - mean * sc;
    }
    __syncthreads();

#pragma unroll
    for (int t = 0; t < 16; ++t) {
        int idx = tid + t * 256;
        int r = idx >> 6, cc = idx & 63;
        size_t off = (size_t)(r0 + r) * OUTC + cc;
        float v = g_midp[0][off] + g_midp[1][off];
        ysm[r][cc] = fmaxf(fmaf(v, scale_s[cc], shift_s[cc]), 0.f);
    }
    __syncthreads();

    const int tr = tid >> 4, tc = tid & 15;
    float acc[4][4];
#pragma unroll
    for (int i = 0; i < 4; ++i)
#pragma unroll
        for (int j = 0; j < 4; ++j) acc[i][j] = b2[tc * 4 + j];
    for (int k = 0; k < 64; ++k) {
        float w0 = w2t[k][tc * 4 + 0], w1 = w2t[k][tc * 4 + 1];
        float w2v = w2t[k][tc * 4 + 2], w3 = w2t[k][tc * 4 + 3];
#pragma unroll
        for (int i = 0; i < 4; ++i) {
            float y = ysm[tr * 4 + i][k];
            acc[i][0] = fmaf(y, w0, acc[i][0]);
            acc[i][1] = fmaf(y, w1, acc[i][1]);
            acc[i][2] = fmaf(y, w2v, acc[i][2]);
            acc[i][3] = fmaf(y, w3, acc[i][3]);
        }
    }
#pragma unroll
    for (int i = 0; i < 4; ++i)
        *(float4*)&out[(size_t)(r0 + tr * 4 + i) * OUTC + tc * 4] = *(float4*)&acc[i][0];
}

// ---------------- launch ----------------
extern "C" void kernel_launch(void* const* d_in, const int* in_sizes, int n_in,
                              void* d_out, int out_size) {
    const float* x       = (const float*)d_in[0];
    const float* support = (const float*)d_in[1];
    const float* weight  = (const float*)d_in[2];
    const float* eps     = (const float*)d_in[3];
    const float* gamma   = (const float*)d_in[4];
    const float* beta    = (const float*)d_in[5];
    const float* w2      = (const float*)d_in[6];
    const float* b2      = (const float*)d_in[7];
    float* out           = (float*)d_out;

    cudaFuncSetAttribute(stage1_mma,  cudaFuncAttributeMaxDynamicSharedMemorySize, S1_SMEM);
    cudaFuncSetAttribute(stage2a_mma, cudaFuncAttributeMaxDynamicSharedMemorySize, S2_SMEM);
    cudaFuncSetAttribute(stage2b_mma, cudaFuncAttributeMaxDynamicSharedMemorySize, S2_SMEM);

    {
        int total = 2 * (int)AS + ZC * BD;
        prep_all<<<(total + 255) / 256, 256>>>(support, eps, weight);
    }

    stage1_mma<<<dim3(ZC / 128, ROWS / 128), 256, S1_SMEM>>>(x);

    stage2a_mma<<<dim3(NN / 128, BB, 2), 256, S2_SMEM>>>();
    stage2b_mma<<<dim3(NN / 128, BB, 2), 256, S2_SMEM>>>();

    bn_stats<<<128, 256>>>();
    bn_relu_fc2<<<ROWS / 64, 256>>>(gamma, beta, w2, b2, out);
}

// round 15
// speedup vs baseline: 1.1742x; 1.0241x over previous
#include <cuda_runtime.h>
#include <cuda_bf16.h>
#include <math.h>
#include <stdint.h>

typedef __nv_bfloat16 bf16;

// ---------------- problem dims ----------------
#define BB    32
#define NN    512
#define BD    768            // L*H
#define ROWS  (BB*NN)        // 16384
#define OUTC  64
#define KSUP  4
#define ZC    256            // KSUP*OUTC
#define AS    ((size_t)NN*NN)

// ---------------- device scratch (no allocation) ----------------
__device__ __align__(256) bf16  g_Mh [2*AS], g_Ml [2*AS];    // M = A+(1+eps)I, split
__device__ __align__(256) bf16  g_Wth[ZC*BD], g_Wtl[ZC*BD];  // W^T repack [ko][d]
__device__ __align__(256) bf16  g_Zh[(size_t)ROWS*ZC], g_Zl[(size_t)ROWS*ZC];
__device__ __align__(256) bf16  g_Vh[(size_t)2*ROWS*OUTC], g_Vl[(size_t)2*ROWS*OUTC];
__device__ __align__(256) float g_mid[(size_t)ROWS*OUTC];
__device__ float g_sum[OUTC], g_sumsq[OUTC];

__device__ __forceinline__ uint32_t smem_u32(const void* p) {
    uint32_t a;
    asm("{ .reg .u64 t; cvta.to.shared.u64 t, %1; cvt.u32.u64 %0, t; }" : "=r"(a) : "l"(p));
    return a;
}
__device__ __forceinline__ void split_bf16(float v, bf16& h, bf16& l) {
    h = __float2bfloat16(v);
    l = __float2bfloat16(v - __bfloat162float(h));
}
__device__ __forceinline__ uint32_t pack2(bf16 lo, bf16 hi) {
    return ((uint32_t)__bfloat16_as_ushort(hi) << 16) | __bfloat16_as_ushort(lo);
}
__device__ __forceinline__ float bf_lo(uint32_t u) {
    return __bfloat162float(__ushort_as_bfloat16((unsigned short)(u & 0xFFFF)));
}
__device__ __forceinline__ float bf_hi(uint32_t u) {
    return __bfloat162float(__ushort_as_bfloat16((unsigned short)(u >> 16)));
}
__device__ __forceinline__ void cp16(uint32_t s, const void* g) {
    asm volatile("cp.async.cg.shared.global [%0], [%1], 16;"
                 :: "r"(s), "l"(__cvta_generic_to_global(g)) : "memory");
}
#define CP_COMMIT() asm volatile("cp.async.commit_group;" ::: "memory")
#define CP_WAIT1()  asm volatile("cp.async.wait_group 1;"  ::: "memory")

#define LDSM_X4(r0,r1,r2,r3,addr) \
    asm volatile("ldmatrix.sync.aligned.m8n8.x4.shared.b16 {%0,%1,%2,%3}, [%4];" \
                 : "=r"(r0), "=r"(r1), "=r"(r2), "=r"(r3) : "r"(addr))
#define LDSM_X4T(r0,r1,r2,r3,addr) \
    asm volatile("ldmatrix.sync.aligned.m8n8.x4.trans.shared.b16 {%0,%1,%2,%3}, [%4];" \
                 : "=r"(r0), "=r"(r1), "=r"(r2), "=r"(r3) : "r"(addr))
#define MMA_BF16(c0,c1,c2,c3,a0,a1,a2,a3,b0,b1) \
    asm volatile("mma.sync.aligned.m16n8k16.row.col.f32.bf16.bf16.f32 " \
                 "{%0,%1,%2,%3}, {%4,%5,%6,%7}, {%8,%9}, {%0,%1,%2,%3};" \
                 : "+f"(c0), "+f"(c1), "+f"(c2), "+f"(c3) \
                 : "r"(a0), "r"(a1), "r"(a2), "r"(a3), "r"(b0), "r"(b1))

// ---------------- fused prep: M split + W split + zero stats + zero mid ----------
__global__ void prep_all(const float* __restrict__ sup, const float* __restrict__ eps,
                         const float* __restrict__ w) {
    int idx = blockIdx.x * blockDim.x + threadIdx.x;
    if (idx < 64) { g_sum[idx] = 0.f; g_sumsq[idx] = 0.f; }
    if (idx < (int)(ROWS * (size_t)OUTC)) g_mid[idx] = 0.f;
    if (idx < 2 * (int)AS) {
        int rest = idx & (int)(AS - 1);
        int n = rest >> 9, m = rest & 511;
        float v = sup[idx] + ((n == m) ? (1.0f + eps[0]) : 0.0f);
        bf16 h, l; split_bf16(v, h, l);
        g_Mh[idx] = h; g_Ml[idx] = l;
    } else {
        int widx = idx - 2 * (int)AS;          // ko*768 + d
        if (widx >= ZC * BD) return;
        int d  = widx % BD;
        int ko = widx / BD;
        int k = ko >> 6, o = ko & 63;
        int l = d >> 6, h = d & 63;
        float v = w[((size_t)l * 256 + h * 4 + k) * OUTC + o];
        bf16 hh, ll; split_bf16(v, hh, ll);
        g_Wth[widx] = hh; g_Wtl[widx] = ll;
    }
}

// ---------------- stage1 (fused X-split; BK=64; 12 chunks x 3 parts) -------------
#define S1_PAD 72
#define S1_NCH 12
#define S1_TILE (128 * S1_PAD)
#define S1_SMEM (10 * S1_TILE * 2)

__global__ __launch_bounds__(256, 1) void stage1_mma(const float* __restrict__ X) {
    extern __shared__ __align__(16) bf16 sm1[];
    const int tid = threadIdx.x;
    const int warp = tid >> 5, lane = tid & 31;
    const int wm = warp >> 1, wn = warp & 1;
    const int g = lane >> 2, q = lane & 3;
    const int r0 = blockIdx.y * 128;
    const int c0 = blockIdx.x * 128;

    const int aRowOff = ((lane >> 3) & 1) * 8 + (lane & 7);
    const int aKOff   = (lane >> 4) * 8;
    const int bRowOff = (lane >> 4) * 8 + (lane & 7);
    const int bKOff   = ((lane >> 3) & 1) * 8;

    uint32_t AhB[2], AlB[2], WhB[3], WlB[3];
#pragma unroll
    for (int i = 0; i < 2; ++i) {
        AhB[i] = smem_u32(sm1 + (0 + i) * S1_TILE);
        AlB[i] = smem_u32(sm1 + (2 + i) * S1_TILE);
    }
#pragma unroll
    for (int i = 0; i < 3; ++i) {
        WhB[i] = smem_u32(sm1 + (4 + i) * S1_TILE);
        WlB[i] = smem_u32(sm1 + (7 + i) * S1_TILE);
    }

    float c[2][8][4];
#pragma unroll
    for (int i = 0; i < 2; ++i)
#pragma unroll
        for (int j = 0; j < 8; ++j)
#pragma unroll
            for (int t = 0; t < 4; ++t) c[i][j][t] = 0.f;

    const int xRow = tid >> 4;
    const int xSeg = tid & 15;
    float4 xv[8];

    auto ldgX = [&](int ch) {
        int kpos = ch * 64;
#pragma unroll
        for (int t = 0; t < 8; ++t) {
            int row = xRow + t * 16;
            xv[t] = *(const float4*)(X + (size_t)(r0 + row) * BD + kpos + xSeg * 4);
        }
    };
    auto cvtSts = [&](int abuf) {
#pragma unroll
        for (int t = 0; t < 8; ++t) {
            int row = xRow + t * 16;
            bf16 h0,l0,h1,l1,h2,l2,h3,l3;
            split_bf16(xv[t].x, h0, l0); split_bf16(xv[t].y, h1, l1);
            split_bf16(xv[t].z, h2, l2); split_bf16(xv[t].w, h3, l3);
            uint2 ph = { pack2(h0, h1), pack2(h2, h3) };
            uint2 pl = { pack2(l0, l1), pack2(l2, l3) };
            uint32_t so = (uint32_t)(row * S1_PAD + xSeg * 4) * 2;
            *(uint2*)((char*)sm1 + (AhB[abuf] - smem_u32(sm1)) + so) = ph;
            *(uint2*)((char*)sm1 + (AlB[abuf] - smem_u32(sm1)) + so) = pl;
        }
    };
    auto loadW = [&](int ch) {
        int wb = ch % 3;
        int kpos = ch * 64;
#pragma unroll
        for (int t = 0; t < 4; ++t) {
            int u = tid + t * 256;
            int row = u >> 3, seg = u & 7;
            uint32_t so = (uint32_t)(row * S1_PAD + seg * 8) * 2;
            cp16(WhB[wb] + so, g_Wth + (size_t)(c0 + row) * BD + kpos + seg * 8);
            cp16(WlB[wb] + so, g_Wtl + (size_t)(c0 + row) * BD + kpos + seg * 8);
        }
        CP_COMMIT();
    };

    ldgX(0); cvtSts(0);
    loadW(0); loadW(1);
    ldgX(1);
    CP_WAIT1();
    __syncthreads();

    for (int ch = 0; ch < S1_NCH; ++ch) {
        int abuf = ch & 1, wbuf = ch % 3;
#pragma unroll
        for (int ks = 0; ks < 64; ks += 16) {
            uint32_t ah[2][4], al[2][4];
#pragma unroll
            for (int i = 0; i < 2; ++i) {
                uint32_t ro = (uint32_t)(wm * 32 + i * 16 + aRowOff) * (S1_PAD * 2)
                            + (uint32_t)(ks + aKOff) * 2;
                LDSM_X4(ah[i][0], ah[i][1], ah[i][2], ah[i][3], AhB[abuf] + ro);
                LDSM_X4(al[i][0], al[i][1], al[i][2], al[i][3], AlB[abuf] + ro);
            }
            uint32_t bh[8][2], bl[8][2];
#pragma unroll
            for (int j2 = 0; j2 < 4; ++j2) {
                uint32_t ro = (uint32_t)(wn * 64 + j2 * 16 + bRowOff) * (S1_PAD * 2)
                            + (uint32_t)(ks + bKOff) * 2;
                uint32_t r0_, r1_, r2_, r3_;
                LDSM_X4(r0_, r1_, r2_, r3_, WhB[wbuf] + ro);
                bh[2*j2][0] = r0_;   bh[2*j2][1] = r1_;
                bh[2*j2+1][0] = r2_; bh[2*j2+1][1] = r3_;
                LDSM_X4(r0_, r1_, r2_, r3_, WlB[wbuf] + ro);
                bl[2*j2][0] = r0_;   bl[2*j2][1] = r1_;
                bl[2*j2+1][0] = r2_; bl[2*j2+1][1] = r3_;
            }
#pragma unroll
            for (int i = 0; i < 2; ++i)
#pragma unroll
                for (int j = 0; j < 8; ++j) {
                    MMA_BF16(c[i][j][0], c[i][j][1], c[i][j][2], c[i][j][3],
                             ah[i][0], ah[i][1], ah[i][2], ah[i][3], bh[j][0], bh[j][1]);
                    MMA_BF16(c[i][j][0], c[i][j][1], c[i][j][2], c[i][j][3],
                             al[i][0], al[i][1], al[i][2], al[i][3], bh[j][0], bh[j][1]);
                    MMA_BF16(c[i][j][0], c[i][j][1], c[i][j][2], c[i][j][3],
                             ah[i][0], ah[i][1], ah[i][2], ah[i][3], bl[j][0], bl[j][1]);
                }
        }
        if (ch + 1 < S1_NCH) cvtSts(abuf ^ 1);
        if (ch + 2 < S1_NCH) { ldgX(ch + 2); loadW(ch + 2); }
        else CP_COMMIT();
        CP_WAIT1();
        __syncthreads();
    }

#pragma unroll
    for (int i = 0; i < 2; ++i) {
        int row = r0 + wm * 32 + i * 16 + g;
#pragma unroll
        for (int j = 0; j < 8; ++j) {
            int col = c0 + wn * 64 + j * 8 + 2 * q;
#pragma unroll
            for (int hrow = 0; hrow < 2; ++hrow) {
                float v0 = c[i][j][hrow * 2], v1 = c[i][j][hrow * 2 + 1];
                bf16 h0, l0, h1, l1;
                split_bf16(v0, h0, l0); split_bf16(v1, h1, l1);
                size_t off = (size_t)(row + hrow * 8) * ZC + col;
                *(uint32_t*)&g_Zh[off] = pack2(h0, h1);
                *(uint32_t*)&g_Zl[off] = pack2(l0, l1);
            }
        }
    }
}

// ---------------- stage2 common: fragment-reuse, BK=64, 8 chunks, 2-stage --------
// smem: Ah[2] Al[2] (128x72) + Bh[2] Bl[2] (64x72) = 110.6 KB -> occ 2
#define S2_APAD 72
#define S2_BPAD 72
#define S2_NCH 8
#define S2_ATILE (128 * S2_APAD)
#define S2_BTILE (64 * S2_BPAD)
#define S2_SMEM ((4 * S2_ATILE + 4 * S2_BTILE) * 2)

// stage2a: V_s = Z_{2s} + M_s * Z_{2s+1}  (fused vadd epilogue)
__global__ __launch_bounds__(256, 2) void stage2a_mma() {
    extern __shared__ __align__(16) bf16 sm2[];
    const int tid = threadIdx.x;
    const int warp = tid >> 5, lane = tid & 31;
    const int wm = warp >> 1, wn = warp & 1;
    const int g = lane >> 2, q = lane & 3;
    const int n0 = blockIdx.x * 128;
    const int b  = blockIdx.y;
    const int s  = blockIdx.z;

    const int fragRow  = lane & 15;
    const int fragCol8 = (lane >> 4) * 8;

    uint32_t AhB[2], AlB[2], BhB[2], BlB[2];
#pragma unroll
    for (int i = 0; i < 2; ++i) {
        AhB[i] = smem_u32(sm2 + (0 + i) * S2_ATILE);
        AlB[i] = smem_u32(sm2 + (2 + i) * S2_ATILE);
        BhB[i] = smem_u32(sm2 + 4 * S2_ATILE + (0 + i) * S2_BTILE);
        BlB[i] = smem_u32(sm2 + 4 * S2_ATILE + (2 + i) * S2_BTILE);
    }

    float c[2][4][4];
#pragma unroll
    for (int i = 0; i < 2; ++i)
#pragma unroll
        for (int j = 0; j < 4; ++j)
#pragma unroll
            for (int t = 0; t < 4; ++t) c[i][j][t] = 0.f;

    const bf16* Amh = g_Mh + (size_t)s * AS;
    const bf16* Aml = g_Ml + (size_t)s * AS;
    const int zcol = (2 * s + 1) * 64;

    auto load_chunk = [&](int ch) {
        int buf = ch & 1;
        int mpos = ch * 64;
#pragma unroll
        for (int t = 0; t < 4; ++t) {
            int u = tid + t * 256;
            int row = u >> 3, seg = u & 7;
            uint32_t so = (uint32_t)(row * S2_APAD + seg * 8) * 2;
            cp16(AhB[buf] + so, Amh + (size_t)(n0 + row) * NN + mpos + seg * 8);
            cp16(AlB[buf] + so, Aml + (size_t)(n0 + row) * NN + mpos + seg * 8);
        }
#pragma unroll
        for (int t = 0; t < 2; ++t) {
            int u = tid + t * 256;
            int row = u >> 3, seg = u & 7;
            uint32_t so = (uint32_t)(row * S2_BPAD + seg * 8) * 2;
            cp16(BhB[buf] + so, g_Zh + (size_t)(b * NN + mpos + row) * ZC + zcol + seg * 8);
            cp16(BlB[buf] + so, g_Zl + (size_t)(b * NN + mpos + row) * ZC + zcol + seg * 8);
        }
        CP_COMMIT();
    };

    load_chunk(0); load_chunk(1);

    for (int ch = 0; ch < S2_NCH; ++ch) {
        int buf = ch & 1;
        CP_WAIT1();
        __syncthreads();
#pragma unroll
        for (int ks = 0; ks < 64; ks += 16) {
            uint32_t ah[2][4], al[2][4];
#pragma unroll
            for (int i = 0; i < 2; ++i) {
                uint32_t ro = (uint32_t)(wm * 32 + i * 16 + fragRow) * (S2_APAD * 2)
                            + (uint32_t)(ks + fragCol8) * 2;
                LDSM_X4(ah[i][0], ah[i][1], ah[i][2], ah[i][3], AhB[buf] + ro);
                LDSM_X4(al[i][0], al[i][1], al[i][2], al[i][3], AlB[buf] + ro);
            }
            uint32_t bh[4][2], bl[4][2];
#pragma unroll
            for (int jj = 0; jj < 2; ++jj) {
                uint32_t ro = (uint32_t)(ks + fragRow) * (S2_BPAD * 2)
                            + (uint32_t)(wn * 32 + jj * 16 + fragCol8) * 2;
                uint32_t r0_, r1_, r2_, r3_;
                LDSM_X4T(r0_, r1_, r2_, r3_, BhB[buf] + ro);
                bh[2*jj][0] = r0_;   bh[2*jj][1] = r1_;
                bh[2*jj+1][0] = r2_; bh[2*jj+1][1] = r3_;
                LDSM_X4T(r0_, r1_, r2_, r3_, BlB[buf] + ro);
                bl[2*jj][0] = r0_;   bl[2*jj][1] = r1_;
                bl[2*jj+1][0] = r2_; bl[2*jj+1][1] = r3_;
            }
#pragma unroll
            for (int i = 0; i < 2; ++i)
#pragma unroll
                for (int j = 0; j < 4; ++j) {
                    MMA_BF16(c[i][j][0], c[i][j][1], c[i][j][2], c[i][j][3],
                             ah[i][0], ah[i][1], ah[i][2], ah[i][3], bh[j][0], bh[j][1]);
                    MMA_BF16(c[i][j][0], c[i][j][1], c[i][j][2], c[i][j][3],
                             al[i][0], al[i][1], al[i][2], al[i][3], bh[j][0], bh[j][1]);
                    MMA_BF16(c[i][j][0], c[i][j][1], c[i][j][2], c[i][j][3],
                             ah[i][0], ah[i][1], ah[i][2], ah[i][3], bl[j][0], bl[j][1]);
                }
        }
        __syncthreads();
        if (ch + 2 < S2_NCH) load_chunk(ch + 2);
        else CP_COMMIT();
    }

    // fused epilogue: V = Z_even + M*Z_odd, split to bf16 -> Vh/Vl
    const size_t vbase = ((size_t)(s * BB + b) * NN) * OUTC;
#pragma unroll
    for (int i = 0; i < 2; ++i) {
#pragma unroll
        for (int j = 0; j < 4; ++j) {
            int col = wn * 32 + j * 8 + 2 * q;
#pragma unroll
            for (int hrow = 0; hrow < 2; ++hrow) {
                int row = n0 + wm * 32 + i * 16 + g + hrow * 8;
                size_t zo = (size_t)(b * NN + row) * ZC + s * 128 + col;
                uint32_t zh = *(const uint32_t*)&g_Zh[zo];
                uint32_t zl = *(const uint32_t*)&g_Zl[zo];
                float v0 = c[i][j][hrow * 2]     + bf_lo(zh) + bf_lo(zl);
                float v1 = c[i][j][hrow * 2 + 1] + bf_hi(zh) + bf_hi(zl);
                bf16 h0, l0, h1, l1;
                split_bf16(v0, h0, l0); split_bf16(v1, h1, l1);
                size_t vo = vbase + (size_t)row * OUTC + col;
                *(uint32_t*)&g_Vh[vo] = pack2(h0, h1);
                *(uint32_t*)&g_Vl[vo] = pack2(l0, l1);
            }
        }
    }
}

// stage2b: mid += M_s * V_s  (deterministic 2-way atomicAdd; mid zeroed in prep)
__global__ __launch_bounds__(256, 2) void stage2b_mma() {
    extern __shared__ __align__(16) bf16 sm3[];
    const int tid = threadIdx.x;
    const int warp = tid >> 5, lane = tid & 31;
    const int wm = warp >> 1, wn = warp & 1;
    const int g = lane >> 2, q = lane & 3;
    const int n0 = blockIdx.x * 128;
    const int b  = blockIdx.y;
    const int s  = blockIdx.z;

    const int fragRow  = lane & 15;
    const int fragCol8 = (lane >> 4) * 8;

    uint32_t AhB[2], AlB[2], BhB[2], BlB[2];
#pragma unroll
    for (int i = 0; i < 2; ++i) {
        AhB[i] = smem_u32(sm3 + (0 + i) * S2_ATILE);
        AlB[i] = smem_u32(sm3 + (2 + i) * S2_ATILE);
        BhB[i] = smem_u32(sm3 + 4 * S2_ATILE + (0 + i) * S2_BTILE);
        BlB[i] = smem_u32(sm3 + 4 * S2_ATILE + (2 + i) * S2_BTILE);
    }

    float c[2][4][4];
#pragma unroll
    for (int i = 0; i < 2; ++i)
#pragma unroll
        for (int j = 0; j < 4; ++j)
#pragma unroll
            for (int t = 0; t < 4; ++t) c[i][j][t] = 0.f;

    const bf16* Amh = g_Mh + (size_t)s * AS;
    const bf16* Aml = g_Ml + (size_t)s * AS;
    const size_t vbase = ((size_t)(s * BB + b) * NN) * OUTC;

    auto load_chunk = [&](int ch) {
        int buf = ch & 1;
        int mpos = ch * 64;
#pragma unroll
        for (int t = 0; t < 4; ++t) {
            int u = tid + t * 256;
            int row = u >> 3, seg = u & 7;
            uint32_t so = (uint32_t)(row * S2_APAD + seg * 8) * 2;
            cp16(AhB[buf] + so, Amh + (size_t)(n0 + row) * NN + mpos + seg * 8);
            cp16(AlB[buf] + so, Aml + (size_t)(n0 + row) * NN + mpos + seg * 8);
        }
#pragma unroll
        for (int t = 0; t < 2; ++t) {
            int u = tid + t * 256;
            int row = u >> 3, seg = u & 7;
            uint32_t so = (uint32_t)(row * S2_BPAD + seg * 8) * 2;
            cp16(BhB[buf] + so, g_Vh + vbase + (size_t)(mpos + row) * OUTC + seg * 8);
            cp16(BlB[buf] + so, g_Vl + vbase + (size_t)(mpos + row) * OUTC + seg * 8);
        }
        CP_COMMIT();
    };

    load_chunk(0); load_chunk(1);

    for (int ch = 0; ch < S2_NCH; ++ch) {
        int buf = ch & 1;
        CP_WAIT1();
        __syncthreads();
#pragma unroll
        for (int ks = 0; ks < 64; ks += 16) {
            uint32_t ah[2][4], al[2][4];
#pragma unroll
            for (int i = 0; i < 2; ++i) {
                uint32_t ro = (uint32_t)(wm * 32 + i * 16 + fragRow) * (S2_APAD * 2)
                            + (uint32_t)(ks + fragCol8) * 2;
                LDSM_X4(ah[i][0], ah[i][1], ah[i][2], ah[i][3], AhB[buf] + ro);
                LDSM_X4(al[i][0], al[i][1], al[i][2], al[i][3], AlB[buf] + ro);
            }
            uint32_t bh[4][2], bl[4][2];
#pragma unroll
            for (int jj = 0; jj < 2; ++jj) {
                uint32_t ro = (uint32_t)(ks + fragRow) * (S2_BPAD * 2)
                            + (uint32_t)(wn * 32 + jj * 16 + fragCol8) * 2;
                uint32_t r0_, r1_, r2_, r3_;
                LDSM_X4T(r0_, r1_, r2_, r3_, BhB[buf] + ro);
                bh[2*jj][0] = r0_;   bh[2*jj][1] = r1_;
                bh[2*jj+1][0] = r2_; bh[2*jj+1][1] = r3_;
                LDSM_X4T(r0_, r1_, r2_, r3_, BlB[buf] + ro);
                bl[2*jj][0] = r0_;   bl[2*jj][1] = r1_;
                bl[2*jj+1][0] = r2_; bl[2*jj+1][1] = r3_;
            }
#pragma unroll
            for (int i = 0; i < 2; ++i)
#pragma unroll
                for (int j = 0; j < 4; ++j) {
                    MMA_BF16(c[i][j][0], c[i][j][1], c[i][j][2], c[i][j][3],
                             ah[i][0], ah[i][1], ah[i][2], ah[i][3], bh[j][0], bh[j][1]);
                    MMA_BF16(c[i][j][0], c[i][j][1], c[i][j][2], c[i][j][3],
                             al[i][0], al[i][1], al[i][2], al[i][3], bh[j][0], bh[j][1]);
                    MMA_BF16(c[i][j][0], c[i][j][1], c[i][j][2], c[i][j][3],
                             ah[i][0], ah[i][1], ah[i][2], ah[i][3], bl[j][0], bl[j][1]);
                }
        }
        __syncthreads();
        if (ch + 2 < S2_NCH) load_chunk(ch + 2);
        else CP_COMMIT();
    }

    // epilogue: deterministic 2-way accumulate into g_mid (a+b == b+a in IEEE)
#pragma unroll
    for (int i = 0; i < 2; ++i) {
        int row = n0 + wm * 32 + i * 16 + g;
#pragma unroll
        for (int j = 0; j < 4; ++j) {
            int col = wn * 32 + j * 8 + 2 * q;
#pragma unroll
            for (int hrow = 0; hrow < 2; ++hrow) {
                size_t off = (size_t)(b * NN + row + hrow * 8) * OUTC + col;
                atomicAdd(&g_mid[off],     c[i][j][hrow * 2]);
                atomicAdd(&g_mid[off + 1], c[i][j][hrow * 2 + 1]);
            }
        }
    }
}

// ---------------- BN tail (single g_mid) ----------------
__global__ __launch_bounds__(256) void bn_stats() {
    const int c = threadIdx.x & 63;
    const int rl = threadIdx.x >> 6;
    float s = 0.f, s2 = 0.f;
    for (int r = blockIdx.x * 4 + rl; r < ROWS; r += gridDim.x * 4) {
        float v = g_mid[(size_t)r * OUTC + c];
        s += v; s2 += v * v;
    }
    __shared__ float sh[256], sh2[256];
    sh[threadIdx.x] = s; sh2[threadIdx.x] = s2;
    __syncthreads();
    if (rl == 0) {
        s  = sh[c] + sh[c + 64] + sh[c + 128] + sh[c + 192];
        s2 = sh2[c] + sh2[c + 64] + sh2[c + 128] + sh2[c + 192];
        atomicAdd(&g_sum[c], s); atomicAdd(&g_sumsq[c], s2);
    }
}
__global__ __launch_bounds__(256) void bn_relu_fc2(
    const float* __restrict__ gamma, const float* __restrict__ beta,
    const float* __restrict__ w2,    const float* __restrict__ b2,
    float* __restrict__ out)
{
    __shared__ float w2t[64][65];
    __shared__ float ysm[64][65];
    __shared__ float scale_s[64], shift_s[64];
    const int tid = threadIdx.x;
    const int r0 = blockIdx.x * 64;

#pragma unroll
    for (int t = 0; t < 16; ++t) {
        int idx = tid + t * 256;
        int o = idx >> 6, cc = idx & 63;
        w2t[cc][o] = w2[idx];
    }
    if (tid < OUTC) {
        const float invN = 1.0f / (float)ROWS;
        float mean = g_sum[tid] * invN;
        float var  = g_sumsq[tid] * invN - mean * mean;
        float sc   = gamma[tid] * rsqrtf(var + 1e-5f);
        scale_s[tid] = sc;
        shift_s[tid] = beta[tid] - mean * sc;
    }
    __syncthreads();

#pragma unroll
    for (int t = 0; t < 16; ++t) {
        int idx = tid + t * 256;
        int r = idx >> 6, cc = idx & 63;
        float v = g_mid[(size_t)(r0 + r) * OUTC + cc];
        ysm[r][cc] = fmaxf(fmaf(v, scale_s[cc], shift_s[cc]), 0.f);
    }
    __syncthreads();

    const int tr = tid >> 4, tc = tid & 15;
    float acc[4][4];
#pragma unroll
    for (int i = 0; i < 4; ++i)
#pragma unroll
        for (int j = 0; j < 4; ++j) acc[i][j] = b2[tc * 4 + j];
    for (int k = 0; k < 64; ++k) {
        float w0 = w2t[k][tc * 4 + 0], w1 = w2t[k][tc * 4 + 1];
        float w2v = w2t[k][tc * 4 + 2], w3 = w2t[k][tc * 4 + 3];
#pragma unroll
        for (int i = 0; i < 4; ++i) {
            float y = ysm[tr * 4 + i][k];
            acc[i][0] = fmaf(y, w0, acc[i][0]);
            acc[i][1] = fmaf(y, w1, acc[i][1]);
            acc[i][2] = fmaf(y, w2v, acc[i][2]);
            acc[i][3] = fmaf(y, w3, acc[i][3]);
        }
    }
#pragma unroll
    for (int i = 0; i < 4; ++i)
        *(float4*)&out[(size_t)(r0 + tr * 4 + i) * OUTC + tc * 4] = *(float4*)&acc[i][0];
}

// ---------------- launch ----------------
extern "C" void kernel_launch(void* const* d_in, const int* in_sizes, int n_in,
                              void* d_out, int out_size) {
    const float* x       = (const float*)d_in[0];
    const float* support = (const float*)d_in[1];
    const float* weight  = (const float*)d_in[2];
    const float* eps     = (const float*)d_in[3];
    const float* gamma   = (const float*)d_in[4];
    const float* beta    = (const float*)d_in[5];
    const float* w2      = (const float*)d_in[6];
    const float* b2      = (const float*)d_in[7];
    float* out           = (float*)d_out;

    cudaFuncSetAttribute(stage1_mma,  cudaFuncAttributeMaxDynamicSharedMemorySize, S1_SMEM);
    cudaFuncSetAttribute(stage2a_mma, cudaFuncAttributeMaxDynamicSharedMemorySize, S2_SMEM);
    cudaFuncSetAttribute(stage2b_mma, cudaFuncAttributeMaxDynamicSharedMemorySize, S2_SMEM);

    {
        int total = (int)(ROWS * (size_t)OUTC);           // 1,048,576 covers all sections
        prep_all<<<(total + 255) / 256, 256>>>(support, eps, weight);
    }

    stage1_mma<<<dim3(ZC / 128, ROWS / 128), 256, S1_SMEM>>>(x);

    stage2a_mma<<<dim3(NN / 128, BB, 2), 256, S2_SMEM>>>();
    stage2b_mma<<<dim3(NN / 128, BB, 2), 256, S2_SMEM>>>();

    bn_stats<<<128, 256>>>();
    bn_relu_fc2<<<ROWS / 64, 256>>>(gamma, beta, w2, b2, out);
}

// round 16
// speedup vs baseline: 1.2209x; 1.0397x over previous
#include <cuda_runtime.h>
#include <cuda_bf16.h>
#include <math.h>
#include <stdint.h>

typedef __nv_bfloat16 bf16;

// ---------------- problem dims ----------------
#define BB    32
#define NN    512
#define BD    768            // L*H
#define ROWS  (BB*NN)        // 16384
#define OUTC  64
#define KSUP  4
#define ZC    256            // KSUP*OUTC
#define AS    ((size_t)NN*NN)

// ---------------- device scratch (no allocation) ----------------
__device__ __align__(256) bf16  g_Mh [2*AS], g_Ml [2*AS];    // M = A+(1+eps)I, split
__device__ __align__(256) bf16  g_Wth[ZC*BD], g_Wtl[ZC*BD];  // W^T repack [ko][d]
__device__ __align__(256) bf16  g_Zh[(size_t)ROWS*ZC], g_Zl[(size_t)ROWS*ZC];
__device__ __align__(256) bf16  g_Vh[(size_t)2*ROWS*OUTC], g_Vl[(size_t)2*ROWS*OUTC];
__device__ __align__(256) float g_mid[(size_t)ROWS*OUTC];
__device__ float g_sum[OUTC], g_sumsq[OUTC];

__device__ __forceinline__ uint32_t smem_u32(const void* p) {
    uint32_t a;
    asm("{ .reg .u64 t; cvta.to.shared.u64 t, %1; cvt.u32.u64 %0, t; }" : "=r"(a) : "l"(p));
    return a;
}
__device__ __forceinline__ void split_bf16(float v, bf16& h, bf16& l) {
    h = __float2bfloat16(v);
    l = __float2bfloat16(v - __bfloat162float(h));
}
__device__ __forceinline__ uint32_t pack2(bf16 lo, bf16 hi) {
    return ((uint32_t)__bfloat16_as_ushort(hi) << 16) | __bfloat16_as_ushort(lo);
}
__device__ __forceinline__ float bf_lo(uint32_t u) {
    return __bfloat162float(__ushort_as_bfloat16((unsigned short)(u & 0xFFFF)));
}
__device__ __forceinline__ float bf_hi(uint32_t u) {
    return __bfloat162float(__ushort_as_bfloat16((unsigned short)(u >> 16)));
}
__device__ __forceinline__ void cp16(uint32_t s, const void* g) {
    asm volatile("cp.async.cg.shared.global [%0], [%1], 16;"
                 :: "r"(s), "l"(__cvta_generic_to_global(g)) : "memory");
}
#define CP_COMMIT() asm volatile("cp.async.commit_group;" ::: "memory")
#define CP_WAIT1()  asm volatile("cp.async.wait_group 1;"  ::: "memory")

#define LDSM_X4(r0,r1,r2,r3,addr) \
    asm volatile("ldmatrix.sync.aligned.m8n8.x4.shared.b16 {%0,%1,%2,%3}, [%4];" \
                 : "=r"(r0), "=r"(r1), "=r"(r2), "=r"(r3) : "r"(addr))
#define LDSM_X4T(r0,r1,r2,r3,addr) \
    asm volatile("ldmatrix.sync.aligned.m8n8.x4.trans.shared.b16 {%0,%1,%2,%3}, [%4];" \
                 : "=r"(r0), "=r"(r1), "=r"(r2), "=r"(r3) : "r"(addr))
#define MMA_BF16(c0,c1,c2,c3,a0,a1,a2,a3,b0,b1) \
    asm volatile("mma.sync.aligned.m16n8k16.row.col.f32.bf16.bf16.f32 " \
                 "{%0,%1,%2,%3}, {%4,%5,%6,%7}, {%8,%9}, {%0,%1,%2,%3};" \
                 : "+f"(c0), "+f"(c1), "+f"(c2), "+f"(c3) \
                 : "r"(a0), "r"(a1), "r"(a2), "r"(a3), "r"(b0), "r"(b1))

// ---------------- fused prep: M split + W split + zero stats + zero mid ----------
__global__ void prep_all(const float* __restrict__ sup, const float* __restrict__ eps,
                         const float* __restrict__ w) {
    int idx = blockIdx.x * blockDim.x + threadIdx.x;
    if (idx < 64) { g_sum[idx] = 0.f; g_sumsq[idx] = 0.f; }
    if (idx < (int)(ROWS * (size_t)OUTC)) g_mid[idx] = 0.f;
    if (idx < 2 * (int)AS) {
        int rest = idx & (int)(AS - 1);
        int n = rest >> 9, m = rest & 511;
        float v = sup[idx] + ((n == m) ? (1.0f + eps[0]) : 0.0f);
        bf16 h, l; split_bf16(v, h, l);
        g_Mh[idx] = h; g_Ml[idx] = l;
    } else {
        int widx = idx - 2 * (int)AS;          // ko*768 + d
        if (widx >= ZC * BD) return;
        int d  = widx % BD;
        int ko = widx / BD;
        int k = ko >> 6, o = ko & 63;
        int l = d >> 6, h = d & 63;
        float v = w[((size_t)l * 256 + h * 4 + k) * OUTC + o];
        bf16 hh, ll; split_bf16(v, hh, ll);
        g_Wth[widx] = hh; g_Wtl[widx] = ll;
    }
}

// ---------------- stage1 (fused X-split; BK=64; 12 chunks x 3 parts) -------------
#define S1_PAD 72
#define S1_NCH 12
#define S1_TILE (128 * S1_PAD)
#define S1_SMEM (10 * S1_TILE * 2)

__global__ __launch_bounds__(256, 1) void stage1_mma(const float* __restrict__ X) {
    extern __shared__ __align__(16) bf16 sm1[];
    const int tid = threadIdx.x;
    const int warp = tid >> 5, lane = tid & 31;
    const int wm = warp >> 1, wn = warp & 1;
    const int g = lane >> 2, q = lane & 3;
    const int r0 = blockIdx.y * 128;
    const int c0 = blockIdx.x * 128;

    const int aRowOff = ((lane >> 3) & 1) * 8 + (lane & 7);
    const int aKOff   = (lane >> 4) * 8;
    const int bRowOff = (lane >> 4) * 8 + (lane & 7);
    const int bKOff   = ((lane >> 3) & 1) * 8;

    uint32_t AhB[2], AlB[2], WhB[3], WlB[3];
#pragma unroll
    for (int i = 0; i < 2; ++i) {
        AhB[i] = smem_u32(sm1 + (0 + i) * S1_TILE);
        AlB[i] = smem_u32(sm1 + (2 + i) * S1_TILE);
    }
#pragma unroll
    for (int i = 0; i < 3; ++i) {
        WhB[i] = smem_u32(sm1 + (4 + i) * S1_TILE);
        WlB[i] = smem_u32(sm1 + (7 + i) * S1_TILE);
    }

    float c[2][8][4];
#pragma unroll
    for (int i = 0; i < 2; ++i)
#pragma unroll
        for (int j = 0; j < 8; ++j)
#pragma unroll
            for (int t = 0; t < 4; ++t) c[i][j][t] = 0.f;

    const int xRow = tid >> 4;
    const int xSeg = tid & 15;
    float4 xv[8];

    auto ldgX = [&](int ch) {
        int kpos = ch * 64;
#pragma unroll
        for (int t = 0; t < 8; ++t) {
            int row = xRow + t * 16;
            xv[t] = *(const float4*)(X + (size_t)(r0 + row) * BD + kpos + xSeg * 4);
        }
    };
    auto cvtSts = [&](int abuf) {
#pragma unroll
        for (int t = 0; t < 8; ++t) {
            int row = xRow + t * 16;
            bf16 h0,l0,h1,l1,h2,l2,h3,l3;
            split_bf16(xv[t].x, h0, l0); split_bf16(xv[t].y, h1, l1);
            split_bf16(xv[t].z, h2, l2); split_bf16(xv[t].w, h3, l3);
            uint2 ph = { pack2(h0, h1), pack2(h2, h3) };
            uint2 pl = { pack2(l0, l1), pack2(l2, l3) };
            uint32_t so = (uint32_t)(row * S1_PAD + xSeg * 4) * 2;
            *(uint2*)((char*)sm1 + (AhB[abuf] - smem_u32(sm1)) + so) = ph;
            *(uint2*)((char*)sm1 + (AlB[abuf] - smem_u32(sm1)) + so) = pl;
        }
    };
    auto loadW = [&](int ch) {
        int wb = ch % 3;
        int kpos = ch * 64;
#pragma unroll
        for (int t = 0; t < 4; ++t) {
            int u = tid + t * 256;
            int row = u >> 3, seg = u & 7;
            uint32_t so = (uint32_t)(row * S1_PAD + seg * 8) * 2;
            cp16(WhB[wb] + so, g_Wth + (size_t)(c0 + row) * BD + kpos + seg * 8);
            cp16(WlB[wb] + so, g_Wtl + (size_t)(c0 + row) * BD + kpos + seg * 8);
        }
        CP_COMMIT();
    };

    ldgX(0); cvtSts(0);
    loadW(0); loadW(1);
    ldgX(1);
    CP_WAIT1();
    __syncthreads();

    for (int ch = 0; ch < S1_NCH; ++ch) {
        int abuf = ch & 1, wbuf = ch % 3;
#pragma unroll
        for (int ks = 0; ks < 64; ks += 16) {
            uint32_t ah[2][4], al[2][4];
#pragma unroll
            for (int i = 0; i < 2; ++i) {
                uint32_t ro = (uint32_t)(wm * 32 + i * 16 + aRowOff) * (S1_PAD * 2)
                            + (uint32_t)(ks + aKOff) * 2;
                LDSM_X4(ah[i][0], ah[i][1], ah[i][2], ah[i][3], AhB[abuf] + ro);
                LDSM_X4(al[i][0], al[i][1], al[i][2], al[i][3], AlB[abuf] + ro);
            }
            uint32_t bh[8][2], bl[8][2];
#pragma unroll
            for (int j2 = 0; j2 < 4; ++j2) {
                uint32_t ro = (uint32_t)(wn * 64 + j2 * 16 + bRowOff) * (S1_PAD * 2)
                            + (uint32_t)(ks + bKOff) * 2;
                uint32_t r0_, r1_, r2_, r3_;
                LDSM_X4(r0_, r1_, r2_, r3_, WhB[wbuf] + ro);
                bh[2*j2][0] = r0_;   bh[2*j2][1] = r1_;
                bh[2*j2+1][0] = r2_; bh[2*j2+1][1] = r3_;
                LDSM_X4(r0_, r1_, r2_, r3_, WlB[wbuf] + ro);
                bl[2*j2][0] = r0_;   bl[2*j2][1] = r1_;
                bl[2*j2+1][0] = r2_; bl[2*j2+1][1] = r3_;
            }
#pragma unroll
            for (int i = 0; i < 2; ++i)
#pragma unroll
                for (int j = 0; j < 8; ++j) {
                    MMA_BF16(c[i][j][0], c[i][j][1], c[i][j][2], c[i][j][3],
                             ah[i][0], ah[i][1], ah[i][2], ah[i][3], bh[j][0], bh[j][1]);
                    MMA_BF16(c[i][j][0], c[i][j][1], c[i][j][2], c[i][j][3],
                             al[i][0], al[i][1], al[i][2], al[i][3], bh[j][0], bh[j][1]);
                    MMA_BF16(c[i][j][0], c[i][j][1], c[i][j][2], c[i][j][3],
                             ah[i][0], ah[i][1], ah[i][2], ah[i][3], bl[j][0], bl[j][1]);
                }
        }
        if (ch + 1 < S1_NCH) cvtSts(abuf ^ 1);
        if (ch + 2 < S1_NCH) { ldgX(ch + 2); loadW(ch + 2); }
        else CP_COMMIT();
        CP_WAIT1();
        __syncthreads();
    }

#pragma unroll
    for (int i = 0; i < 2; ++i) {
        int row = r0 + wm * 32 + i * 16 + g;
#pragma unroll
        for (int j = 0; j < 8; ++j) {
            int col = c0 + wn * 64 + j * 8 + 2 * q;
#pragma unroll
            for (int hrow = 0; hrow < 2; ++hrow) {
                float v0 = c[i][j][hrow * 2], v1 = c[i][j][hrow * 2 + 1];
                bf16 h0, l0, h1, l1;
                split_bf16(v0, h0, l0); split_bf16(v1, h1, l1);
                size_t off = (size_t)(row + hrow * 8) * ZC + col;
                *(uint32_t*)&g_Zh[off] = pack2(h0, h1);
                *(uint32_t*)&g_Zl[off] = pack2(l0, l1);
            }
        }
    }
}

// ---------------- stage2: fragment-reuse, BK=32, 16 chunks, 3-stage, 1 sync ------
// smem per stage: Ah+Al (128x40) + Bh+Bl (32x72) = 29.7 KB; 3 stages = 89 KB -> occ 2
#define S2_APAD 40
#define S2_BPAD 72
#define S2_NCH 16
#define S2_ATILE (128 * S2_APAD)
#define S2_BTILE (32 * S2_BPAD)
#define S2_SMEM ((6 * S2_ATILE + 6 * S2_BTILE) * 2)

// stage2a: V_s = Z_{2s} + M_s * Z_{2s+1}  (fused vadd epilogue)
__global__ __launch_bounds__(256, 2) void stage2a_mma() {
    extern __shared__ __align__(16) bf16 sm2[];
    const int tid = threadIdx.x;
    const int warp = tid >> 5, lane = tid & 31;
    const int wm = warp >> 1, wn = warp & 1;
    const int g = lane >> 2, q = lane & 3;
    const int n0 = blockIdx.x * 128;
    const int b  = blockIdx.y;
    const int s  = blockIdx.z;

    const int aLdRow = tid >> 2, aLdSeg = tid & 3;   // A: 128x32, 2 cp16 per h/l
    const int bLdRow = tid >> 3, bLdSeg = tid & 7;   // B: 32x64,  1 cp16 per h/l
    const int fragRow  = lane & 15;
    const int fragCol8 = (lane >> 4) * 8;

    uint32_t AhB[3], AlB[3], BhB[3], BlB[3];
#pragma unroll
    for (int i = 0; i < 3; ++i) {
        AhB[i] = smem_u32(sm2 + (0 + i) * S2_ATILE);
        AlB[i] = smem_u32(sm2 + (3 + i) * S2_ATILE);
        BhB[i] = smem_u32(sm2 + 6 * S2_ATILE + (0 + i) * S2_BTILE);
        BlB[i] = smem_u32(sm2 + 6 * S2_ATILE + (3 + i) * S2_BTILE);
    }

    float c[2][4][4];
#pragma unroll
    for (int i = 0; i < 2; ++i)
#pragma unroll
        for (int j = 0; j < 4; ++j)
#pragma unroll
            for (int t = 0; t < 4; ++t) c[i][j][t] = 0.f;

    const bf16* Amh = g_Mh + (size_t)s * AS;
    const bf16* Aml = g_Ml + (size_t)s * AS;
    const int zcol = (2 * s + 1) * 64;

    auto load_chunk = [&](int ch) {
        int buf = ch % 3;
        int mpos = ch * 32;
        uint32_t soA0 = (uint32_t)(aLdRow * S2_APAD + aLdSeg * 8) * 2;
        uint32_t soA1 = (uint32_t)((aLdRow + 64) * S2_APAD + aLdSeg * 8) * 2;
        cp16(AhB[buf] + soA0, Amh + (size_t)(n0 + aLdRow) * NN + mpos + aLdSeg * 8);
        cp16(AhB[buf] + soA1, Amh + (size_t)(n0 + aLdRow + 64) * NN + mpos + aLdSeg * 8);
        cp16(AlB[buf] + soA0, Aml + (size_t)(n0 + aLdRow) * NN + mpos + aLdSeg * 8);
        cp16(AlB[buf] + soA1, Aml + (size_t)(n0 + aLdRow + 64) * NN + mpos + aLdSeg * 8);
        uint32_t soB = (uint32_t)(bLdRow * S2_BPAD + bLdSeg * 8) * 2;
        cp16(BhB[buf] + soB, g_Zh + (size_t)(b * NN + mpos + bLdRow) * ZC + zcol + bLdSeg * 8);
        cp16(BlB[buf] + soB, g_Zl + (size_t)(b * NN + mpos + bLdRow) * ZC + zcol + bLdSeg * 8);
        CP_COMMIT();
    };

    load_chunk(0); load_chunk(1);

    for (int ch = 0; ch < S2_NCH; ++ch) {
        int buf = ch % 3;
        CP_WAIT1();
        __syncthreads();
#pragma unroll
        for (int ks = 0; ks < 32; ks += 16) {
            uint32_t ah[2][4], al[2][4];
#pragma unroll
            for (int i = 0; i < 2; ++i) {
                uint32_t ro = (uint32_t)(wm * 32 + i * 16 + fragRow) * (S2_APAD * 2)
                            + (uint32_t)(ks + fragCol8) * 2;
                LDSM_X4(ah[i][0], ah[i][1], ah[i][2], ah[i][3], AhB[buf] + ro);
                LDSM_X4(al[i][0], al[i][1], al[i][2], al[i][3], AlB[buf] + ro);
            }
            uint32_t bh[4][2], bl[4][2];
#pragma unroll
            for (int jj = 0; jj < 2; ++jj) {
                uint32_t ro = (uint32_t)(ks + fragRow) * (S2_BPAD * 2)
                            + (uint32_t)(wn * 32 + jj * 16 + fragCol8) * 2;
                uint32_t r0_, r1_, r2_, r3_;
                LDSM_X4T(r0_, r1_, r2_, r3_, BhB[buf] + ro);
                bh[2*jj][0] = r0_;   bh[2*jj][1] = r1_;
                bh[2*jj+1][0] = r2_; bh[2*jj+1][1] = r3_;
                LDSM_X4T(r0_, r1_, r2_, r3_, BlB[buf] + ro);
                bl[2*jj][0] = r0_;   bl[2*jj][1] = r1_;
                bl[2*jj+1][0] = r2_; bl[2*jj+1][1] = r3_;
            }
#pragma unroll
            for (int i = 0; i < 2; ++i)
#pragma unroll
                for (int j = 0; j < 4; ++j) {
                    MMA_BF16(c[i][j][0], c[i][j][1], c[i][j][2], c[i][j][3],
                             ah[i][0], ah[i][1], ah[i][2], ah[i][3], bh[j][0], bh[j][1]);
                    MMA_BF16(c[i][j][0], c[i][j][1], c[i][j][2], c[i][j][3],
                             al[i][0], al[i][1], al[i][2], al[i][3], bh[j][0], bh[j][1]);
                    MMA_BF16(c[i][j][0], c[i][j][1], c[i][j][2], c[i][j][3],
                             ah[i][0], ah[i][1], ah[i][2], ah[i][3], bl[j][0], bl[j][1]);
                }
        }
        if (ch + 2 < S2_NCH) load_chunk(ch + 2);
        else CP_COMMIT();
    }

    // fused epilogue: V = Z_even + M*Z_odd, split to bf16 -> Vh/Vl
    const size_t vbase = ((size_t)(s * BB + b) * NN) * OUTC;
#pragma unroll
    for (int i = 0; i < 2; ++i) {
#pragma unroll
        for (int j = 0; j < 4; ++j) {
            int col = wn * 32 + j * 8 + 2 * q;
#pragma unroll
            for (int hrow = 0; hrow < 2; ++hrow) {
                int row = n0 + wm * 32 + i * 16 + g + hrow * 8;
                size_t zo = (size_t)(b * NN + row) * ZC + s * 128 + col;
                uint32_t zh = *(const uint32_t*)&g_Zh[zo];
                uint32_t zl = *(const uint32_t*)&g_Zl[zo];
                float v0 = c[i][j][hrow * 2]     + bf_lo(zh) + bf_lo(zl);
                float v1 = c[i][j][hrow * 2 + 1] + bf_hi(zh) + bf_hi(zl);
                bf16 h0, l0, h1, l1;
                split_bf16(v0, h0, l0); split_bf16(v1, h1, l1);
                size_t vo = vbase + (size_t)row * OUTC + col;
                *(uint32_t*)&g_Vh[vo] = pack2(h0, h1);
                *(uint32_t*)&g_Vl[vo] = pack2(l0, l1);
            }
        }
    }
}

// stage2b: mid += M_s * V_s  (deterministic 2-way atomicAdd; mid zeroed in prep)
__global__ __launch_bounds__(256, 2) void stage2b_mma() {
    extern __shared__ __align__(16) bf16 sm3[];
    const int tid = threadIdx.x;
    const int warp = tid >> 5, lane = tid & 31;
    const int wm = warp >> 1, wn = warp & 1;
    const int g = lane >> 2, q = lane & 3;
    const int n0 = blockIdx.x * 128;
    const int b  = blockIdx.y;
    const int s  = blockIdx.z;

    const int aLdRow = tid >> 2, aLdSeg = tid & 3;
    const int bLdRow = tid >> 3, bLdSeg = tid & 7;
    const int fragRow  = lane & 15;
    const int fragCol8 = (lane >> 4) * 8;

    uint32_t AhB[3], AlB[3], BhB[3], BlB[3];
#pragma unroll
    for (int i = 0; i < 3; ++i) {
        AhB[i] = smem_u32(sm3 + (0 + i) * S2_ATILE);
        AlB[i] = smem_u32(sm3 + (3 + i) * S2_ATILE);
        BhB[i] = smem_u32(sm3 + 6 * S2_ATILE + (0 + i) * S2_BTILE);
        BlB[i] = smem_u32(sm3 + 6 * S2_ATILE + (3 + i) * S2_BTILE);
    }

    float c[2][4][4];
#pragma unroll
    for (int i = 0; i < 2; ++i)
#pragma unroll
        for (int j = 0; j < 4; ++j)
#pragma unroll
            for (int t = 0; t < 4; ++t) c[i][j][t] = 0.f;

    const bf16* Amh = g_Mh + (size_t)s * AS;
    const bf16* Aml = g_Ml + (size_t)s * AS;
    const size_t vbase = ((size_t)(s * BB + b) * NN) * OUTC;

    auto load_chunk = [&](int ch) {
        int buf = ch % 3;
        int mpos = ch * 32;
        uint32_t soA0 = (uint32_t)(aLdRow * S2_APAD + aLdSeg * 8) * 2;
        uint32_t soA1 = (uint32_t)((aLdRow + 64) * S2_APAD + aLdSeg * 8) * 2;
        cp16(AhB[buf] + soA0, Amh + (size_t)(n0 + aLdRow) * NN + mpos + aLdSeg * 8);
        cp16(AhB[buf] + soA1, Amh + (size_t)(n0 + aLdRow + 64) * NN + mpos + aLdSeg * 8);
        cp16(AlB[buf] + soA0, Aml + (size_t)(n0 + aLdRow) * NN + mpos + aLdSeg * 8);
        cp16(AlB[buf] + soA1, Aml + (size_t)(n0 + aLdRow + 64) * NN + mpos + aLdSeg * 8);
        uint32_t soB = (uint32_t)(bLdRow * S2_BPAD + bLdSeg * 8) * 2;
        cp16(BhB[buf] + soB, g_Vh + vbase + (size_t)(mpos + bLdRow) * OUTC + bLdSeg * 8);
        cp16(BlB[buf] + soB, g_Vl + vbase + (size_t)(mpos + bLdRow) * OUTC + bLdSeg * 8);
        CP_COMMIT();
    };

    load_chunk(0); load_chunk(1);

    for (int ch = 0; ch < S2_NCH; ++ch) {
        int buf = ch % 3;
        CP_WAIT1();
        __syncthreads();
#pragma unroll
        for (int ks = 0; ks < 32; ks += 16) {
            uint32_t ah[2][4], al[2][4];
#pragma unroll
            for (int i = 0; i < 2; ++i) {
                uint32_t ro = (uint32_t)(wm * 32 + i * 16 + fragRow) * (S2_APAD * 2)
                            + (uint32_t)(ks + fragCol8) * 2;
                LDSM_X4(ah[i][0], ah[i][1], ah[i][2], ah[i][3], AhB[buf] + ro);
                LDSM_X4(al[i][0], al[i][1], al[i][2], al[i][3], AlB[buf] + ro);
            }
            uint32_t bh[4][2], bl[4][2];
#pragma unroll
            for (int jj = 0; jj < 2; ++jj) {
                uint32_t ro = (uint32_t)(ks + fragRow) * (S2_BPAD * 2)
                            + (uint32_t)(wn * 32 + jj * 16 + fragCol8) * 2;
                uint32_t r0_, r1_, r2_, r3_;
                LDSM_X4T(r0_, r1_, r2_, r3_, BhB[buf] + ro);
                bh[2*jj][0] = r0_;   bh[2*jj][1] = r1_;
                bh[2*jj+1][0] = r2_; bh[2*jj+1][1] = r3_;
                LDSM_X4T(r0_, r1_, r2_, r3_, BlB[buf] + ro);
                bl[2*jj][0] = r0_;   bl[2*jj][1] = r1_;
                bl[2*jj+1][0] = r2_; bl[2*jj+1][1] = r3_;
            }
#pragma unroll
            for (int i = 0; i < 2; ++i)
#pragma unroll
                for (int j = 0; j < 4; ++j) {
                    MMA_BF16(c[i][j][0], c[i][j][1], c[i][j][2], c[i][j][3],
                             ah[i][0], ah[i][1], ah[i][2], ah[i][3], bh[j][0], bh[j][1]);
                    MMA_BF16(c[i][j][0], c[i][j][1], c[i][j][2], c[i][j][3],
                             al[i][0], al[i][1], al[i][2], al[i][3], bh[j][0], bh[j][1]);
                    MMA_BF16(c[i][j][0], c[i][j][1], c[i][j][2], c[i][j][3],
                             ah[i][0], ah[i][1], ah[i][2], ah[i][3], bl[j][0], bl[j][1]);
                }
        }
        if (ch + 2 < S2_NCH) load_chunk(ch + 2);
        else CP_COMMIT();
    }

    // epilogue: deterministic 2-way accumulate into g_mid
#pragma unroll
    for (int i = 0; i < 2; ++i) {
        int row = n0 + wm * 32 + i * 16 + g;
#pragma unroll
        for (int j = 0; j < 4; ++j) {
            int col = wn * 32 + j * 8 + 2 * q;
#pragma unroll
            for (int hrow = 0; hrow < 2; ++hrow) {
                size_t off = (size_t)(b * NN + row + hrow * 8) * OUTC + col;
                atomicAdd(&g_mid[off],     c[i][j][hrow * 2]);
                atomicAdd(&g_mid[off + 1], c[i][j][hrow * 2 + 1]);
            }
        }
    }
}

// ---------------- BN tail (single g_mid) ----------------
__global__ __launch_bounds__(256) void bn_stats() {
    const int c = threadIdx.x & 63;
    const int rl = threadIdx.x >> 6;
    float s = 0.f, s2 = 0.f;
    for (int r = blockIdx.x * 4 + rl; r < ROWS; r += gridDim.x * 4) {
        float v = g_mid[(size_t)r * OUTC + c];
        s += v; s2 += v * v;
    }
    __shared__ float sh[256], sh2[256];
    sh[threadIdx.x] = s; sh2[threadIdx.x] = s2;
    __syncthreads();
    if (rl == 0) {
        s  = sh[c] + sh[c + 64] + sh[c + 128] + sh[c + 192];
        s2 = sh2[c] + sh2[c + 64] + sh2[c + 128] + sh2[c + 192];
        atomicAdd(&g_sum[c], s); atomicAdd(&g_sumsq[c], s2);
    }
}
__global__ __launch_bounds__(256) void bn_relu_fc2(
    const float* __restrict__ gamma, const float* __restrict__ beta,
    const float* __restrict__ w2,    const float* __restrict__ b2,
    float* __restrict__ out)
{
    __shared__ float w2t[64][65];
    __shared__ float ysm[64][65];
    __shared__ float scale_s[64], shift_s[64];
    const int tid = threadIdx.x;
    const int r0 = blockIdx.x * 64;

#pragma unroll
    for (int t = 0; t < 16; ++t) {
        int idx = tid + t * 256;
        int o = idx >> 6, cc = idx & 63;
        w2t[cc][o] = w2[idx];
    }
    if (tid < OUTC) {
        const float invN = 1.0f / (float)ROWS;
        float mean = g_sum[tid] * invN;
        float var  = g_sumsq[tid] * invN - mean * mean;
        float sc   = gamma[tid] * rsqrtf(var + 1e-5f);
        scale_s[tid] = sc;
        shift_s[tid] = beta[tid] - mean * sc;
    }
    __syncthreads();

#pragma unroll
    for (int t = 0; t < 16; ++t) {
        int idx = tid + t * 256;
        int r = idx >> 6, cc = idx & 63;
        float v = g_mid[(size_t)(r0 + r) * OUTC + cc];
        ysm[r][cc] = fmaxf(fmaf(v, scale_s[cc], shift_s[cc]), 0.f);
    }
    __syncthreads();

    const int tr = tid >> 4, tc = tid & 15;
    float acc[4][4];
#pragma unroll
    for (int i = 0; i < 4; ++i)
#pragma unroll
        for (int j = 0; j < 4; ++j) acc[i][j] = b2[tc * 4 + j];
    for (int k = 0; k < 64; ++k) {
        float w0 = w2t[k][tc * 4 + 0], w1 = w2t[k][tc * 4 + 1];
        float w2v = w2t[k][tc * 4 + 2], w3 = w2t[k][tc * 4 + 3];
#pragma unroll
        for (int i = 0; i < 4; ++i) {
            float y = ysm[tr * 4 + i][k];
            acc[i][0] = fmaf(y, w0, acc[i][0]);
            acc[i][1] = fmaf(y, w1, acc[i][1]);
            acc[i][2] = fmaf(y, w2v, acc[i][2]);
            acc[i][3] = fmaf(y, w3, acc[i][3]);
        }
    }
#pragma unroll
    for (int i = 0; i < 4; ++i)
        *(float4*)&out[(size_t)(r0 + tr * 4 + i) * OUTC + tc * 4] = *(float4*)&acc[i][0];
}

// ---------------- launch ----------------
extern "C" void kernel_launch(void* const* d_in, const int* in_sizes, int n_in,
                              void* d_out, int out_size) {
    const float* x       = (const float*)d_in[0];
    const float* support = (const float*)d_in[1];
    const float* weight  = (const float*)d_in[2];
    const float* eps     = (const float*)d_in[3];
    const float* gamma   = (const float*)d_in[4];
    const float* beta    = (const float*)d_in[5];
    const float* w2      = (const float*)d_in[6];
    const float* b2      = (const float*)d_in[7];
    float* out           = (float*)d_out;

    cudaFuncSetAttribute(stage1_mma,  cudaFuncAttributeMaxDynamicSharedMemorySize, S1_SMEM);
    cudaFuncSetAttribute(stage2a_mma, cudaFuncAttributeMaxDynamicSharedMemorySize, S2_SMEM);
    cudaFuncSetAttribute(stage2b_mma, cudaFuncAttributeMaxDynamicSharedMemorySize, S2_SMEM);

    {
        int total = (int)(ROWS * (size_t)OUTC);
        prep_all<<<(total + 255) / 256, 256>>>(support, eps, weight);
    }

    stage1_mma<<<dim3(ZC / 128, ROWS / 128), 256, S1_SMEM>>>(x);

    stage2a_mma<<<dim3(NN / 128, BB, 2), 256, S2_SMEM>>>();
    stage2b_mma<<<dim3(NN / 128, BB, 2), 256, S2_SMEM>>>();

    bn_stats<<<128, 256>>>();
    bn_relu_fc2<<<ROWS / 64, 256>>>(gamma, beta, w2, b2, out);
}

// round 17
// speedup vs baseline: 1.2926x; 1.0588x over previous
#include <cuda_runtime.h>
#include <cuda_bf16.h>
#include <math.h>
#include <stdint.h>

typedef __nv_bfloat16 bf16;

// ---------------- problem dims ----------------
#define BB    32
#define NN    512
#define BD    768            // L*H
#define ROWS  (BB*NN)        // 16384
#define OUTC  64
#define KSUP  4
#define ZC    256            // KSUP*OUTC
#define AS    ((size_t)NN*NN)

// ---------------- device scratch (no allocation) ----------------
__device__ __align__(256) bf16  g_Mh [2*AS], g_Ml [2*AS];    // M = A+(1+eps)I, split
__device__ __align__(256) bf16  g_Wth[ZC*BD], g_Wtl[ZC*BD];  // W^T repack [ko][d]
__device__ __align__(256) bf16  g_Zh[(size_t)ROWS*ZC], g_Zl[(size_t)ROWS*ZC];
__device__ __align__(256) bf16  g_Vh[(size_t)2*ROWS*OUTC], g_Vl[(size_t)2*ROWS*OUTC];
__device__ __align__(256) float g_mid[(size_t)ROWS*OUTC];
__device__ float g_sum[OUTC], g_sumsq[OUTC];

__device__ __forceinline__ uint32_t smem_u32(const void* p) {
    uint32_t a;
    asm("{ .reg .u64 t; cvta.to.shared.u64 t, %1; cvt.u32.u64 %0, t; }" : "=r"(a) : "l"(p));
    return a;
}
__device__ __forceinline__ void split_bf16(float v, bf16& h, bf16& l) {
    h = __float2bfloat16(v);
    l = __float2bfloat16(v - __bfloat162float(h));
}
__device__ __forceinline__ uint32_t pack2(bf16 lo, bf16 hi) {
    return ((uint32_t)__bfloat16_as_ushort(hi) << 16) | __bfloat16_as_ushort(lo);
}
__device__ __forceinline__ float bf_lo(uint32_t u) {
    return __bfloat162float(__ushort_as_bfloat16((unsigned short)(u & 0xFFFF)));
}
__device__ __forceinline__ float bf_hi(uint32_t u) {
    return __bfloat162float(__ushort_as_bfloat16((unsigned short)(u >> 16)));
}
__device__ __forceinline__ void cp16(uint32_t s, const void* g) {
    asm volatile("cp.async.cg.shared.global [%0], [%1], 16;"
                 :: "r"(s), "l"(__cvta_generic_to_global(g)) : "memory");
}
#define CP_COMMIT() asm volatile("cp.async.commit_group;" ::: "memory")
#define CP_WAIT1()  asm volatile("cp.async.wait_group 1;"  ::: "memory")

#define LDSM_X4(r0,r1,r2,r3,addr) \
    asm volatile("ldmatrix.sync.aligned.m8n8.x4.shared.b16 {%0,%1,%2,%3}, [%4];" \
                 : "=r"(r0), "=r"(r1), "=r"(r2), "=r"(r3) : "r"(addr))
#define LDSM_X4T(r0,r1,r2,r3,addr) \
    asm volatile("ldmatrix.sync.aligned.m8n8.x4.trans.shared.b16 {%0,%1,%2,%3}, [%4];" \
                 : "=r"(r0), "=r"(r1), "=r"(r2), "=r"(r3) : "r"(addr))
#define MMA_BF16(c0,c1,c2,c3,a0,a1,a2,a3,b0,b1) \
    asm volatile("mma.sync.aligned.m16n8k16.row.col.f32.bf16.bf16.f32 " \
                 "{%0,%1,%2,%3}, {%4,%5,%6,%7}, {%8,%9}, {%0,%1,%2,%3};" \
                 : "+f"(c0), "+f"(c1), "+f"(c2), "+f"(c3) \
                 : "r"(a0), "r"(a1), "r"(a2), "r"(a3), "r"(b0), "r"(b1))

// ---------------- fused prep: M split + W split + zero stats + zero mid ----------
__global__ void prep_all(const float* __restrict__ sup, const float* __restrict__ eps,
                         const float* __restrict__ w) {
    int idx = blockIdx.x * blockDim.x + threadIdx.x;
    if (idx < 64) { g_sum[idx] = 0.f; g_sumsq[idx] = 0.f; }
    if (idx < (int)(ROWS * (size_t)OUTC)) g_mid[idx] = 0.f;
    if (idx < 2 * (int)AS) {
        int rest = idx & (int)(AS - 1);
        int n = rest >> 9, m = rest & 511;
        float v = sup[idx] + ((n == m) ? (1.0f + eps[0]) : 0.0f);
        bf16 h, l; split_bf16(v, h, l);
        g_Mh[idx] = h; g_Ml[idx] = l;
    } else {
        int widx = idx - 2 * (int)AS;          // ko*768 + d
        if (widx >= ZC * BD) return;
        int d  = widx % BD;
        int ko = widx / BD;
        int k = ko >> 6, o = ko & 63;
        int l = d >> 6, h = d & 63;
        float v = w[((size_t)l * 256 + h * 4 + k) * OUTC + o];
        bf16 hh, ll; split_bf16(v, hh, ll);
        g_Wth[widx] = hh; g_Wtl[widx] = ll;
    }
}

// ---------------- stage1 (fused X-split; BK=32; 24 chunks; occ 2) ----------------
// smem: Ah[2] Al[2] Wh[3] Wl[3] tiles of 128x40 bf16 (10.24 KB) = 102.4 KB -> occ 2
#define S1_PAD 40
#define S1_NCH 24
#define S1_TILE (128 * S1_PAD)
#define S1_SMEM (10 * S1_TILE * 2)

__global__ __launch_bounds__(256, 2) void stage1_mma(const float* __restrict__ X) {
    extern __shared__ __align__(16) bf16 sm1[];
    const int tid = threadIdx.x;
    const int warp = tid >> 5, lane = tid & 31;
    const int wm = warp >> 1, wn = warp & 1;
    const int g = lane >> 2, q = lane & 3;
    const int r0 = blockIdx.y * 128;
    const int c0 = blockIdx.x * 128;

    // validated lane-invariant ldmatrix offsets (rounds 5-9, PAD 40, BK=32)
    const int aRowOff = ((lane >> 3) & 1) * 8 + (lane & 7);
    const int aKOff   = (lane >> 4) * 8;
    const int bRowOff = (lane >> 4) * 8 + (lane & 7);
    const int bKOff   = ((lane >> 3) & 1) * 8;

    uint32_t AhB[2], AlB[2], WhB[3], WlB[3];
#pragma unroll
    for (int i = 0; i < 2; ++i) {
        AhB[i] = smem_u32(sm1 + (0 + i) * S1_TILE);
        AlB[i] = smem_u32(sm1 + (2 + i) * S1_TILE);
    }
#pragma unroll
    for (int i = 0; i < 3; ++i) {
        WhB[i] = smem_u32(sm1 + (4 + i) * S1_TILE);
        WlB[i] = smem_u32(sm1 + (7 + i) * S1_TILE);
    }

    float c[2][8][4];
#pragma unroll
    for (int i = 0; i < 2; ++i)
#pragma unroll
        for (int j = 0; j < 8; ++j)
#pragma unroll
            for (int t = 0; t < 4; ++t) c[i][j][t] = 0.f;

    // X staging: 4 float4 per thread per BK=32 chunk (128 rows x 32 cols)
    const int xRow = tid >> 3;          // 0..31, +32 per t
    const int xSeg = tid & 7;           // 8 segs x 4 floats
    float4 xv[4];

    auto ldgX = [&](int ch) {
        int kpos = ch * 32;
#pragma unroll
        for (int t = 0; t < 4; ++t) {
            int row = xRow + t * 32;
            xv[t] = *(const float4*)(X + (size_t)(r0 + row) * BD + kpos + xSeg * 4);
        }
    };
    auto cvtSts = [&](int abuf) {
        uint32_t base = smem_u32(sm1);
#pragma unroll
        for (int t = 0; t < 4; ++t) {
            int row = xRow + t * 32;
            bf16 h0,l0,h1,l1,h2,l2,h3,l3;
            split_bf16(xv[t].x, h0, l0); split_bf16(xv[t].y, h1, l1);
            split_bf16(xv[t].z, h2, l2); split_bf16(xv[t].w, h3, l3);
            uint2 ph = { pack2(h0, h1), pack2(h2, h3) };
            uint2 pl = { pack2(l0, l1), pack2(l2, l3) };
            uint32_t so = (uint32_t)(row * S1_PAD + xSeg * 4) * 2;
            *(uint2*)((char*)sm1 + (AhB[abuf] - base) + so) = ph;
            *(uint2*)((char*)sm1 + (AlB[abuf] - base) + so) = pl;
        }
    };
    auto loadW = [&](int ch) {
        int wb = ch % 3;
        int kpos = ch * 32;
#pragma unroll
        for (int t = 0; t < 2; ++t) {
            int u = tid + t * 256;
            int row = u >> 2, seg = u & 3;
            uint32_t so = (uint32_t)(row * S1_PAD + seg * 8) * 2;
            cp16(WhB[wb] + so, g_Wth + (size_t)(c0 + row) * BD + kpos + seg * 8);
            cp16(WlB[wb] + so, g_Wtl + (size_t)(c0 + row) * BD + kpos + seg * 8);
        }
        CP_COMMIT();
    };

    // prologue
    ldgX(0); cvtSts(0);
    loadW(0); loadW(1);
    ldgX(1);
    CP_WAIT1();
    __syncthreads();

    for (int ch = 0; ch < S1_NCH; ++ch) {
        int abuf = ch & 1, wbuf = ch % 3;
#pragma unroll
        for (int ks = 0; ks < 32; ks += 16) {
            uint32_t ah[2][4], al[2][4];
#pragma unroll
            for (int i = 0; i < 2; ++i) {
                uint32_t ro = (uint32_t)(wm * 32 + i * 16 + aRowOff) * (S1_PAD * 2)
                            + (uint32_t)(ks + aKOff) * 2;
                LDSM_X4(ah[i][0], ah[i][1], ah[i][2], ah[i][3], AhB[abuf] + ro);
                LDSM_X4(al[i][0], al[i][1], al[i][2], al[i][3], AlB[abuf] + ro);
            }
            uint32_t bh[8][2], bl[8][2];
#pragma unroll
            for (int j2 = 0; j2 < 4; ++j2) {
                uint32_t ro = (uint32_t)(wn * 64 + j2 * 16 + bRowOff) * (S1_PAD * 2)
                            + (uint32_t)(ks + bKOff) * 2;
                uint32_t r0_, r1_, r2_, r3_;
                LDSM_X4(r0_, r1_, r2_, r3_, WhB[wbuf] + ro);
                bh[2*j2][0] = r0_;   bh[2*j2][1] = r1_;
                bh[2*j2+1][0] = r2_; bh[2*j2+1][1] = r3_;
                LDSM_X4(r0_, r1_, r2_, r3_, WlB[wbuf] + ro);
                bl[2*j2][0] = r0_;   bl[2*j2][1] = r1_;
                bl[2*j2+1][0] = r2_; bl[2*j2+1][1] = r3_;
            }
#pragma unroll
            for (int i = 0; i < 2; ++i)
#pragma unroll
                for (int j = 0; j < 8; ++j) {
                    MMA_BF16(c[i][j][0], c[i][j][1], c[i][j][2], c[i][j][3],
                             ah[i][0], ah[i][1], ah[i][2], ah[i][3], bh[j][0], bh[j][1]);
                    MMA_BF16(c[i][j][0], c[i][j][1], c[i][j][2], c[i][j][3],
                             al[i][0], al[i][1], al[i][2], al[i][3], bh[j][0], bh[j][1]);
                    MMA_BF16(c[i][j][0], c[i][j][1], c[i][j][2], c[i][j][3],
                             ah[i][0], ah[i][1], ah[i][2], ah[i][3], bl[j][0], bl[j][1]);
                }
        }
        if (ch + 1 < S1_NCH) cvtSts(abuf ^ 1);       // X(ch+1) from xv registers
        if (ch + 2 < S1_NCH) { ldgX(ch + 2); loadW(ch + 2); }
        else CP_COMMIT();
        CP_WAIT1();
        __syncthreads();
    }

    // epilogue: split fp32 -> Zh/Zl bf16
#pragma unroll
    for (int i = 0; i < 2; ++i) {
        int row = r0 + wm * 32 + i * 16 + g;
#pragma unroll
        for (int j = 0; j < 8; ++j) {
            int col = c0 + wn * 64 + j * 8 + 2 * q;
#pragma unroll
            for (int hrow = 0; hrow < 2; ++hrow) {
                float v0 = c[i][j][hrow * 2], v1 = c[i][j][hrow * 2 + 1];
                bf16 h0, l0, h1, l1;
                split_bf16(v0, h0, l0); split_bf16(v1, h1, l1);
                size_t off = (size_t)(row + hrow * 8) * ZC + col;
                *(uint32_t*)&g_Zh[off] = pack2(h0, h1);
                *(uint32_t*)&g_Zl[off] = pack2(l0, l1);
            }
        }
    }
}

// ---------------- stage2: fragment-reuse, BK=32, 16 chunks, 3-stage, 1 sync ------
#define S2_APAD 40
#define S2_BPAD 72
#define S2_NCH 16
#define S2_ATILE (128 * S2_APAD)
#define S2_BTILE (32 * S2_BPAD)
#define S2_SMEM ((6 * S2_ATILE + 6 * S2_BTILE) * 2)

// stage2a: V_s = Z_{2s} + M_s * Z_{2s+1}  (fused vadd epilogue)
__global__ __launch_bounds__(256, 2) void stage2a_mma() {
    extern __shared__ __align__(16) bf16 sm2[];
    const int tid = threadIdx.x;
    const int warp = tid >> 5, lane = tid & 31;
    const int wm = warp >> 1, wn = warp & 1;
    const int g = lane >> 2, q = lane & 3;
    const int n0 = blockIdx.x * 128;
    const int b  = blockIdx.y;
    const int s  = blockIdx.z;

    const int aLdRow = tid >> 2, aLdSeg = tid & 3;
    const int bLdRow = tid >> 3, bLdSeg = tid & 7;
    const int fragRow  = lane & 15;
    const int fragCol8 = (lane >> 4) * 8;

    uint32_t AhB[3], AlB[3], BhB[3], BlB[3];
#pragma unroll
    for (int i = 0; i < 3; ++i) {
        AhB[i] = smem_u32(sm2 + (0 + i) * S2_ATILE);
        AlB[i] = smem_u32(sm2 + (3 + i) * S2_ATILE);
        BhB[i] = smem_u32(sm2 + 6 * S2_ATILE + (0 + i) * S2_BTILE);
        BlB[i] = smem_u32(sm2 + 6 * S2_ATILE + (3 + i) * S2_BTILE);
    }

    float c[2][4][4];
#pragma unroll
    for (int i = 0; i < 2; ++i)
#pragma unroll
        for (int j = 0; j < 4; ++j)
#pragma unroll
            for (int t = 0; t < 4; ++t) c[i][j][t] = 0.f;

    const bf16* Amh = g_Mh + (size_t)s * AS;
    const bf16* Aml = g_Ml + (size_t)s * AS;
    const int zcol = (2 * s + 1) * 64;

    auto load_chunk = [&](int ch) {
        int buf = ch % 3;
        int mpos = ch * 32;
        uint32_t soA0 = (uint32_t)(aLdRow * S2_APAD + aLdSeg * 8) * 2;
        uint32_t soA1 = (uint32_t)((aLdRow + 64) * S2_APAD + aLdSeg * 8) * 2;
        cp16(AhB[buf] + soA0, Amh + (size_t)(n0 + aLdRow) * NN + mpos + aLdSeg * 8);
        cp16(AhB[buf] + soA1, Amh + (size_t)(n0 + aLdRow + 64) * NN + mpos + aLdSeg * 8);
        cp16(AlB[buf] + soA0, Aml + (size_t)(n0 + aLdRow) * NN + mpos + aLdSeg * 8);
        cp16(AlB[buf] + soA1, Aml + (size_t)(n0 + aLdRow + 64) * NN + mpos + aLdSeg * 8);
        uint32_t soB = (uint32_t)(bLdRow * S2_BPAD + bLdSeg * 8) * 2;
        cp16(BhB[buf] + soB, g_Zh + (size_t)(b * NN + mpos + bLdRow) * ZC + zcol + bLdSeg * 8);
        cp16(BlB[buf] + soB, g_Zl + (size_t)(b * NN + mpos + bLdRow) * ZC + zcol + bLdSeg * 8);
        CP_COMMIT();
    };

    load_chunk(0); load_chunk(1);

    for (int ch = 0; ch < S2_NCH; ++ch) {
        int buf = ch % 3;
        CP_WAIT1();
        __syncthreads();
#pragma unroll
        for (int ks = 0; ks < 32; ks += 16) {
            uint32_t ah[2][4], al[2][4];
#pragma unroll
            for (int i = 0; i < 2; ++i) {
                uint32_t ro = (uint32_t)(wm * 32 + i * 16 + fragRow) * (S2_APAD * 2)
                            + (uint32_t)(ks + fragCol8) * 2;
                LDSM_X4(ah[i][0], ah[i][1], ah[i][2], ah[i][3], AhB[buf] + ro);
                LDSM_X4(al[i][0], al[i][1], al[i][2], al[i][3], AlB[buf] + ro);
            }
            uint32_t bh[4][2], bl[4][2];
#pragma unroll
            for (int jj = 0; jj < 2; ++jj) {
                uint32_t ro = (uint32_t)(ks + fragRow) * (S2_BPAD * 2)
                            + (uint32_t)(wn * 32 + jj * 16 + fragCol8) * 2;
                uint32_t r0_, r1_, r2_, r3_;
                LDSM_X4T(r0_, r1_, r2_, r3_, BhB[buf] + ro);
                bh[2*jj][0] = r0_;   bh[2*jj][1] = r1_;
                bh[2*jj+1][0] = r2_; bh[2*jj+1][1] = r3_;
                LDSM_X4T(r0_, r1_, r2_, r3_, BlB[buf] + ro);
                bl[2*jj][0] = r0_;   bl[2*jj][1] = r1_;
                bl[2*jj+1][0] = r2_; bl[2*jj+1][1] = r3_;
            }
#pragma unroll
            for (int i = 0; i < 2; ++i)
#pragma unroll
                for (int j = 0; j < 4; ++j) {
                    MMA_BF16(c[i][j][0], c[i][j][1], c[i][j][2], c[i][j][3],
                             ah[i][0], ah[i][1], ah[i][2], ah[i][3], bh[j][0], bh[j][1]);
                    MMA_BF16(c[i][j][0], c[i][j][1], c[i][j][2], c[i][j][3],
                             al[i][0], al[i][1], al[i][2], al[i][3], bh[j][0], bh[j][1]);
                    MMA_BF16(c[i][j][0], c[i][j][1], c[i][j][2], c[i][j][3],
                             ah[i][0], ah[i][1], ah[i][2], ah[i][3], bl[j][0], bl[j][1]);
                }
        }
        if (ch + 2 < S2_NCH) load_chunk(ch + 2);
        else CP_COMMIT();
    }

    // fused epilogue: V = Z_even + M*Z_odd, split to bf16 -> Vh/Vl
    const size_t vbase = ((size_t)(s * BB + b) * NN) * OUTC;
#pragma unroll
    for (int i = 0; i < 2; ++i) {
#pragma unroll
        for (int j = 0; j < 4; ++j) {
            int col = wn * 32 + j * 8 + 2 * q;
#pragma unroll
            for (int hrow = 0; hrow < 2; ++hrow) {
                int row = n0 + wm * 32 + i * 16 + g + hrow * 8;
                size_t zo = (size_t)(b * NN + row) * ZC + s * 128 + col;
                uint32_t zh = *(const uint32_t*)&g_Zh[zo];
                uint32_t zl = *(const uint32_t*)&g_Zl[zo];
                float v0 = c[i][j][hrow * 2]     + bf_lo(zh) + bf_lo(zl);
                float v1 = c[i][j][hrow * 2 + 1] + bf_hi(zh) + bf_hi(zl);
                bf16 h0, l0, h1, l1;
                split_bf16(v0, h0, l0); split_bf16(v1, h1, l1);
                size_t vo = vbase + (size_t)row * OUTC + col;
                *(uint32_t*)&g_Vh[vo] = pack2(h0, h1);
                *(uint32_t*)&g_Vl[vo] = pack2(l0, l1);
            }
        }
    }
}

// stage2b: mid += M_s * V_s  (deterministic 2-way atomicAdd; mid zeroed in prep)
__global__ __launch_bounds__(256, 2) void stage2b_mma() {
    extern __shared__ __align__(16) bf16 sm3[];
    const int tid = threadIdx.x;
    const int warp = tid >> 5, lane = tid & 31;
    const int wm = warp >> 1, wn = warp & 1;
    const int g = lane >> 2, q = lane & 3;
    const int n0 = blockIdx.x * 128;
    const int b  = blockIdx.y;
    const int s  = blockIdx.z;

    const int aLdRow = tid >> 2, aLdSeg = tid & 3;
    const int bLdRow = tid >> 3, bLdSeg = tid & 7;
    const int fragRow  = lane & 15;
    const int fragCol8 = (lane >> 4) * 8;

    uint32_t AhB[3], AlB[3], BhB[3], BlB[3];
#pragma unroll
    for (int i = 0; i < 3; ++i) {
        AhB[i] = smem_u32(sm3 + (0 + i) * S2_ATILE);
        AlB[i] = smem_u32(sm3 + (3 + i) * S2_ATILE);
        BhB[i] = smem_u32(sm3 + 6 * S2_ATILE + (0 + i) * S2_BTILE);
        BlB[i] = smem_u32(sm3 + 6 * S2_ATILE + (3 + i) * S2_BTILE);
    }

    float c[2][4][4];
#pragma unroll
    for (int i = 0; i < 2; ++i)
#pragma unroll
        for (int j = 0; j < 4; ++j)
#pragma unroll
            for (int t = 0; t < 4; ++t) c[i][j][t] = 0.f;

    const bf16* Amh = g_Mh + (size_t)s * AS;
    const bf16* Aml = g_Ml + (size_t)s * AS;
    const size_t vbase = ((size_t)(s * BB + b) * NN) * OUTC;

    auto load_chunk = [&](int ch) {
        int buf = ch % 3;
        int mpos = ch * 32;
        uint32_t soA0 = (uint32_t)(aLdRow * S2_APAD + aLdSeg * 8) * 2;
        uint32_t soA1 = (uint32_t)((aLdRow + 64) * S2_APAD + aLdSeg * 8) * 2;
        cp16(AhB[buf] + soA0, Amh + (size_t)(n0 + aLdRow) * NN + mpos + aLdSeg * 8);
        cp16(AhB[buf] + soA1, Amh + (size_t)(n0 + aLdRow + 64) * NN + mpos + aLdSeg * 8);
        cp16(AlB[buf] + soA0, Aml + (size_t)(n0 + aLdRow) * NN + mpos + aLdSeg * 8);
        cp16(AlB[buf] + soA1, Aml + (size_t)(n0 + aLdRow + 64) * NN + mpos + aLdSeg * 8);
        uint32_t soB = (uint32_t)(bLdRow * S2_BPAD + bLdSeg * 8) * 2;
        cp16(BhB[buf] + soB, g_Vh + vbase + (size_t)(mpos + bLdRow) * OUTC + bLdSeg * 8);
        cp16(BlB[buf] + soB, g_Vl + vbase + (size_t)(mpos + bLdRow) * OUTC + bLdSeg * 8);
        CP_COMMIT();
    };

    load_chunk(0); load_chunk(1);

    for (int ch = 0; ch < S2_NCH; ++ch) {
        int buf = ch % 3;
        CP_WAIT1();
        __syncthreads();
#pragma unroll
        for (int ks = 0; ks < 32; ks += 16) {
            uint32_t ah[2][4], al[2][4];
#pragma unroll
            for (int i = 0; i < 2; ++i) {
                uint32_t ro = (uint32_t)(wm * 32 + i * 16 + fragRow) * (S2_APAD * 2)
                            + (uint32_t)(ks + fragCol8) * 2;
                LDSM_X4(ah[i][0], ah[i][1], ah[i][2], ah[i][3], AhB[buf] + ro);
                LDSM_X4(al[i][0], al[i][1], al[i][2], al[i][3], AlB[buf] + ro);
            }
            uint32_t bh[4][2], bl[4][2];
#pragma unroll
            for (int jj = 0; jj < 2; ++jj) {
                uint32_t ro = (uint32_t)(ks + fragRow) * (S2_BPAD * 2)
                            + (uint32_t)(wn * 32 + jj * 16 + fragCol8) * 2;
                uint32_t r0_, r1_, r2_, r3_;
                LDSM_X4T(r0_, r1_, r2_, r3_, BhB[buf] + ro);
                bh[2*jj][0] = r0_;   bh[2*jj][1] = r1_;
                bh[2*jj+1][0] = r2_; bh[2*jj+1][1] = r3_;
                LDSM_X4T(r0_, r1_, r2_, r3_, BlB[buf] + ro);
                bl[2*jj][0] = r0_;   bl[2*jj][1] = r1_;
                bl[2*jj+1][0] = r2_; bl[2*jj+1][1] = r3_;
            }
#pragma unroll
            for (int i = 0; i < 2; ++i)
#pragma unroll
                for (int j = 0; j < 4; ++j) {
                    MMA_BF16(c[i][j][0], c[i][j][1], c[i][j][2], c[i][j][3],
                             ah[i][0], ah[i][1], ah[i][2], ah[i][3], bh[j][0], bh[j][1]);
                    MMA_BF16(c[i][j][0], c[i][j][1], c[i][j][2], c[i][j][3],
                             al[i][0], al[i][1], al[i][2], al[i][3], bh[j][0], bh[j][1]);
                    MMA_BF16(c[i][j][0], c[i][j][1], c[i][j][2], c[i][j][3],
                             ah[i][0], ah[i][1], ah[i][2], ah[i][3], bl[j][0], bl[j][1]);
                }
        }
        if (ch + 2 < S2_NCH) load_chunk(ch + 2);
        else CP_COMMIT();
    }

    // epilogue: deterministic 2-way accumulate into g_mid
#pragma unroll
    for (int i = 0; i < 2; ++i) {
        int row = n0 + wm * 32 + i * 16 + g;
#pragma unroll
        for (int j = 0; j < 4; ++j) {
            int col = wn * 32 + j * 8 + 2 * q;
#pragma unroll
            for (int hrow = 0; hrow < 2; ++hrow) {
                size_t off = (size_t)(b * NN + row + hrow * 8) * OUTC + col;
                atomicAdd(&g_mid[off],     c[i][j][hrow * 2]);
                atomicAdd(&g_mid[off + 1], c[i][j][hrow * 2 + 1]);
            }
        }
    }
}

// ---------------- BN tail (single g_mid) ----------------
__global__ __launch_bounds__(256) void bn_stats() {
    const int c = threadIdx.x & 63;
    const int rl = threadIdx.x >> 6;
    float s = 0.f, s2 = 0.f;
    for (int r = blockIdx.x * 4 + rl; r < ROWS; r += gridDim.x * 4) {
        float v = g_mid[(size_t)r * OUTC + c];
        s += v; s2 += v * v;
    }
    __shared__ float sh[256], sh2[256];
    sh[threadIdx.x] = s; sh2[threadIdx.x] = s2;
    __syncthreads();
    if (rl == 0) {
        s  = sh[c] + sh[c + 64] + sh[c + 128] + sh[c + 192];
        s2 = sh2[c] + sh2[c + 64] + sh2[c + 128] + sh2[c + 192];
        atomicAdd(&g_sum[c], s); atomicAdd(&g_sumsq[c], s2);
    }
}
__global__ __launch_bounds__(256) void bn_relu_fc2(
    const float* __restrict__ gamma, const float* __restrict__ beta,
    const float* __restrict__ w2,    const float* __restrict__ b2,
    float* __restrict__ out)
{
    __shared__ float w2t[64][65];
    __shared__ float ysm[64][65];
    __shared__ float scale_s[64], shift_s[64];
    const int tid = threadIdx.x;
    const int r0 = blockIdx.x * 64;

#pragma unroll
    for (int t = 0; t < 16; ++t) {
        int idx = tid + t * 256;
        int o = idx >> 6, cc = idx & 63;
        w2t[cc][o] = w2[idx];
    }
    if (tid < OUTC) {
        const float invN = 1.0f / (float)ROWS;
        float mean = g_sum[tid] * invN;
        float var  = g_sumsq[tid] * invN - mean * mean;
        float sc   = gamma[tid] * rsqrtf(var + 1e-5f);
        scale_s[tid] = sc;
        shift_s[tid] = beta[tid] - mean * sc;
    }
    __syncthreads();

#pragma unroll
    for (int t = 0; t < 16; ++t) {
        int idx = tid + t * 256;
        int r = idx >> 6, cc = idx & 63;
        float v = g_mid[(size_t)(r0 + r) * OUTC + cc];
        ysm[r][cc] = fmaxf(fmaf(v, scale_s[cc], shift_s[cc]), 0.f);
    }
    __syncthreads();

    const int tr = tid >> 4, tc = tid & 15;
    float acc[4][4];
#pragma unroll
    for (int i = 0; i < 4; ++i)
#pragma unroll
        for (int j = 0; j < 4; ++j) acc[i][j] = b2[tc * 4 + j];
    for (int k = 0; k < 64; ++k) {
        float w0 = w2t[k][tc * 4 + 0], w1 = w2t[k][tc * 4 + 1];
        float w2v = w2t[k][tc * 4 + 2], w3 = w2t[k][tc * 4 + 3];
#pragma unroll
        for (int i = 0; i < 4; ++i) {
            float y = ysm[tr * 4 + i][k];
            acc[i][0] = fmaf(y, w0, acc[i][0]);
            acc[i][1] = fmaf(y, w1, acc[i][1]);
            acc[i][2] = fmaf(y, w2v, acc[i][2]);
            acc[i][3] = fmaf(y, w3, acc[i][3]);
        }
    }
#pragma unroll
    for (int i = 0; i < 4; ++i)
        *(float4*)&out[(size_t)(r0 + tr * 4 + i) * OUTC + tc * 4] = *(float4*)&acc[i][0];
}

// ---------------- launch ----------------
extern "C" void kernel_launch(void* const* d_in, const int* in_sizes, int n_in,
                              void* d_out, int out_size) {
    const float* x       = (const float*)d_in[0];
    const float* support = (const float*)d_in[1];
    const float* weight  = (const float*)d_in[2];
    const float* eps     = (const float*)d_in[3];
    const float* gamma   = (const float*)d_in[4];
    const float* beta    = (const float*)d_in[5];
    const float* w2      = (const float*)d_in[6];
    const float* b2      = (const float*)d_in[7];
    float* out           = (float*)d_out;

    cudaFuncSetAttribute(stage1_mma,  cudaFuncAttributeMaxDynamicSharedMemorySize, S1_SMEM);
    cudaFuncSetAttribute(stage2a_mma, cudaFuncAttributeMaxDynamicSharedMemorySize, S2_SMEM);
    cudaFuncSetAttribute(stage2b_mma, cudaFuncAttributeMaxDynamicSharedMemorySize, S2_SMEM);

    {
        int total = (int)(ROWS * (size_t)OUTC);
        prep_all<<<(total + 255) / 256, 256>>>(support, eps, weight);
    }

    stage1_mma<<<dim3(ZC / 128, ROWS / 128), 256, S1_SMEM>>>(x);

    stage2a_mma<<<dim3(NN / 128, BB, 2), 256, S2_SMEM>>>();
    stage2b_mma<<<dim3(NN / 128, BB, 2), 256, S2_SMEM>>>();

    bn_stats<<<128, 256>>>();
    bn_relu_fc2<<<ROWS / 64, 256>>>(gamma, beta, w2, b2, out);
}